// round 3
// baseline (speedup 1.0000x reference)
#include <cuda_runtime.h>
#include <math.h>
#include <stdint.h>
#include <stddef.h>

// ============================================================================
// TripletGNN decomposition:
//   qkv(n,t) = P[ci0] + Q[ci1] + ang(n,t) @ Wa^T
// where P = x @ W[:,0:256]^T + b   (bias folded into P)
//       Q = x @ W[:,256:512]^T
//       Wa = W[:,512:576]
// Attention mean folded into per-k weights: mean[c] = sum_t w_t * v[t][c].
// NOTE: corner_masks arrives as int32 (harness bool->int32 convention).
// ============================================================================

#define MAXN 40000

__device__ float g_PQ[(size_t)(MAXN + 1) * 1536];  // [i][0:768]=P(+b), [768:1536]=Q
__device__ float g_Bmat[256 * 1536];               // B[c][j] for the SGEMM
__device__ float g_WaT[64 * 768];                  // WaT[m][j] = W[j][512+m]

// ----------------------------------------------------------------------------
// Prep: build Bmat, WaT, and the padded PQ row (index N -> zero x row).
// ----------------------------------------------------------------------------
__global__ void prep_kernel(const float* __restrict__ W,
                            const float* __restrict__ bias, int N) {
    int idx = blockIdx.x * blockDim.x + threadIdx.x;
    const int B_SZ = 256 * 1536;
    const int WA_SZ = 64 * 768;
    if (idx < B_SZ) {
        int c = idx / 1536, j = idx % 1536;
        g_Bmat[idx] = (j < 768) ? W[j * 576 + c] : W[(j - 768) * 576 + 256 + c];
    } else if (idx < B_SZ + WA_SZ) {
        int r = idx - B_SZ;
        int m = r / 768, j = r % 768;
        g_WaT[r] = W[j * 576 + 512 + m];
    } else if (idx < B_SZ + WA_SZ + 1536) {
        int j = idx - (B_SZ + WA_SZ);
        g_PQ[(size_t)N * 1536 + j] = (j < 768) ? bias[j] : 0.0f;
    }
}

// ----------------------------------------------------------------------------
// out[:, 0:256] = x ; out[:, 256:512] = 0 (scatter target init)
// ----------------------------------------------------------------------------
__global__ void out_init_kernel(const float* __restrict__ x,
                                float* __restrict__ out, int N) {
    int idx = blockIdx.x * blockDim.x + threadIdx.x;
    if (idx < N * 512) {
        int r = idx >> 9, cc = idx & 511;
        out[idx] = (cc < 256) ? x[((size_t)r << 8) + cc] : 0.0f;
    }
}

// ----------------------------------------------------------------------------
// SGEMM: g_PQ[M x 1536] = X[M x 256] @ g_Bmat[256 x 1536]  (+ bias on j<768)
// 128x128 tile, 256 threads, 8x8 micro-tile.
// ----------------------------------------------------------------------------
__global__ __launch_bounds__(256, 2)
void sgemm_pq_kernel(const float* __restrict__ X,
                     const float* __restrict__ bias, int M) {
    __shared__ float As[16][132];  // transposed A tile, padded
    __shared__ float Bs[16][128];

    const int tid = threadIdx.x;
    const int tx = tid & 15;
    const int ty = tid >> 4;
    const int row0 = blockIdx.y * 128;
    const int col0 = blockIdx.x * 128;

    float acc[8][8];
#pragma unroll
    for (int i = 0; i < 8; i++)
#pragma unroll
        for (int j = 0; j < 8; j++) acc[i][j] = 0.0f;

    for (int kk = 0; kk < 256; kk += 16) {
#pragma unroll
        for (int l = 0; l < 2; l++) {
            int fid = tid + l * 256;
            int i = fid >> 2;
            int kq = fid & 3;
            float4 v = make_float4(0.f, 0.f, 0.f, 0.f);
            int grow = row0 + i;
            if (grow < M)
                v = *(const float4*)(X + (size_t)grow * 256 + kk + kq * 4);
            As[kq * 4 + 0][i] = v.x;
            As[kq * 4 + 1][i] = v.y;
            As[kq * 4 + 2][i] = v.z;
            As[kq * 4 + 3][i] = v.w;
        }
#pragma unroll
        for (int l = 0; l < 2; l++) {
            int fid = tid + l * 256;
            int k = fid >> 5;
            int j4 = fid & 31;
            float4 v = *(const float4*)(g_Bmat + (size_t)(kk + k) * 1536 + col0 + j4 * 4);
            *(float4*)&Bs[k][j4 * 4] = v;
        }
        __syncthreads();
#pragma unroll
        for (int k = 0; k < 16; k++) {
            float a[8], b[8];
            *(float4*)&a[0] = *(const float4*)&As[k][ty * 4];
            *(float4*)&a[4] = *(const float4*)&As[k][64 + ty * 4];
            *(float4*)&b[0] = *(const float4*)&Bs[k][tx * 4];
            *(float4*)&b[4] = *(const float4*)&Bs[k][64 + tx * 4];
#pragma unroll
            for (int i = 0; i < 8; i++)
#pragma unroll
                for (int j = 0; j < 8; j++)
                    acc[i][j] = fmaf(a[i], b[j], acc[i][j]);
        }
        __syncthreads();
    }

#pragma unroll
    for (int half = 0; half < 2; half++) {
#pragma unroll
        for (int r = 0; r < 4; r++) {
            int grow = row0 + half * 64 + ty * 4 + r;
            if (grow >= M) continue;
            int ri = half * 4 + r;
#pragma unroll
            for (int ch = 0; ch < 2; ch++) {
                int gcol = col0 + ch * 64 + tx * 4;
                float4 o;
                o.x = acc[ri][ch * 4 + 0];
                o.y = acc[ri][ch * 4 + 1];
                o.z = acc[ri][ch * 4 + 2];
                o.w = acc[ri][ch * 4 + 3];
                if (gcol < 768) {
                    o.x += bias[gcol + 0];
                    o.y += bias[gcol + 1];
                    o.z += bias[gcol + 2];
                    o.w += bias[gcol + 3];
                }
                *(float4*)(g_PQ + (size_t)grow * 1536 + gcol) = o;
            }
        }
    }
}

// ----------------------------------------------------------------------------
// Main per-anchor kernel: one block per anchor, 256 threads (thread = channel).
// ----------------------------------------------------------------------------
__global__ __launch_bounds__(256, 2)
void triplet_main_kernel(const float* __restrict__ pos,
                         const int* __restrict__ anchor_idx,
                         const int* __restrict__ corner_idx,
                         const int* __restrict__ masks,   // int32 (bool)
                         float* __restrict__ out,
                         int N, int write_masks) {
    __shared__ float angT[64][16];   // transposed angle features
    __shared__ float qs[16][260];
    __shared__ float ks[16][260];
    __shared__ float red[16][16];
    __shared__ int ci0s[16], ci1s[16];
    __shared__ float cosvs[16], maskf[16], wsh[16];

    const int n = blockIdx.x;
    const int tid = threadIdx.x;
    const int a_idx = anchor_idx[n];

    // ---- Phase 0: triplet geometry (16 threads) ----
    if (tid < 16) {
        int t = tid;
        float ax = 0.f, ay = 0.f;
        if (a_idx >= 0 && a_idx < N) {
            ax = pos[(size_t)a_idx * 3 + 0];
            ay = pos[(size_t)a_idx * 3 + 1];
        }
        int i0 = corner_idx[(size_t)n * 32 + 2 * t];
        int i1 = corner_idx[(size_t)n * 32 + 2 * t + 1];
        float p0x = 0.f, p0y = 0.f, p1x = 0.f, p1y = 0.f;
        if (i0 >= 0 && i0 < N) { p0x = pos[(size_t)i0 * 3]; p0y = pos[(size_t)i0 * 3 + 1]; }
        if (i1 >= 0 && i1 < N) { p1x = pos[(size_t)i1 * 3]; p1y = pos[(size_t)i1 * 3 + 1]; }
        float v0x = p0x - ax, v0y = p0y - ay;
        float v1x = p1x - ax, v1y = p1y - ay;
        float dot = v0x * v1x + v0y * v1y;
        float n0 = sqrtf(v0x * v0x + v0y * v0y);
        float n1 = sqrtf(v1x * v1x + v1y * v1y);
        float cosv = dot / (n0 * n1 + 1e-6f);
        float sinz = v0x * v1y - v0y * v1x;
        bool reorder = sinz < 0.0f;
        ci0s[t] = reorder ? i1 : i0;
        ci1s[t] = reorder ? i0 : i1;
        cosvs[t] = cosv;
        int mb = masks[(size_t)n * 16 + t];
        maskf[t] = (mb != 0) ? 1.0f : 0.0f;
        if (write_masks) {
            float newsin = reorder ? -sinz : sinz;  // fp-exact negation
            out[(size_t)N * 512 + (size_t)n * 16 + t] =
                ((newsin < -1e-6f) && (mb != 0)) ? 1.0f : 0.0f;
        }
    }
    __syncthreads();

    // ---- Phase 1: sinusoidal angle embedding (transposed) ----
#pragma unroll
    for (int l = 0; l < 2; l++) {
        int p = tid + l * 256;      // 512 (t, m) pairs
        int t = p >> 5, m = p & 31;
        float om = cosvs[t] * expf(-0.28782313662425572f * (float)m);
        float s, co;
        sincosf(om, &s, &co);
        angT[2 * m + 0][t] = s;
        angT[2 * m + 1][t] = co;
    }
    __syncthreads();

    // ---- Phase 2: gather P/Q rows + angle GEMM (thread = channel c) ----
    const int c = tid;
    float q[16], kv[16], vv[16];
#pragma unroll
    for (int t = 0; t < 16; t++) {
        int i0 = ci0s[t]; if (i0 < 0 || i0 > N) i0 = N;
        int i1 = ci1s[t]; if (i1 < 0 || i1 > N) i1 = N;
        const float* r0 = g_PQ + (size_t)i0 * 1536;
        const float* r1 = g_PQ + (size_t)i1 * 1536 + 768;
        q[t]  = r0[c]       + r1[c];
        kv[t] = r0[256 + c] + r1[256 + c];
        vv[t] = r0[512 + c] + r1[512 + c];
    }

#define ANG_STEP(T, AV)                        \
    q[T]  = fmaf((AV), w0, q[T]);              \
    kv[T] = fmaf((AV), w1, kv[T]);             \
    vv[T] = fmaf((AV), w2, vv[T]);

#pragma unroll 8
    for (int m = 0; m < 64; m++) {
        float w0 = g_WaT[m * 768 + c];
        float w1 = g_WaT[m * 768 + 256 + c];
        float w2 = g_WaT[m * 768 + 512 + c];
        float4 a0 = *(const float4*)&angT[m][0];
        float4 a1 = *(const float4*)&angT[m][4];
        float4 a2 = *(const float4*)&angT[m][8];
        float4 a3 = *(const float4*)&angT[m][12];
        ANG_STEP(0, a0.x)  ANG_STEP(1, a0.y)  ANG_STEP(2, a0.z)  ANG_STEP(3, a0.w)
        ANG_STEP(4, a1.x)  ANG_STEP(5, a1.y)  ANG_STEP(6, a1.z)  ANG_STEP(7, a1.w)
        ANG_STEP(8, a2.x)  ANG_STEP(9, a2.y)  ANG_STEP(10, a2.z) ANG_STEP(11, a2.w)
        ANG_STEP(12, a3.x) ANG_STEP(13, a3.y) ANG_STEP(14, a3.z) ANG_STEP(15, a3.w)
    }
#undef ANG_STEP

    // ---- Phase 3: stage q, k to smem (v stays in registers) ----
#pragma unroll
    for (int t = 0; t < 16; t++) {
        qs[t][c] = q[t];
        ks[t][c] = kv[t];
    }
    __syncthreads();

    // ---- Phase 4: 16x16 scores + softmax. thread -> (a, b) ----
    {
        int aa = tid >> 4, bb = tid & 15;
        float dotv = 0.0f;
        const float4* qrow = (const float4*)&qs[aa][0];
        const float4* krow = (const float4*)&ks[bb][0];
#pragma unroll 8
        for (int c4 = 0; c4 < 64; c4++) {
            float4 qv4 = qrow[c4];
            float4 kv4 = krow[c4];
            dotv += qv4.x * kv4.x + qv4.y * kv4.y + qv4.z * kv4.z + qv4.w * kv4.w;
        }
        float sc = dotv * 0.0625f;  // / sqrt(256)
        float mx = sc;
#pragma unroll
        for (int off = 8; off > 0; off >>= 1)
            mx = fmaxf(mx, __shfl_xor_sync(0xffffffffu, mx, off, 16));
        float e = expf(sc - mx);
        float sm = e;
#pragma unroll
        for (int off = 8; off > 0; off >>= 1)
            sm += __shfl_xor_sync(0xffffffffu, sm, off, 16);
        float attn = e / sm;
        red[aa][bb] = maskf[aa] * attn;
    }
    __syncthreads();

    // ---- Phase 5: fold mask-mean into per-k weights ----
    if (tid < 16) {
        float s = 0.0f, dn = 0.0f;
#pragma unroll
        for (int a2 = 0; a2 < 16; a2++) {
            s += red[a2][tid];
            dn += maskf[a2];
        }
        wsh[tid] = s / dn;
    }
    __syncthreads();

    // ---- Phase 6: mean[c] = sum_t w_t * v[t][c]; scatter ----
    float mean = 0.0f;
#pragma unroll
    for (int t = 0; t < 16; t++) mean = fmaf(wsh[t], vv[t], mean);
    if (a_idx >= 0 && a_idx < N)
        out[(size_t)a_idx * 512 + 256 + c] = mean;
}

// ----------------------------------------------------------------------------
extern "C" void kernel_launch(void* const* d_in, const int* in_sizes, int n_in,
                              void* d_out, int out_size) {
    if (n_in < 7) return;
    const float* x = (const float*)d_in[0];
    const float* pos = (const float*)d_in[1];
    const int* anchor = (const int*)d_in[2];
    const int* corner = (const int*)d_in[3];
    const int* masks = (const int*)d_in[4];
    const float* W = (const float*)d_in[5];
    const float* bias = (const float*)d_in[6];
    float* out = (float*)d_out;

    int N = in_sizes[0] / 256;
    if (N > MAXN) N = MAXN;
    int write_masks = (out_size >= N * 512 + N * 16) ? 1 : 0;

    const int prep_work = 256 * 1536 + 64 * 768 + 1536;
    prep_kernel<<<(prep_work + 255) / 256, 256>>>(W, bias, N);
    out_init_kernel<<<(N * 512 + 255) / 256, 256>>>(x, out, N);

    dim3 gg(1536 / 128, (N + 127) / 128);
    sgemm_pq_kernel<<<gg, 256>>>(x, bias, N);

    triplet_main_kernel<<<N, 256>>>(pos, anchor, corner, masks, out, N, write_masks);
}

// round 4
// speedup vs baseline: 1.1227x; 1.1227x over previous
#include <cuda_runtime.h>
#include <cuda_fp16.h>
#include <math.h>
#include <stdint.h>
#include <stddef.h>

// ============================================================================
// TripletGNN decomposition:
//   qkv(n,t) = P[ci0] + Q[ci1] + ang(n,t) @ Wa^T
//   P = x @ W[:,0:256]^T + b ; Q = x @ W[:,256:512]^T ; Wa = W[:,512:576]
// fp16 WaT storage (2x L1 bandwidth), f32x2 packed FMA (2x fp32 throughput),
// double-buffered SGEMM.
// ============================================================================

#define MAXN 40000

typedef unsigned long long u64;

__device__ float  g_PQ[(size_t)(MAXN + 1) * 1536]; // [i][0:768]=P(+b),[768:]=Q
__device__ float  g_Bmat[256 * 1536];              // B[c][j] for the SGEMM
__device__ __half2 g_WaTh[32 * 768];               // [m2][j] = (WaT[2m2][j], WaT[2m2+1][j])

// ---------------------------------------------------------------- helpers ---
__device__ __forceinline__ u64 ffma2(u64 a, u64 b, u64 c) {
    u64 d;
    asm("fma.rn.f32x2 %0, %1, %2, %3;" : "=l"(d) : "l"(a), "l"(b), "l"(c));
    return d;
}
__device__ __forceinline__ u64 pack2(float lo, float hi) {
    u64 d;
    asm("mov.b64 %0, {%1, %2};" : "=l"(d) : "f"(lo), "f"(hi));
    return d;
}
__device__ __forceinline__ float lo32(u64 v) {
    return __uint_as_float((unsigned)(v & 0xffffffffull));
}
__device__ __forceinline__ float hi32(u64 v) {
    return __uint_as_float((unsigned)(v >> 32));
}

// ------------------------------------------------------------------- prep ---
__global__ void prep_kernel(const float* __restrict__ W,
                            const float* __restrict__ bias, int N) {
    int idx = blockIdx.x * blockDim.x + threadIdx.x;
    const int B_SZ = 256 * 1536;
    const int WH_SZ = 32 * 768;
    if (idx < B_SZ) {
        int c = idx / 1536, j = idx % 1536;
        g_Bmat[idx] = (j < 768) ? W[j * 576 + c] : W[(j - 768) * 576 + 256 + c];
    } else if (idx < B_SZ + WH_SZ) {
        int r = idx - B_SZ;
        int m2 = r / 768, j = r % 768;
        float lo = W[j * 576 + 512 + 2 * m2];
        float hi = W[j * 576 + 512 + 2 * m2 + 1];
        g_WaTh[r] = __halves2half2(__float2half(lo), __float2half(hi));
    } else if (idx < B_SZ + WH_SZ + 1536) {
        int j = idx - (B_SZ + WH_SZ);
        g_PQ[(size_t)N * 1536 + j] = (j < 768) ? bias[j] : 0.0f;
    }
}

// out[:,0:256] = x ; out[:,256:512] = 0
__global__ void out_init_kernel(const float* __restrict__ x,
                                float* __restrict__ out, int N) {
    int idx = blockIdx.x * blockDim.x + threadIdx.x;
    if (idx < N * 512) {
        int r = idx >> 9, cc = idx & 511;
        out[idx] = (cc < 256) ? x[((size_t)r << 8) + cc] : 0.0f;
    }
}

// ------------------------------------------------------------------ SGEMM ---
// g_PQ[M x 1536] = X[M x 256] @ g_Bmat[256 x 1536] (+bias on j<768)
// 128x128 tile, 256 threads, 8x8 micro-tile as 4x8 FFMA2, double-buffered.
__global__ __launch_bounds__(256, 2)
void sgemm_pq_kernel(const float* __restrict__ X,
                     const float* __restrict__ bias, int M) {
    __shared__ __align__(16) float As[2][16][132];
    __shared__ __align__(16) float Bs[2][16][128];

    const int tid = threadIdx.x;
    const int tx = tid & 15;
    const int ty = tid >> 4;
    const int row0 = blockIdx.y * 128;
    const int col0 = blockIdx.x * 128;

    u64 acc2[4][8];
#pragma unroll
    for (int i = 0; i < 4; i++)
#pragma unroll
        for (int j = 0; j < 8; j++) acc2[i][j] = 0ull;

    float4 aReg[2], bReg[2];

#define LDG_TILE(KK)                                                          \
    {                                                                         \
        _Pragma("unroll") for (int l = 0; l < 2; l++) {                       \
            int fid = tid + l * 256;                                          \
            int i = fid >> 2;                                                 \
            int kq = fid & 3;                                                 \
            int grow = row0 + i;                                              \
            aReg[l] = make_float4(0.f, 0.f, 0.f, 0.f);                        \
            if (grow < M)                                                     \
                aReg[l] = *(const float4*)(X + (size_t)grow * 256 + (KK) + kq * 4); \
        }                                                                     \
        _Pragma("unroll") for (int l = 0; l < 2; l++) {                       \
            int fid = tid + l * 256;                                          \
            int k = fid >> 5;                                                 \
            int j4 = fid & 31;                                                \
            bReg[l] = *(const float4*)(g_Bmat + (size_t)((KK) + k) * 1536 + col0 + j4 * 4); \
        }                                                                     \
    }

#define STS_TILE(BUF)                                                         \
    {                                                                         \
        _Pragma("unroll") for (int l = 0; l < 2; l++) {                       \
            int fid = tid + l * 256;                                          \
            int i = fid >> 2;                                                 \
            int kq = fid & 3;                                                 \
            As[BUF][kq * 4 + 0][i] = aReg[l].x;                               \
            As[BUF][kq * 4 + 1][i] = aReg[l].y;                               \
            As[BUF][kq * 4 + 2][i] = aReg[l].z;                               \
            As[BUF][kq * 4 + 3][i] = aReg[l].w;                               \
        }                                                                     \
        _Pragma("unroll") for (int l = 0; l < 2; l++) {                       \
            int fid = tid + l * 256;                                          \
            int k = fid >> 5;                                                 \
            int j4 = fid & 31;                                                \
            *(float4*)&Bs[BUF][k][j4 * 4] = bReg[l];                          \
        }                                                                     \
    }

    LDG_TILE(0)
    STS_TILE(0)
    __syncthreads();

    const int NT = 16;  // 256 / 16
    for (int kt = 0; kt < NT; kt++) {
        int cur = kt & 1;
        if (kt + 1 < NT) LDG_TILE((kt + 1) * 16)

#pragma unroll
        for (int k = 0; k < 16; k++) {
            ulonglong2 A0 = *(const ulonglong2*)&As[cur][k][ty * 4];
            ulonglong2 A1 = *(const ulonglong2*)&As[cur][k][64 + ty * 4];
            float4 b0 = *(const float4*)&Bs[cur][k][tx * 4];
            float4 b1 = *(const float4*)&Bs[cur][k][64 + tx * 4];
            u64 br[8];
            br[0] = pack2(b0.x, b0.x); br[1] = pack2(b0.y, b0.y);
            br[2] = pack2(b0.z, b0.z); br[3] = pack2(b0.w, b0.w);
            br[4] = pack2(b1.x, b1.x); br[5] = pack2(b1.y, b1.y);
            br[6] = pack2(b1.z, b1.z); br[7] = pack2(b1.w, b1.w);
#pragma unroll
            for (int j = 0; j < 8; j++) {
                acc2[0][j] = ffma2(A0.x, br[j], acc2[0][j]);
                acc2[1][j] = ffma2(A0.y, br[j], acc2[1][j]);
                acc2[2][j] = ffma2(A1.x, br[j], acc2[2][j]);
                acc2[3][j] = ffma2(A1.y, br[j], acc2[3][j]);
            }
        }
        if (kt + 1 < NT) STS_TILE((kt + 1) & 1)
        __syncthreads();
    }
#undef LDG_TILE
#undef STS_TILE

    // Epilogue (+bias for j<768). acc2[i2][j]: lo -> ri=2*i2, hi -> ri=2*i2+1.
#pragma unroll
    for (int half = 0; half < 2; half++) {
#pragma unroll
        for (int r = 0; r < 4; r++) {
            int grow = row0 + half * 64 + ty * 4 + r;
            if (grow >= M) continue;
            int ri = half * 4 + r;
            int i2 = ri >> 1, sel = ri & 1;
#pragma unroll
            for (int ch = 0; ch < 2; ch++) {
                int gcol = col0 + ch * 64 + tx * 4;
                float4 o;
                o.x = sel ? hi32(acc2[i2][ch * 4 + 0]) : lo32(acc2[i2][ch * 4 + 0]);
                o.y = sel ? hi32(acc2[i2][ch * 4 + 1]) : lo32(acc2[i2][ch * 4 + 1]);
                o.z = sel ? hi32(acc2[i2][ch * 4 + 2]) : lo32(acc2[i2][ch * 4 + 2]);
                o.w = sel ? hi32(acc2[i2][ch * 4 + 3]) : lo32(acc2[i2][ch * 4 + 3]);
                if (gcol < 768) {
                    o.x += bias[gcol + 0];
                    o.y += bias[gcol + 1];
                    o.z += bias[gcol + 2];
                    o.w += bias[gcol + 3];
                }
                *(float4*)(g_PQ + (size_t)grow * 1536 + gcol) = o;
            }
        }
    }
}

// --------------------------------------------------------------- main ------
__global__ __launch_bounds__(256, 2)
void triplet_main_kernel(const float* __restrict__ pos,
                         const int* __restrict__ anchor_idx,
                         const int* __restrict__ corner_idx,
                         const int* __restrict__ masks,  // int32 bool
                         float* __restrict__ out,
                         int N, int write_masks) {
    __shared__ __align__(16) float angT[64][16];
    __shared__ __align__(16) float qs[16][260];
    __shared__ __align__(16) float ks[16][260];
    __shared__ __align__(16) float red[16][16];
    __shared__ int ci0s[16], ci1s[16];
    __shared__ __align__(16) float cosvs[16];
    __shared__ __align__(16) float maskf[16];
    __shared__ __align__(16) float wsh[16];

    const int n = blockIdx.x;
    const int tid = threadIdx.x;
    const int a_idx = anchor_idx[n];

    // ---- Phase 0: triplet geometry ----
    if (tid < 16) {
        int t = tid;
        float ax = 0.f, ay = 0.f;
        if (a_idx >= 0 && a_idx < N) {
            ax = pos[(size_t)a_idx * 3 + 0];
            ay = pos[(size_t)a_idx * 3 + 1];
        }
        int i0 = corner_idx[(size_t)n * 32 + 2 * t];
        int i1 = corner_idx[(size_t)n * 32 + 2 * t + 1];
        float p0x = 0.f, p0y = 0.f, p1x = 0.f, p1y = 0.f;
        if (i0 >= 0 && i0 < N) { p0x = pos[(size_t)i0 * 3]; p0y = pos[(size_t)i0 * 3 + 1]; }
        if (i1 >= 0 && i1 < N) { p1x = pos[(size_t)i1 * 3]; p1y = pos[(size_t)i1 * 3 + 1]; }
        float v0x = p0x - ax, v0y = p0y - ay;
        float v1x = p1x - ax, v1y = p1y - ay;
        float dot = v0x * v1x + v0y * v1y;
        float n0 = sqrtf(v0x * v0x + v0y * v0y);
        float n1 = sqrtf(v1x * v1x + v1y * v1y);
        float cosv = dot / (n0 * n1 + 1e-6f);
        float sinz = v0x * v1y - v0y * v1x;
        bool reorder = sinz < 0.0f;
        ci0s[t] = reorder ? i1 : i0;
        ci1s[t] = reorder ? i0 : i1;
        cosvs[t] = cosv;
        int mb = masks[(size_t)n * 16 + t];
        maskf[t] = (mb != 0) ? 1.0f : 0.0f;
        if (write_masks) {
            float newsin = reorder ? -sinz : sinz;  // fp-exact negation
            out[(size_t)N * 512 + (size_t)n * 16 + t] =
                ((newsin < -1e-6f) && (mb != 0)) ? 1.0f : 0.0f;
        }
    }
    __syncthreads();

    // ---- Phase 1: sinusoidal embedding (transposed) ----
#pragma unroll
    for (int l = 0; l < 2; l++) {
        int p = tid + l * 256;
        int t = p >> 5, m = p & 31;
        float om = cosvs[t] * expf(-0.28782313662425572f * (float)m);
        float s, co;
        sincosf(om, &s, &co);
        angT[2 * m + 0][t] = s;
        angT[2 * m + 1][t] = co;
    }
    __syncthreads();

    // ---- Phase 2: gathers + angle GEMM (thread = channel, t packed x2) ----
    const int c = tid;
    u64 q2[8], k2[8], v2[8];
#pragma unroll
    for (int t2 = 0; t2 < 8; t2++) {
        int ia = ci0s[2 * t2];     if (ia < 0 || ia > N) ia = N;
        int ib = ci1s[2 * t2];     if (ib < 0 || ib > N) ib = N;
        int ic = ci0s[2 * t2 + 1]; if (ic < 0 || ic > N) ic = N;
        int id = ci1s[2 * t2 + 1]; if (id < 0 || id > N) id = N;
        const float* ra = g_PQ + (size_t)ia * 1536;
        const float* rb = g_PQ + (size_t)ib * 1536 + 768;
        const float* rc = g_PQ + (size_t)ic * 1536;
        const float* rd = g_PQ + (size_t)id * 1536 + 768;
        q2[t2] = pack2(ra[c] + rb[c], rc[c] + rd[c]);
        k2[t2] = pack2(ra[256 + c] + rb[256 + c], rc[256 + c] + rd[256 + c]);
        v2[t2] = pack2(ra[512 + c] + rb[512 + c], rc[512 + c] + rd[512 + c]);
    }

#pragma unroll 4
    for (int m2 = 0; m2 < 32; m2++) {
        const __half2* wrow = g_WaTh + m2 * 768;
        float2 w0 = __half22float2(wrow[c]);
        float2 w1 = __half22float2(wrow[256 + c]);
        float2 w2 = __half22float2(wrow[512 + c]);
#pragma unroll
        for (int mi = 0; mi < 2; mi++) {
            int m = 2 * m2 + mi;
            float w0s = mi ? w0.y : w0.x;
            float w1s = mi ? w1.y : w1.x;
            float w2s = mi ? w2.y : w2.x;
            u64 w0r = pack2(w0s, w0s);
            u64 w1r = pack2(w1s, w1s);
            u64 w2r = pack2(w2s, w2s);
            ulonglong2 pa = *(const ulonglong2*)&angT[m][0];
            ulonglong2 pb = *(const ulonglong2*)&angT[m][4];
            ulonglong2 pc = *(const ulonglong2*)&angT[m][8];
            ulonglong2 pd = *(const ulonglong2*)&angT[m][12];
            q2[0] = ffma2(pa.x, w0r, q2[0]); k2[0] = ffma2(pa.x, w1r, k2[0]); v2[0] = ffma2(pa.x, w2r, v2[0]);
            q2[1] = ffma2(pa.y, w0r, q2[1]); k2[1] = ffma2(pa.y, w1r, k2[1]); v2[1] = ffma2(pa.y, w2r, v2[1]);
            q2[2] = ffma2(pb.x, w0r, q2[2]); k2[2] = ffma2(pb.x, w1r, k2[2]); v2[2] = ffma2(pb.x, w2r, v2[2]);
            q2[3] = ffma2(pb.y, w0r, q2[3]); k2[3] = ffma2(pb.y, w1r, k2[3]); v2[3] = ffma2(pb.y, w2r, v2[3]);
            q2[4] = ffma2(pc.x, w0r, q2[4]); k2[4] = ffma2(pc.x, w1r, k2[4]); v2[4] = ffma2(pc.x, w2r, v2[4]);
            q2[5] = ffma2(pc.y, w0r, q2[5]); k2[5] = ffma2(pc.y, w1r, k2[5]); v2[5] = ffma2(pc.y, w2r, v2[5]);
            q2[6] = ffma2(pd.x, w0r, q2[6]); k2[6] = ffma2(pd.x, w1r, k2[6]); v2[6] = ffma2(pd.x, w2r, v2[6]);
            q2[7] = ffma2(pd.y, w0r, q2[7]); k2[7] = ffma2(pd.y, w1r, k2[7]); v2[7] = ffma2(pd.y, w2r, v2[7]);
        }
    }

    // ---- Phase 3: stage q, k to smem ----
#pragma unroll
    for (int t2 = 0; t2 < 8; t2++) {
        qs[2 * t2][c] = lo32(q2[t2]);
        qs[2 * t2 + 1][c] = hi32(q2[t2]);
        ks[2 * t2][c] = lo32(k2[t2]);
        ks[2 * t2 + 1][c] = hi32(k2[t2]);
    }
    __syncthreads();

    // ---- Phase 4: 16x16 scores + softmax ----
    {
        int aa = tid >> 4, bb = tid & 15;
        const ulonglong2* qrow = (const ulonglong2*)&qs[aa][0];
        const ulonglong2* krow = (const ulonglong2*)&ks[bb][0];
        u64 acc = pack2(0.f, 0.f);
#pragma unroll 8
        for (int c4 = 0; c4 < 64; c4++) {
            ulonglong2 qv = qrow[c4];
            ulonglong2 kv = krow[c4];
            acc = ffma2(qv.x, kv.x, acc);
            acc = ffma2(qv.y, kv.y, acc);
        }
        float dotv = lo32(acc) + hi32(acc);
        float sc = dotv * 0.0625f;  // / sqrt(256)
        float mx = sc;
#pragma unroll
        for (int off = 8; off > 0; off >>= 1)
            mx = fmaxf(mx, __shfl_xor_sync(0xffffffffu, mx, off, 16));
        float e = expf(sc - mx);
        float sm = e;
#pragma unroll
        for (int off = 8; off > 0; off >>= 1)
            sm += __shfl_xor_sync(0xffffffffu, sm, off, 16);
        float attn = e / sm;
        red[aa][bb] = maskf[aa] * attn;
    }
    __syncthreads();

    // ---- Phase 5: fold mask-mean into per-k weights ----
    if (tid < 16) {
        float s = 0.0f, dn = 0.0f;
#pragma unroll
        for (int a2 = 0; a2 < 16; a2++) {
            s += red[a2][tid];
            dn += maskf[a2];
        }
        wsh[tid] = s / dn;
    }
    __syncthreads();

    // ---- Phase 6: mean[c] = sum_t w_t * v[t][c]; scatter ----
    u64 macc = pack2(0.f, 0.f);
    const u64* wp = (const u64*)wsh;
#pragma unroll
    for (int t2 = 0; t2 < 8; t2++) macc = ffma2(wp[t2], v2[t2], macc);
    float mean = lo32(macc) + hi32(macc);
    if (a_idx >= 0 && a_idx < N)
        out[(size_t)a_idx * 512 + 256 + c] = mean;
}

// ----------------------------------------------------------------------------
extern "C" void kernel_launch(void* const* d_in, const int* in_sizes, int n_in,
                              void* d_out, int out_size) {
    if (n_in < 7) return;
    const float* x = (const float*)d_in[0];
    const float* pos = (const float*)d_in[1];
    const int* anchor = (const int*)d_in[2];
    const int* corner = (const int*)d_in[3];
    const int* masks = (const int*)d_in[4];
    const float* W = (const float*)d_in[5];
    const float* bias = (const float*)d_in[6];
    float* out = (float*)d_out;

    int N = in_sizes[0] / 256;
    if (N > MAXN) N = MAXN;
    int write_masks = (out_size >= N * 512 + N * 16) ? 1 : 0;

    const int prep_work = 256 * 1536 + 32 * 768 + 1536;
    prep_kernel<<<(prep_work + 255) / 256, 256>>>(W, bias, N);
    out_init_kernel<<<(N * 512 + 255) / 256, 256>>>(x, out, N);

    dim3 gg(1536 / 128, (N + 127) / 128);
    sgemm_pq_kernel<<<gg, 256>>>(x, bias, N);

    triplet_main_kernel<<<N, 256>>>(pos, anchor, corner, masks, out, N, write_masks);
}

// round 5
// speedup vs baseline: 1.1833x; 1.0540x over previous
#include <cuda_runtime.h>
#include <cuda_fp16.h>
#include <math.h>
#include <stdint.h>
#include <stddef.h>

// ============================================================================
// TripletGNN decomposition:
//   qkv(n,t) = P[ci0] + Q[ci1] + ang(n,t) @ Wa^T
//   P = x @ W[:,0:256]^T + b ; Q = x @ W[:,256:512]^T ; Wa = W[:,512:576]
// Round 5: triplet_main thread layout = (channel-pair f32x2, t-half).
// Halves angT LDS wavefronts and PQ gather wavefronts at equal FLOPs.
// ============================================================================

#define MAXN 40000

typedef unsigned long long u64;

__device__ float  g_PQ[(size_t)(MAXN + 1) * 1536]; // [i][0:768]=P(+b),[768:]=Q
__device__ float  g_Bmat[256 * 1536];              // B[c][j] for the SGEMM
// WaT packed: [m2][sect][cp] uint2; .x=half2(w[2m2][2cp],w[2m2][2cp+1]),
//                                   .y=half2(w[2m2+1][2cp],w[2m2+1][2cp+1])
__device__ uint2  g_WaTq[32 * 3 * 128];

// ---------------------------------------------------------------- helpers ---
__device__ __forceinline__ u64 ffma2(u64 a, u64 b, u64 c) {
    u64 d;
    asm("fma.rn.f32x2 %0, %1, %2, %3;" : "=l"(d) : "l"(a), "l"(b), "l"(c));
    return d;
}
__device__ __forceinline__ u64 fadd2(u64 a, u64 b) {
    u64 d;
    asm("add.rn.f32x2 %0, %1, %2;" : "=l"(d) : "l"(a), "l"(b));
    return d;
}
__device__ __forceinline__ u64 pack2(float lo, float hi) {
    u64 d;
    asm("mov.b64 %0, {%1, %2};" : "=l"(d) : "f"(lo), "f"(hi));
    return d;
}
__device__ __forceinline__ float lo32(u64 v) {
    return __uint_as_float((unsigned)(v & 0xffffffffull));
}
__device__ __forceinline__ float hi32(u64 v) {
    return __uint_as_float((unsigned)(v >> 32));
}

// ------------------------------------------------------------------- prep ---
__global__ void prep_kernel(const float* __restrict__ W,
                            const float* __restrict__ bias, int N) {
    int idx = blockIdx.x * blockDim.x + threadIdx.x;
    const int B_SZ = 256 * 1536;
    const int WQ_SZ = 32 * 3 * 128;
    if (idx < B_SZ) {
        int c = idx / 1536, j = idx % 1536;
        g_Bmat[idx] = (j < 768) ? W[j * 576 + c] : W[(j - 768) * 576 + 256 + c];
    } else if (idx < B_SZ + WQ_SZ) {
        int r = idx - B_SZ;
        int m2 = r / 384;
        int rem = r % 384;
        int sect = rem / 128, cp = rem % 128;
        int j = sect * 256 + 2 * cp;             // WaT column (0..767)
        float a0 = W[j * 576 + 512 + 2 * m2];        // m=2m2,   ch j
        float b0 = W[(j + 1) * 576 + 512 + 2 * m2];  // m=2m2,   ch j+1
        float a1 = W[j * 576 + 512 + 2 * m2 + 1];    // m=2m2+1, ch j
        float b1 = W[(j + 1) * 576 + 512 + 2 * m2 + 1];
        uint2 v;
        __half2 h0 = __halves2half2(__float2half(a0), __float2half(b0));
        __half2 h1 = __halves2half2(__float2half(a1), __float2half(b1));
        v.x = *(unsigned*)&h0;
        v.y = *(unsigned*)&h1;
        g_WaTq[r] = v;
    } else if (idx < B_SZ + WQ_SZ + 1536) {
        int j = idx - (B_SZ + WQ_SZ);
        g_PQ[(size_t)N * 1536 + j] = (j < 768) ? bias[j] : 0.0f;
    }
}

// out[:,0:256] = x ; out[:,256:512] = 0
__global__ void out_init_kernel(const float* __restrict__ x,
                                float* __restrict__ out, int N) {
    int idx = blockIdx.x * blockDim.x + threadIdx.x;
    if (idx < N * 512) {
        int r = idx >> 9, cc = idx & 511;
        out[idx] = (cc < 256) ? x[((size_t)r << 8) + cc] : 0.0f;
    }
}

// ------------------------------------------------------------------ SGEMM ---
// g_PQ[M x 1536] = X[M x 256] @ g_Bmat[256 x 1536] (+bias on j<768)
__global__ __launch_bounds__(256, 2)
void sgemm_pq_kernel(const float* __restrict__ X,
                     const float* __restrict__ bias, int M) {
    __shared__ __align__(16) float As[2][16][132];
    __shared__ __align__(16) float Bs[2][16][128];

    const int tid = threadIdx.x;
    const int tx = tid & 15;
    const int ty = tid >> 4;
    const int row0 = blockIdx.y * 128;
    const int col0 = blockIdx.x * 128;

    u64 acc2[4][8];
#pragma unroll
    for (int i = 0; i < 4; i++)
#pragma unroll
        for (int j = 0; j < 8; j++) acc2[i][j] = 0ull;

    float4 aReg[2], bReg[2];

#define LDG_TILE(KK)                                                          \
    {                                                                         \
        _Pragma("unroll") for (int l = 0; l < 2; l++) {                       \
            int fid = tid + l * 256;                                          \
            int i = fid >> 2;                                                 \
            int kq = fid & 3;                                                 \
            int grow = row0 + i;                                              \
            aReg[l] = make_float4(0.f, 0.f, 0.f, 0.f);                        \
            if (grow < M)                                                     \
                aReg[l] = *(const float4*)(X + (size_t)grow * 256 + (KK) + kq * 4); \
        }                                                                     \
        _Pragma("unroll") for (int l = 0; l < 2; l++) {                       \
            int fid = tid + l * 256;                                          \
            int k = fid >> 5;                                                 \
            int j4 = fid & 31;                                                \
            bReg[l] = *(const float4*)(g_Bmat + (size_t)((KK) + k) * 1536 + col0 + j4 * 4); \
        }                                                                     \
    }

#define STS_TILE(BUF)                                                         \
    {                                                                         \
        _Pragma("unroll") for (int l = 0; l < 2; l++) {                       \
            int fid = tid + l * 256;                                          \
            int i = fid >> 2;                                                 \
            int kq = fid & 3;                                                 \
            As[BUF][kq * 4 + 0][i] = aReg[l].x;                               \
            As[BUF][kq * 4 + 1][i] = aReg[l].y;                               \
            As[BUF][kq * 4 + 2][i] = aReg[l].z;                               \
            As[BUF][kq * 4 + 3][i] = aReg[l].w;                               \
        }                                                                     \
        _Pragma("unroll") for (int l = 0; l < 2; l++) {                       \
            int fid = tid + l * 256;                                          \
            int k = fid >> 5;                                                 \
            int j4 = fid & 31;                                                \
            *(float4*)&Bs[BUF][k][j4 * 4] = bReg[l];                          \
        }                                                                     \
    }

    LDG_TILE(0)
    STS_TILE(0)
    __syncthreads();

    const int NT = 16;
    for (int kt = 0; kt < NT; kt++) {
        int cur = kt & 1;
        if (kt + 1 < NT) LDG_TILE((kt + 1) * 16)

#pragma unroll
        for (int k = 0; k < 16; k++) {
            ulonglong2 A0 = *(const ulonglong2*)&As[cur][k][ty * 4];
            ulonglong2 A1 = *(const ulonglong2*)&As[cur][k][64 + ty * 4];
            float4 b0 = *(const float4*)&Bs[cur][k][tx * 4];
            float4 b1 = *(const float4*)&Bs[cur][k][64 + tx * 4];
            u64 br[8];
            br[0] = pack2(b0.x, b0.x); br[1] = pack2(b0.y, b0.y);
            br[2] = pack2(b0.z, b0.z); br[3] = pack2(b0.w, b0.w);
            br[4] = pack2(b1.x, b1.x); br[5] = pack2(b1.y, b1.y);
            br[6] = pack2(b1.z, b1.z); br[7] = pack2(b1.w, b1.w);
#pragma unroll
            for (int j = 0; j < 8; j++) {
                acc2[0][j] = ffma2(A0.x, br[j], acc2[0][j]);
                acc2[1][j] = ffma2(A0.y, br[j], acc2[1][j]);
                acc2[2][j] = ffma2(A1.x, br[j], acc2[2][j]);
                acc2[3][j] = ffma2(A1.y, br[j], acc2[3][j]);
            }
        }
        if (kt + 1 < NT) STS_TILE((kt + 1) & 1)
        __syncthreads();
    }
#undef LDG_TILE
#undef STS_TILE

#pragma unroll
    for (int half = 0; half < 2; half++) {
#pragma unroll
        for (int r = 0; r < 4; r++) {
            int grow = row0 + half * 64 + ty * 4 + r;
            if (grow >= M) continue;
            int ri = half * 4 + r;
            int i2 = ri >> 1, sel = ri & 1;
#pragma unroll
            for (int ch = 0; ch < 2; ch++) {
                int gcol = col0 + ch * 64 + tx * 4;
                float4 o;
                o.x = sel ? hi32(acc2[i2][ch * 4 + 0]) : lo32(acc2[i2][ch * 4 + 0]);
                o.y = sel ? hi32(acc2[i2][ch * 4 + 1]) : lo32(acc2[i2][ch * 4 + 1]);
                o.z = sel ? hi32(acc2[i2][ch * 4 + 2]) : lo32(acc2[i2][ch * 4 + 2]);
                o.w = sel ? hi32(acc2[i2][ch * 4 + 3]) : lo32(acc2[i2][ch * 4 + 3]);
                if (gcol < 768) {
                    o.x += bias[gcol + 0];
                    o.y += bias[gcol + 1];
                    o.z += bias[gcol + 2];
                    o.w += bias[gcol + 3];
                }
                *(float4*)(g_PQ + (size_t)grow * 1536 + gcol) = o;
            }
        }
    }
}

// --------------------------------------------------------------- main ------
// Thread layout: cp = tid & 127 -> channels (2cp, 2cp+1) packed in f32x2;
//                th = tid >> 7  -> t in [8*th, 8*th+8). th uniform per warp.
__global__ __launch_bounds__(256, 2)
void triplet_main_kernel(const float* __restrict__ pos,
                         const int* __restrict__ anchor_idx,
                         const int* __restrict__ corner_idx,
                         const int* __restrict__ masks,  // int32 bool
                         float* __restrict__ out,
                         int N, int write_masks) {
    __shared__ __align__(16) float angT[64][16];
    __shared__ __align__(16) float qs[16][260];
    __shared__ __align__(16) float ks[16][260];
    __shared__ __align__(16) float red[16][16];
    __shared__ __align__(16) u64 vp[2][128];
    __shared__ int ci0s[16], ci1s[16];
    __shared__ __align__(16) float cosvs[16];
    __shared__ __align__(16) float maskf[16];
    __shared__ __align__(16) float wsh[16];

    const int n = blockIdx.x;
    const int tid = threadIdx.x;
    const int cp = tid & 127;
    const int th = tid >> 7;
    const int a_idx = anchor_idx[n];

    // ---- Phase 0: triplet geometry ----
    if (tid < 16) {
        int t = tid;
        float ax = 0.f, ay = 0.f;
        if (a_idx >= 0 && a_idx < N) {
            ax = pos[(size_t)a_idx * 3 + 0];
            ay = pos[(size_t)a_idx * 3 + 1];
        }
        int i0 = corner_idx[(size_t)n * 32 + 2 * t];
        int i1 = corner_idx[(size_t)n * 32 + 2 * t + 1];
        float p0x = 0.f, p0y = 0.f, p1x = 0.f, p1y = 0.f;
        if (i0 >= 0 && i0 < N) { p0x = pos[(size_t)i0 * 3]; p0y = pos[(size_t)i0 * 3 + 1]; }
        if (i1 >= 0 && i1 < N) { p1x = pos[(size_t)i1 * 3]; p1y = pos[(size_t)i1 * 3 + 1]; }
        float v0x = p0x - ax, v0y = p0y - ay;
        float v1x = p1x - ax, v1y = p1y - ay;
        float dot = v0x * v1x + v0y * v1y;
        float n0 = sqrtf(v0x * v0x + v0y * v0y);
        float n1 = sqrtf(v1x * v1x + v1y * v1y);
        float cosv = dot / (n0 * n1 + 1e-6f);
        float sinz = v0x * v1y - v0y * v1x;
        bool reorder = sinz < 0.0f;
        ci0s[t] = reorder ? i1 : i0;
        ci1s[t] = reorder ? i0 : i1;
        cosvs[t] = cosv;
        int mb = masks[(size_t)n * 16 + t];
        maskf[t] = (mb != 0) ? 1.0f : 0.0f;
        if (write_masks) {
            float newsin = reorder ? -sinz : sinz;
            out[(size_t)N * 512 + (size_t)n * 16 + t] =
                ((newsin < -1e-6f) && (mb != 0)) ? 1.0f : 0.0f;
        }
    }
    __syncthreads();

    // ---- Phase 1: sinusoidal embedding (transposed) ----
#pragma unroll
    for (int l = 0; l < 2; l++) {
        int p = tid + l * 256;
        int t = p >> 5, m = p & 31;
        float om = cosvs[t] * expf(-0.28782313662425572f * (float)m);
        float s, co;
        sincosf(om, &s, &co);
        angT[2 * m + 0][t] = s;
        angT[2 * m + 1][t] = co;
    }
    __syncthreads();

    // ---- Phase 2: gathers (float2) + angle GEMM, channels packed in f32x2 ----
    u64 q2[8], k2[8], v2[8];
#pragma unroll
    for (int tt = 0; tt < 8; tt++) {
        int t = 8 * th + tt;
        int i0 = ci0s[t]; if (i0 < 0 || i0 > N) i0 = N;
        int i1 = ci1s[t]; if (i1 < 0 || i1 > N) i1 = N;
        const float2* r0 = (const float2*)(g_PQ + (size_t)i0 * 1536);
        const float2* r1 = (const float2*)(g_PQ + (size_t)i1 * 1536 + 768);
        float2 pq = r0[cp],        qq = r1[cp];
        float2 pk = r0[128 + cp],  qk = r1[128 + cp];
        float2 pv = r0[256 + cp],  qv = r1[256 + cp];
        q2[tt] = pack2(pq.x + qq.x, pq.y + qq.y);
        k2[tt] = pack2(pk.x + qk.x, pk.y + qk.y);
        v2[tt] = pack2(pv.x + qv.x, pv.y + qv.y);
    }

    // Software-pipelined WaT loads (uint2 = 2 m's x 2 channels, fp16)
    {
        const uint2* wbase = g_WaTq;
        uint2 wq = wbase[0 * 384 + 0 * 128 + cp];
        uint2 wk = wbase[0 * 384 + 1 * 128 + cp];
        uint2 wv = wbase[0 * 384 + 2 * 128 + cp];
#pragma unroll 4
        for (int m2 = 0; m2 < 32; m2++) {
            uint2 nq, nk, nv;
            if (m2 + 1 < 32) {
                nq = wbase[(m2 + 1) * 384 + 0 * 128 + cp];
                nk = wbase[(m2 + 1) * 384 + 1 * 128 + cp];
                nv = wbase[(m2 + 1) * 384 + 2 * 128 + cp];
            }
#pragma unroll
            for (int mi = 0; mi < 2; mi++) {
                int m = 2 * m2 + mi;
                unsigned hq = mi ? wq.y : wq.x;
                unsigned hk = mi ? wk.y : wk.x;
                unsigned hv = mi ? wv.y : wv.x;
                float2 fq = __half22float2(*(__half2*)&hq);
                float2 fk = __half22float2(*(__half2*)&hk);
                float2 fv = __half22float2(*(__half2*)&hv);
                u64 wqr = pack2(fq.x, fq.y);
                u64 wkr = pack2(fk.x, fk.y);
                u64 wvr = pack2(fv.x, fv.y);
                float4 alo = *(const float4*)&angT[m][8 * th];
                float4 ahi = *(const float4*)&angT[m][8 * th + 4];
                u64 a0 = pack2(alo.x, alo.x), a1 = pack2(alo.y, alo.y);
                u64 a2 = pack2(alo.z, alo.z), a3 = pack2(alo.w, alo.w);
                u64 a4 = pack2(ahi.x, ahi.x), a5 = pack2(ahi.y, ahi.y);
                u64 a6 = pack2(ahi.z, ahi.z), a7 = pack2(ahi.w, ahi.w);
                q2[0] = ffma2(a0, wqr, q2[0]); k2[0] = ffma2(a0, wkr, k2[0]); v2[0] = ffma2(a0, wvr, v2[0]);
                q2[1] = ffma2(a1, wqr, q2[1]); k2[1] = ffma2(a1, wkr, k2[1]); v2[1] = ffma2(a1, wvr, v2[1]);
                q2[2] = ffma2(a2, wqr, q2[2]); k2[2] = ffma2(a2, wkr, k2[2]); v2[2] = ffma2(a2, wvr, v2[2]);
                q2[3] = ffma2(a3, wqr, q2[3]); k2[3] = ffma2(a3, wkr, k2[3]); v2[3] = ffma2(a3, wvr, v2[3]);
                q2[4] = ffma2(a4, wqr, q2[4]); k2[4] = ffma2(a4, wkr, k2[4]); v2[4] = ffma2(a4, wvr, v2[4]);
                q2[5] = ffma2(a5, wqr, q2[5]); k2[5] = ffma2(a5, wkr, k2[5]); v2[5] = ffma2(a5, wvr, v2[5]);
                q2[6] = ffma2(a6, wqr, q2[6]); k2[6] = ffma2(a6, wkr, k2[6]); v2[6] = ffma2(a6, wvr, v2[6]);
                q2[7] = ffma2(a7, wqr, q2[7]); k2[7] = ffma2(a7, wkr, k2[7]); v2[7] = ffma2(a7, wvr, v2[7]);
            }
            wq = nq; wk = nk; wv = nv;
        }
    }

    // ---- Phase 3: stage q, k to smem (u64 store = 2 channels) ----
#pragma unroll
    for (int tt = 0; tt < 8; tt++) {
        int t = 8 * th + tt;
        *(u64*)&qs[t][2 * cp] = q2[tt];
        *(u64*)&ks[t][2 * cp] = k2[tt];
    }
    __syncthreads();

    // ---- Phase 4: 16x16 scores + softmax (thread = (a,b) pair) ----
    {
        int aa = tid >> 4, bb = tid & 15;
        const ulonglong2* qrow = (const ulonglong2*)&qs[aa][0];
        const ulonglong2* krow = (const ulonglong2*)&ks[bb][0];
        u64 acc = pack2(0.f, 0.f);
#pragma unroll 8
        for (int c4 = 0; c4 < 64; c4++) {
            ulonglong2 qv = qrow[c4];
            ulonglong2 kv = krow[c4];
            acc = ffma2(qv.x, kv.x, acc);
            acc = ffma2(qv.y, kv.y, acc);
        }
        float dotv = lo32(acc) + hi32(acc);
        float sc = dotv * 0.0625f;
        float mx = sc;
#pragma unroll
        for (int off = 8; off > 0; off >>= 1)
            mx = fmaxf(mx, __shfl_xor_sync(0xffffffffu, mx, off, 16));
        float e = expf(sc - mx);
        float sm = e;
#pragma unroll
        for (int off = 8; off > 0; off >>= 1)
            sm += __shfl_xor_sync(0xffffffffu, sm, off, 16);
        float attn = e / sm;
        red[aa][bb] = maskf[aa] * attn;
    }
    __syncthreads();

    // ---- Phase 5: fold mask-mean into per-k weights ----
    if (tid < 16) {
        float s = 0.0f, dn = 0.0f;
#pragma unroll
        for (int a2 = 0; a2 < 16; a2++) {
            s += red[a2][tid];
            dn += maskf[a2];
        }
        wsh[tid] = s / dn;
    }
    __syncthreads();

    // ---- Phase 6: mean over t (both halves), scatter float2 ----
    {
        u64 part = pack2(0.f, 0.f);
#pragma unroll
        for (int tt = 0; tt < 8; tt++) {
            float w = wsh[8 * th + tt];
            part = ffma2(pack2(w, w), v2[tt], part);
        }
        vp[th][cp] = part;
        __syncthreads();
        if (th == 0) {
            u64 tot = fadd2(vp[0][cp], vp[1][cp]);
            if (a_idx >= 0 && a_idx < N) {
                float2 o;
                o.x = lo32(tot);
                o.y = hi32(tot);
                *(float2*)(out + (size_t)a_idx * 512 + 256 + 2 * cp) = o;
            }
        }
    }
}

// ----------------------------------------------------------------------------
extern "C" void kernel_launch(void* const* d_in, const int* in_sizes, int n_in,
                              void* d_out, int out_size) {
    if (n_in < 7) return;
    const float* x = (const float*)d_in[0];
    const float* pos = (const float*)d_in[1];
    const int* anchor = (const int*)d_in[2];
    const int* corner = (const int*)d_in[3];
    const int* masks = (const int*)d_in[4];
    const float* W = (const float*)d_in[5];
    const float* bias = (const float*)d_in[6];
    float* out = (float*)d_out;

    int N = in_sizes[0] / 256;
    if (N > MAXN) N = MAXN;
    int write_masks = (out_size >= N * 512 + N * 16) ? 1 : 0;

    const int prep_work = 256 * 1536 + 32 * 3 * 128 + 1536;
    prep_kernel<<<(prep_work + 255) / 256, 256>>>(W, bias, N);
    out_init_kernel<<<(N * 512 + 255) / 256, 256>>>(x, out, N);

    dim3 gg(1536 / 128, (N + 127) / 128);
    sgemm_pq_kernel<<<gg, 256>>>(x, bias, N);

    triplet_main_kernel<<<N, 256>>>(pos, anchor, corner, masks, out, N, write_masks);
}

// round 6
// speedup vs baseline: 1.7887x; 1.5116x over previous
#include <cuda_runtime.h>
#include <math.h>
#include <stdint.h>
#include <stddef.h>

// ============================================================================
// TripletGNN:
//   qkv(n,t) = P[ci0] + Q[ci1] + g(cos_values(n,t))
// where g(u) = ang(u) @ Wa^T is tabulated on a 1025-point grid over u in [-1,1]
// with linear interpolation (error ~3e-8, bandlimited integrand).
//   P = x @ W[:,0:256]^T + b ; Q = x @ W[:,256:512]^T
// Attention mean folded into per-k weights.
// ============================================================================

#define MAXN 40000
#define TAB_N 1024  // segments; TAB_N+1 entries

typedef unsigned long long u64;

__device__ float g_PQ[(size_t)(MAXN + 1) * 1536]; // [i][0:768]=P(+b),[768:]=Q
__device__ float g_Bmat[256 * 1536];              // B[c][j] for the SGEMM
__device__ float g_WaT64[64 * 768];               // [m][j] = W[j][512+m] (fp32)
__device__ float g_Tab[(size_t)(TAB_N + 1) * 768];// g(u) table

// ---------------------------------------------------------------- helpers ---
__device__ __forceinline__ u64 ffma2(u64 a, u64 b, u64 c) {
    u64 d;
    asm("fma.rn.f32x2 %0, %1, %2, %3;" : "=l"(d) : "l"(a), "l"(b), "l"(c));
    return d;
}
__device__ __forceinline__ u64 fadd2(u64 a, u64 b) {
    u64 d;
    asm("add.rn.f32x2 %0, %1, %2;" : "=l"(d) : "l"(a), "l"(b));
    return d;
}
__device__ __forceinline__ u64 pack2(float lo, float hi) {
    u64 d;
    asm("mov.b64 %0, {%1, %2};" : "=l"(d) : "f"(lo), "f"(hi));
    return d;
}
__device__ __forceinline__ float lo32(u64 v) {
    return __uint_as_float((unsigned)(v & 0xffffffffull));
}
__device__ __forceinline__ float hi32(u64 v) {
    return __uint_as_float((unsigned)(v >> 32));
}

// ------------------------------------------------------------------- prep ---
__global__ void prep_kernel(const float* __restrict__ W,
                            const float* __restrict__ bias, int N) {
    int idx = blockIdx.x * blockDim.x + threadIdx.x;
    const int B_SZ = 256 * 1536;
    const int WA_SZ = 64 * 768;
    if (idx < B_SZ) {
        int c = idx / 1536, j = idx % 1536;
        g_Bmat[idx] = (j < 768) ? W[j * 576 + c] : W[(j - 768) * 576 + 256 + c];
    } else if (idx < B_SZ + WA_SZ) {
        int r = idx - B_SZ;
        int m = r / 768, j = r % 768;
        g_WaT64[r] = W[j * 576 + 512 + m];
    } else if (idx < B_SZ + WA_SZ + 1536) {
        int j = idx - (B_SZ + WA_SZ);
        g_PQ[(size_t)N * 1536 + j] = (j < 768) ? bias[j] : 0.0f;
    }
}

// --------------------------------------------------------- angle table ------
// Block e computes T[e][0:768] = S_e @ WaT64, S_e[2m]=sin(u d_m), [2m+1]=cos.
__global__ __launch_bounds__(256)
void table_build_kernel() {
    __shared__ float S[64];
    int e = blockIdx.x;
    if (threadIdx.x < 32) {
        int m = threadIdx.x;
        float u = (float)e * (2.0f / TAB_N) - 1.0f;
        float om = u * expf(-0.28782313662425572f * (float)m);
        float s, c;
        sincosf(om, &s, &c);
        S[2 * m] = s;
        S[2 * m + 1] = c;
    }
    __syncthreads();
    int j = threadIdx.x;
    float a0 = 0.f, a1 = 0.f, a2 = 0.f;
#pragma unroll 8
    for (int m = 0; m < 64; m++) {
        float sv = S[m];
        a0 = fmaf(sv, g_WaT64[m * 768 + j], a0);
        a1 = fmaf(sv, g_WaT64[m * 768 + 256 + j], a1);
        a2 = fmaf(sv, g_WaT64[m * 768 + 512 + j], a2);
    }
    float* row = g_Tab + (size_t)e * 768;
    row[j] = a0;
    row[256 + j] = a1;
    row[512 + j] = a2;
}

// out[:,0:256] = x ; out[:,256:512] = 0
__global__ void out_init_kernel(const float* __restrict__ x,
                                float* __restrict__ out, int N) {
    int idx = blockIdx.x * blockDim.x + threadIdx.x;
    if (idx < N * 512) {
        int r = idx >> 9, cc = idx & 511;
        out[idx] = (cc < 256) ? x[((size_t)r << 8) + cc] : 0.0f;
    }
}

// ------------------------------------------------------------------ SGEMM ---
__global__ __launch_bounds__(256, 2)
void sgemm_pq_kernel(const float* __restrict__ X,
                     const float* __restrict__ bias, int M) {
    __shared__ __align__(16) float As[2][16][132];
    __shared__ __align__(16) float Bs[2][16][128];

    const int tid = threadIdx.x;
    const int tx = tid & 15;
    const int ty = tid >> 4;
    const int row0 = blockIdx.y * 128;
    const int col0 = blockIdx.x * 128;

    u64 acc2[4][8];
#pragma unroll
    for (int i = 0; i < 4; i++)
#pragma unroll
        for (int j = 0; j < 8; j++) acc2[i][j] = 0ull;

    float4 aReg[2], bReg[2];

#define LDG_TILE(KK)                                                          \
    {                                                                         \
        _Pragma("unroll") for (int l = 0; l < 2; l++) {                       \
            int fid = tid + l * 256;                                          \
            int i = fid >> 2;                                                 \
            int kq = fid & 3;                                                 \
            int grow = row0 + i;                                              \
            aReg[l] = make_float4(0.f, 0.f, 0.f, 0.f);                        \
            if (grow < M)                                                     \
                aReg[l] = *(const float4*)(X + (size_t)grow * 256 + (KK) + kq * 4); \
        }                                                                     \
        _Pragma("unroll") for (int l = 0; l < 2; l++) {                       \
            int fid = tid + l * 256;                                          \
            int k = fid >> 5;                                                 \
            int j4 = fid & 31;                                                \
            bReg[l] = *(const float4*)(g_Bmat + (size_t)((KK) + k) * 1536 + col0 + j4 * 4); \
        }                                                                     \
    }

#define STS_TILE(BUF)                                                         \
    {                                                                         \
        _Pragma("unroll") for (int l = 0; l < 2; l++) {                       \
            int fid = tid + l * 256;                                          \
            int i = fid >> 2;                                                 \
            int kq = fid & 3;                                                 \
            As[BUF][kq * 4 + 0][i] = aReg[l].x;                               \
            As[BUF][kq * 4 + 1][i] = aReg[l].y;                               \
            As[BUF][kq * 4 + 2][i] = aReg[l].z;                               \
            As[BUF][kq * 4 + 3][i] = aReg[l].w;                               \
        }                                                                     \
        _Pragma("unroll") for (int l = 0; l < 2; l++) {                       \
            int fid = tid + l * 256;                                          \
            int k = fid >> 5;                                                 \
            int j4 = fid & 31;                                                \
            *(float4*)&Bs[BUF][k][j4 * 4] = bReg[l];                          \
        }                                                                     \
    }

    LDG_TILE(0)
    STS_TILE(0)
    __syncthreads();

    const int NT = 16;
    for (int kt = 0; kt < NT; kt++) {
        int cur = kt & 1;
        if (kt + 1 < NT) LDG_TILE((kt + 1) * 16)

#pragma unroll
        for (int k = 0; k < 16; k++) {
            ulonglong2 A0 = *(const ulonglong2*)&As[cur][k][ty * 4];
            ulonglong2 A1 = *(const ulonglong2*)&As[cur][k][64 + ty * 4];
            float4 b0 = *(const float4*)&Bs[cur][k][tx * 4];
            float4 b1 = *(const float4*)&Bs[cur][k][64 + tx * 4];
            u64 br[8];
            br[0] = pack2(b0.x, b0.x); br[1] = pack2(b0.y, b0.y);
            br[2] = pack2(b0.z, b0.z); br[3] = pack2(b0.w, b0.w);
            br[4] = pack2(b1.x, b1.x); br[5] = pack2(b1.y, b1.y);
            br[6] = pack2(b1.z, b1.z); br[7] = pack2(b1.w, b1.w);
#pragma unroll
            for (int j = 0; j < 8; j++) {
                acc2[0][j] = ffma2(A0.x, br[j], acc2[0][j]);
                acc2[1][j] = ffma2(A0.y, br[j], acc2[1][j]);
                acc2[2][j] = ffma2(A1.x, br[j], acc2[2][j]);
                acc2[3][j] = ffma2(A1.y, br[j], acc2[3][j]);
            }
        }
        if (kt + 1 < NT) STS_TILE((kt + 1) & 1)
        __syncthreads();
    }
#undef LDG_TILE
#undef STS_TILE

#pragma unroll
    for (int half = 0; half < 2; half++) {
#pragma unroll
        for (int r = 0; r < 4; r++) {
            int grow = row0 + half * 64 + ty * 4 + r;
            if (grow >= M) continue;
            int ri = half * 4 + r;
            int i2 = ri >> 1, sel = ri & 1;
#pragma unroll
            for (int ch = 0; ch < 2; ch++) {
                int gcol = col0 + ch * 64 + tx * 4;
                float4 o;
                o.x = sel ? hi32(acc2[i2][ch * 4 + 0]) : lo32(acc2[i2][ch * 4 + 0]);
                o.y = sel ? hi32(acc2[i2][ch * 4 + 1]) : lo32(acc2[i2][ch * 4 + 1]);
                o.z = sel ? hi32(acc2[i2][ch * 4 + 2]) : lo32(acc2[i2][ch * 4 + 2]);
                o.w = sel ? hi32(acc2[i2][ch * 4 + 3]) : lo32(acc2[i2][ch * 4 + 3]);
                if (gcol < 768) {
                    o.x += bias[gcol + 0];
                    o.y += bias[gcol + 1];
                    o.z += bias[gcol + 2];
                    o.w += bias[gcol + 3];
                }
                *(float4*)(g_PQ + (size_t)grow * 1536 + gcol) = o;
            }
        }
    }
}

// --------------------------------------------------------------- main ------
// Thread layout: cp = tid & 127 -> channels (2cp,2cp+1); th = tid>>7 -> t-half.
__global__ __launch_bounds__(256, 3)
void triplet_main_kernel(const float* __restrict__ pos,
                         const int* __restrict__ anchor_idx,
                         const int* __restrict__ corner_idx,
                         const int* __restrict__ masks,  // int32 bool
                         float* __restrict__ out,
                         int N, int write_masks) {
    __shared__ __align__(16) float qs[16][260];
    __shared__ __align__(16) float ks[16][260];
    __shared__ __align__(16) float red[16][16];
    __shared__ __align__(16) u64 vp[2][128];
    __shared__ int ci0s[16], ci1s[16];
    __shared__ int tIdx[16];
    __shared__ float tFrac[16];
    __shared__ float maskf[16], wsh[16];

    const int n = blockIdx.x;
    const int tid = threadIdx.x;
    const int cp = tid & 127;
    const int th = tid >> 7;
    const int a_idx = anchor_idx[n];

    // ---- Phase 0: triplet geometry, table index/frac ----
    if (tid < 16) {
        int t = tid;
        float ax = 0.f, ay = 0.f;
        if (a_idx >= 0 && a_idx < N) {
            ax = pos[(size_t)a_idx * 3 + 0];
            ay = pos[(size_t)a_idx * 3 + 1];
        }
        int i0 = corner_idx[(size_t)n * 32 + 2 * t];
        int i1 = corner_idx[(size_t)n * 32 + 2 * t + 1];
        float p0x = 0.f, p0y = 0.f, p1x = 0.f, p1y = 0.f;
        if (i0 >= 0 && i0 < N) { p0x = pos[(size_t)i0 * 3]; p0y = pos[(size_t)i0 * 3 + 1]; }
        if (i1 >= 0 && i1 < N) { p1x = pos[(size_t)i1 * 3]; p1y = pos[(size_t)i1 * 3 + 1]; }
        float v0x = p0x - ax, v0y = p0y - ay;
        float v1x = p1x - ax, v1y = p1y - ay;
        float dot = v0x * v1x + v0y * v1y;
        float n0 = sqrtf(v0x * v0x + v0y * v0y);
        float n1 = sqrtf(v1x * v1x + v1y * v1y);
        float cosv = dot / (n0 * n1 + 1e-6f);
        float sinz = v0x * v1y - v0y * v1x;
        bool reorder = sinz < 0.0f;
        ci0s[t] = reorder ? i1 : i0;
        ci1s[t] = reorder ? i0 : i1;
        // table coordinates
        float s = (cosv + 1.0f) * (TAB_N * 0.5f);
        int ti = (int)floorf(s);
        if (ti < 0) ti = 0;
        if (ti > TAB_N - 1) ti = TAB_N - 1;
        tIdx[t] = ti;
        tFrac[t] = s - (float)ti;
        int mb = masks[(size_t)n * 16 + t];
        maskf[t] = (mb != 0) ? 1.0f : 0.0f;
        if (write_masks) {
            float newsin = reorder ? -sinz : sinz;  // fp-exact negation
            out[(size_t)N * 512 + (size_t)n * 16 + t] =
                ((newsin < -1e-6f) && (mb != 0)) ? 1.0f : 0.0f;
        }
    }
    __syncthreads();

    // ---- Phase 1+2: gathers + table lerp, channels packed as f32x2 ----
    u64 v2[8];
#pragma unroll
    for (int tt = 0; tt < 8; tt++) {
        int t = 8 * th + tt;
        int i0 = ci0s[t]; if (i0 < 0 || i0 > N) i0 = N;
        int i1 = ci1s[t]; if (i1 < 0 || i1 > N) i1 = N;
        const float2* r0 = (const float2*)(g_PQ + (size_t)i0 * 1536);
        const float2* r1 = (const float2*)(g_PQ + (size_t)i1 * 1536 + 768);
        float2 pq = r0[cp],       qq = r1[cp];
        float2 pk = r0[128 + cp], qk = r1[128 + cp];
        float2 pv = r0[256 + cp], qv = r1[256 + cp];

        const float2* T0 = (const float2*)(g_Tab + (size_t)tIdx[t] * 768);
        const float2* T1 = T0 + 384;
        float f = tFrac[t], g1 = 1.0f - f;
        float2 aq = T0[cp],       bq = T1[cp];
        float2 ak = T0[128 + cp], bk = T1[128 + cp];
        float2 av = T0[256 + cp], bv = T1[256 + cp];

        float qx = pq.x + qq.x + (aq.x * g1 + bq.x * f);
        float qy = pq.y + qq.y + (aq.y * g1 + bq.y * f);
        float kx = pk.x + qk.x + (ak.x * g1 + bk.x * f);
        float ky = pk.y + qk.y + (ak.y * g1 + bk.y * f);
        float vx = pv.x + qv.x + (av.x * g1 + bv.x * f);
        float vy = pv.y + qv.y + (av.y * g1 + bv.y * f);

        *(u64*)&qs[t][2 * cp] = pack2(qx, qy);
        *(u64*)&ks[t][2 * cp] = pack2(kx, ky);
        v2[tt] = pack2(vx, vy);
    }
    __syncthreads();

    // ---- Phase 4: 16x16 scores + softmax (thread = (a,b) pair) ----
    {
        int aa = tid >> 4, bb = tid & 15;
        const ulonglong2* qrow = (const ulonglong2*)&qs[aa][0];
        const ulonglong2* krow = (const ulonglong2*)&ks[bb][0];
        u64 acc = pack2(0.f, 0.f);
#pragma unroll 8
        for (int c4 = 0; c4 < 64; c4++) {
            ulonglong2 qv = qrow[c4];
            ulonglong2 kv = krow[c4];
            acc = ffma2(qv.x, kv.x, acc);
            acc = ffma2(qv.y, kv.y, acc);
        }
        float dotv = lo32(acc) + hi32(acc);
        float sc = dotv * 0.0625f;  // / sqrt(256)
        float mx = sc;
#pragma unroll
        for (int off = 8; off > 0; off >>= 1)
            mx = fmaxf(mx, __shfl_xor_sync(0xffffffffu, mx, off, 16));
        float e = expf(sc - mx);
        float sm = e;
#pragma unroll
        for (int off = 8; off > 0; off >>= 1)
            sm += __shfl_xor_sync(0xffffffffu, sm, off, 16);
        float attn = e / sm;
        red[aa][bb] = maskf[aa] * attn;
    }
    __syncthreads();

    // ---- Phase 5: fold mask-mean into per-k weights ----
    if (tid < 16) {
        float s = 0.0f, dn = 0.0f;
#pragma unroll
        for (int a2 = 0; a2 < 16; a2++) {
            s += red[a2][tid];
            dn += maskf[a2];
        }
        wsh[tid] = s / dn;
    }
    __syncthreads();

    // ---- Phase 6: mean over t (both halves), scatter float2 ----
    {
        u64 part = pack2(0.f, 0.f);
#pragma unroll
        for (int tt = 0; tt < 8; tt++) {
            float w = wsh[8 * th + tt];
            part = ffma2(pack2(w, w), v2[tt], part);
        }
        vp[th][cp] = part;
        __syncthreads();
        if (th == 0) {
            u64 tot = fadd2(vp[0][cp], vp[1][cp]);
            if (a_idx >= 0 && a_idx < N) {
                float2 o;
                o.x = lo32(tot);
                o.y = hi32(tot);
                *(float2*)(out + (size_t)a_idx * 512 + 256 + 2 * cp) = o;
            }
        }
    }
}

// ----------------------------------------------------------------------------
extern "C" void kernel_launch(void* const* d_in, const int* in_sizes, int n_in,
                              void* d_out, int out_size) {
    if (n_in < 7) return;
    const float* x = (const float*)d_in[0];
    const float* pos = (const float*)d_in[1];
    const int* anchor = (const int*)d_in[2];
    const int* corner = (const int*)d_in[3];
    const int* masks = (const int*)d_in[4];
    const float* W = (const float*)d_in[5];
    const float* bias = (const float*)d_in[6];
    float* out = (float*)d_out;

    int N = in_sizes[0] / 256;
    if (N > MAXN) N = MAXN;
    int write_masks = (out_size >= N * 512 + N * 16) ? 1 : 0;

    const int prep_work = 256 * 1536 + 64 * 768 + 1536;
    prep_kernel<<<(prep_work + 255) / 256, 256>>>(W, bias, N);
    table_build_kernel<<<TAB_N + 1, 256>>>();
    out_init_kernel<<<(N * 512 + 255) / 256, 256>>>(x, out, N);

    dim3 gg(1536 / 128, (N + 127) / 128);
    sgemm_pq_kernel<<<gg, 256>>>(x, bias, N);

    triplet_main_kernel<<<N, 256>>>(pos, anchor, corner, masks, out, N, write_masks);
}

// round 8
// speedup vs baseline: 2.0640x; 1.1539x over previous
#include <cuda_runtime.h>
#include <cuda_fp16.h>
#include <math.h>
#include <stdint.h>
#include <stddef.h>

// ============================================================================
// TripletGNN:
//   qkv(n,t) = P[ci0] + Q[ci1] + g(cos_values(n,t))   (g tabulated fp16, lerp)
//   [P|Q] = x @ B via mma.sync (HMMA) split-fp16: xh*Bh + xh*Bl + xl*Bh,
//   fp32 accum -> error ~1e-6. (tcgen05 unavailable: harness targets sm_103.)
// ============================================================================

#define MAXN 40000
#define TAB_N 1024
#define APAD 40   // halves per smem row (32 data + 8 pad); 80B stride

typedef unsigned long long u64;

__device__ float  g_PQ[(size_t)(MAXN + 1) * 1536];
__device__ float  g_WaT64[64 * 768];
__device__ __half g_TabH[(size_t)(TAB_N + 1) * 768];
__device__ __half g_Ah[(size_t)MAXN * 256];
__device__ __half g_Al[(size_t)MAXN * 256];
__device__ __half g_Bh[1536 * 256];   // [j][k], k contiguous
__device__ __half g_Bl[1536 * 256];

// ------------------------------------------------------------ f32x2 helpers -
__device__ __forceinline__ u64 ffma2(u64 a, u64 b, u64 c) {
    u64 d;
    asm("fma.rn.f32x2 %0, %1, %2, %3;" : "=l"(d) : "l"(a), "l"(b), "l"(c));
    return d;
}
__device__ __forceinline__ u64 fadd2(u64 a, u64 b) {
    u64 d;
    asm("add.rn.f32x2 %0, %1, %2;" : "=l"(d) : "l"(a), "l"(b));
    return d;
}
__device__ __forceinline__ u64 pack2(float lo, float hi) {
    u64 d;
    asm("mov.b64 %0, {%1, %2};" : "=l"(d) : "f"(lo), "f"(hi));
    return d;
}
__device__ __forceinline__ float lo32(u64 v) {
    return __uint_as_float((unsigned)(v & 0xffffffffull));
}
__device__ __forceinline__ float hi32(u64 v) {
    return __uint_as_float((unsigned)(v >> 32));
}

// ------------------------------------------------------------ mma helpers ---
__device__ __forceinline__ void ldsm4(uint32_t& r0, uint32_t& r1,
                                      uint32_t& r2, uint32_t& r3,
                                      uint32_t addr) {
    asm volatile("ldmatrix.sync.aligned.m8n8.x4.shared.b16 {%0,%1,%2,%3}, [%4];"
                 : "=r"(r0), "=r"(r1), "=r"(r2), "=r"(r3) : "r"(addr));
}
__device__ __forceinline__ void mma16816(float* d, const uint32_t* a,
                                         uint32_t b0, uint32_t b1) {
    asm volatile(
        "mma.sync.aligned.m16n8k16.row.col.f32.f16.f16.f32 "
        "{%0,%1,%2,%3}, {%4,%5,%6,%7}, {%8,%9}, {%0,%1,%2,%3};"
        : "+f"(d[0]), "+f"(d[1]), "+f"(d[2]), "+f"(d[3])
        : "r"(a[0]), "r"(a[1]), "r"(a[2]), "r"(a[3]), "r"(b0), "r"(b1));
}

// ------------------------------------------------------------------- prep ---
__global__ void prep_misc_kernel(const float* __restrict__ W,
                                 const float* __restrict__ bias, int N) {
    int idx = blockIdx.x * blockDim.x + threadIdx.x;
    const int WA_SZ = 64 * 768;
    const int B_SZ = 1536 * 256;
    if (idx < WA_SZ) {
        int m = idx / 768, j = idx % 768;
        g_WaT64[idx] = W[j * 576 + 512 + m];
    } else if (idx < WA_SZ + B_SZ) {
        int r = idx - WA_SZ;
        int j = r >> 8, k = r & 255;
        float v = (j < 768) ? W[j * 576 + k] : W[(j - 768) * 576 + 256 + k];
        __half hi = __float2half(v);
        g_Bh[r] = hi;
        g_Bl[r] = __float2half(v - __half2float(hi));
    } else if (idx < WA_SZ + B_SZ + 1536) {
        int j = idx - (WA_SZ + B_SZ);
        g_PQ[(size_t)N * 1536 + j] = (j < 768) ? bias[j] : 0.0f;
    }
}

__global__ void conv_x_kernel(const float* __restrict__ x, int total) {
    int idx = blockIdx.x * blockDim.x + threadIdx.x;
    if (idx < total) {
        float v = x[idx];
        __half hi = __float2half(v);
        g_Ah[idx] = hi;
        g_Al[idx] = __float2half(v - __half2float(hi));
    }
}

// --------------------------------------------------------- angle table ------
__global__ __launch_bounds__(256)
void table_build_kernel() {
    __shared__ float S[64];
    int e = blockIdx.x;
    if (threadIdx.x < 32) {
        int m = threadIdx.x;
        float u = (float)e * (2.0f / TAB_N) - 1.0f;
        float om = u * expf(-0.28782313662425572f * (float)m);
        float s, c;
        sincosf(om, &s, &c);
        S[2 * m] = s;
        S[2 * m + 1] = c;
    }
    __syncthreads();
    int j = threadIdx.x;
    float a0 = 0.f, a1 = 0.f, a2 = 0.f;
#pragma unroll 8
    for (int m = 0; m < 64; m++) {
        float sv = S[m];
        a0 = fmaf(sv, g_WaT64[m * 768 + j], a0);
        a1 = fmaf(sv, g_WaT64[m * 768 + 256 + j], a1);
        a2 = fmaf(sv, g_WaT64[m * 768 + 512 + j], a2);
    }
    __half* row = g_TabH + (size_t)e * 768;
    row[j] = __float2half(a0);
    row[256 + j] = __float2half(a1);
    row[512 + j] = __float2half(a2);
}

// out[:,0:256] = x ; out[:,256:512] = 0
__global__ void out_init_kernel(const float* __restrict__ x,
                                float* __restrict__ out, int N) {
    int idx = blockIdx.x * blockDim.x + threadIdx.x;
    if (idx < N * 512) {
        int r = idx >> 9, cc = idx & 511;
        out[idx] = (cc < 256) ? x[((size_t)r << 8) + cc] : 0.0f;
    }
}

// --------------------------------------------- HMMA split-fp16 GEMM for PQ --
// Tile: 128(M) x 128(N), K=256 in chunks of 32. 8 warps: 2(M) x 4(N),
// warp tile 64x32. D = Ah*Bh + Ah*Bl + Al*Bh (fp32 accum), bias in epilogue.
__global__ __launch_bounds__(256, 2)
void gemm_mma_kernel(const float* __restrict__ bias, int M) {
    __shared__ __half sAh[128 * APAD];
    __shared__ __half sAl[128 * APAD];
    __shared__ __half sBh[128 * APAD];
    __shared__ __half sBl[128 * APAD];

    const int tid = threadIdx.x;
    const int wid = tid >> 5;
    const int lid = tid & 31;
    const int wm = wid >> 2;          // 0..1
    const int wn = wid & 3;           // 0..3
    const int row0 = blockIdx.y * 128;
    const int col0 = blockIdx.x * 128;

    uint32_t sAh_u = (uint32_t)__cvta_generic_to_shared(sAh);
    uint32_t sAl_u = (uint32_t)__cvta_generic_to_shared(sAl);
    uint32_t sBh_u = (uint32_t)__cvta_generic_to_shared(sBh);
    uint32_t sBl_u = (uint32_t)__cvta_generic_to_shared(sBl);

    float acc[4][4][4];
#pragma unroll
    for (int i = 0; i < 4; i++)
#pragma unroll
        for (int j = 0; j < 4; j++)
#pragma unroll
            for (int r = 0; r < 4; r++) acc[i][j][r] = 0.0f;

    // ldmatrix per-lane base offsets (bytes), row stride = APAD*2 = 80.
    const int lrow = lid & 15;              // row/col-within-tile
    const int lkoff = (lid >> 4) * 16;      // +8 halves for upper k group

    for (int kk = 0; kk < 256; kk += 32) {
        if (kk) __syncthreads();
        // ---- load chunk: 128 rows x 32 halves each array ----
#pragma unroll
        for (int l = 0; l < 2; l++) {
            int fid = tid + l * 256;        // 512 uint4 per array
            int r = fid >> 2, q = fid & 3;
            int sdst = r * APAD + q * 8;    // halves
            int grow = row0 + r;
            uint4 vh = make_uint4(0, 0, 0, 0), vl = make_uint4(0, 0, 0, 0);
            if (grow < M) {
                size_t src = (size_t)grow * 256 + kk + q * 8;
                vh = *(const uint4*)(g_Ah + src);
                vl = *(const uint4*)(g_Al + src);
            }
            *(uint4*)(sAh + sdst) = vh;
            *(uint4*)(sAl + sdst) = vl;
            size_t bsrc = (size_t)(col0 + r) * 256 + kk + q * 8;
            *(uint4*)(sBh + sdst) = *(const uint4*)(g_Bh + bsrc);
            *(uint4*)(sBl + sdst) = *(const uint4*)(g_Bl + bsrc);
        }
        __syncthreads();

#pragma unroll
        for (int k16 = 0; k16 < 32; k16 += 16) {
            // B fragments: 2 n16 groups x (hi, lo)
            uint32_t bh[2][4], bl[2][4];
#pragma unroll
            for (int nt = 0; nt < 2; nt++) {
                uint32_t boff =
                    (uint32_t)((wn * 32 + nt * 16 + lrow) * APAD + k16) * 2 +
                    lkoff;
                ldsm4(bh[nt][0], bh[nt][1], bh[nt][2], bh[nt][3], sBh_u + boff);
                ldsm4(bl[nt][0], bl[nt][1], bl[nt][2], bl[nt][3], sBl_u + boff);
            }
#pragma unroll
            for (int mt = 0; mt < 4; mt++) {
                uint32_t aoff =
                    (uint32_t)((wm * 64 + mt * 16 + lrow) * APAD + k16) * 2 +
                    lkoff;
                uint32_t ah[4], al[4];
                ldsm4(ah[0], ah[1], ah[2], ah[3], sAh_u + aoff);
                ldsm4(al[0], al[1], al[2], al[3], sAl_u + aoff);
#pragma unroll
                for (int n = 0; n < 4; n++) {
                    int nt = n >> 1, jj = n & 1;
                    mma16816(acc[mt][n], ah, bh[nt][jj], bh[nt][jj + 2]);
                    mma16816(acc[mt][n], ah, bl[nt][jj], bl[nt][jj + 2]);
                    mma16816(acc[mt][n], al, bh[nt][jj], bh[nt][jj + 2]);
                }
            }
        }
    }

    // ---- epilogue: direct float2 stores, +bias for cols < 768 ----
#pragma unroll
    for (int mt = 0; mt < 4; mt++) {
#pragma unroll
        for (int n = 0; n < 4; n++) {
            int gcol = col0 + wn * 32 + (n >> 1) * 16 + (n & 1) * 8 +
                       (lid & 3) * 2;
            float bx = 0.f, by = 0.f;
            if (gcol < 768) { bx = bias[gcol]; by = bias[gcol + 1]; }
            int r0g = row0 + wm * 64 + mt * 16 + (lid >> 2);
            if (r0g < M) {
                float2 o = make_float2(acc[mt][n][0] + bx, acc[mt][n][1] + by);
                *(float2*)(g_PQ + (size_t)r0g * 1536 + gcol) = o;
            }
            if (r0g + 8 < M) {
                float2 o = make_float2(acc[mt][n][2] + bx, acc[mt][n][3] + by);
                *(float2*)(g_PQ + (size_t)(r0g + 8) * 1536 + gcol) = o;
            }
        }
    }
}

// --------------------------------------------------------------- main ------
__global__ __launch_bounds__(256, 3)
void triplet_main_kernel(const float* __restrict__ pos,
                         const int* __restrict__ anchor_idx,
                         const int* __restrict__ corner_idx,
                         const int* __restrict__ masks,
                         float* __restrict__ out,
                         int N, int write_masks) {
    __shared__ __align__(16) float qs[16][260];
    __shared__ __align__(16) float ks[16][260];
    __shared__ __align__(16) float red[16][16];
    __shared__ __align__(16) u64 vp[2][128];
    __shared__ int ci0s[16], ci1s[16];
    __shared__ int tIdx[16];
    __shared__ float tFrac[16];
    __shared__ float maskf[16], wsh[16];

    const int n = blockIdx.x;
    const int tid = threadIdx.x;
    const int cp = tid & 127;
    const int th = tid >> 7;
    const int a_idx = anchor_idx[n];

    if (tid < 16) {
        int t = tid;
        float ax = 0.f, ay = 0.f;
        if (a_idx >= 0 && a_idx < N) {
            ax = pos[(size_t)a_idx * 3 + 0];
            ay = pos[(size_t)a_idx * 3 + 1];
        }
        int i0 = corner_idx[(size_t)n * 32 + 2 * t];
        int i1 = corner_idx[(size_t)n * 32 + 2 * t + 1];
        float p0x = 0.f, p0y = 0.f, p1x = 0.f, p1y = 0.f;
        if (i0 >= 0 && i0 < N) { p0x = pos[(size_t)i0 * 3]; p0y = pos[(size_t)i0 * 3 + 1]; }
        if (i1 >= 0 && i1 < N) { p1x = pos[(size_t)i1 * 3]; p1y = pos[(size_t)i1 * 3 + 1]; }
        float v0x = p0x - ax, v0y = p0y - ay;
        float v1x = p1x - ax, v1y = p1y - ay;
        float dot = v0x * v1x + v0y * v1y;
        float n0 = sqrtf(v0x * v0x + v0y * v0y);
        float n1 = sqrtf(v1x * v1x + v1y * v1y);
        float cosv = dot / (n0 * n1 + 1e-6f);
        float sinz = v0x * v1y - v0y * v1x;
        bool reorder = sinz < 0.0f;
        ci0s[t] = reorder ? i1 : i0;
        ci1s[t] = reorder ? i0 : i1;
        float s = (cosv + 1.0f) * (TAB_N * 0.5f);
        int ti = (int)floorf(s);
        if (ti < 0) ti = 0;
        if (ti > TAB_N - 1) ti = TAB_N - 1;
        tIdx[t] = ti;
        tFrac[t] = s - (float)ti;
        int mb = masks[(size_t)n * 16 + t];
        maskf[t] = (mb != 0) ? 1.0f : 0.0f;
        if (write_masks) {
            float newsin = reorder ? -sinz : sinz;
            out[(size_t)N * 512 + (size_t)n * 16 + t] =
                ((newsin < -1e-6f) && (mb != 0)) ? 1.0f : 0.0f;
        }
    }
    __syncthreads();

    u64 v2[8];
#pragma unroll
    for (int tt = 0; tt < 8; tt++) {
        int t = 8 * th + tt;
        int i0 = ci0s[t]; if (i0 < 0 || i0 > N) i0 = N;
        int i1 = ci1s[t]; if (i1 < 0 || i1 > N) i1 = N;
        const float2* r0 = (const float2*)(g_PQ + (size_t)i0 * 1536);
        const float2* r1 = (const float2*)(g_PQ + (size_t)i1 * 1536 + 768);
        float2 pq = r0[cp],       qq = r1[cp];
        float2 pk = r0[128 + cp], qk = r1[128 + cp];
        float2 pv = r0[256 + cp], qv = r1[256 + cp];

        const __half2* T0 = (const __half2*)(g_TabH + (size_t)tIdx[t] * 768);
        const __half2* T1 = T0 + 384;
        float f = tFrac[t], g1 = 1.0f - f;
        float2 aq = __half22float2(T0[cp]);
        float2 bq = __half22float2(T1[cp]);
        float2 ak = __half22float2(T0[128 + cp]);
        float2 bk = __half22float2(T1[128 + cp]);
        float2 av = __half22float2(T0[256 + cp]);
        float2 bv = __half22float2(T1[256 + cp]);

        float qx = pq.x + qq.x + (aq.x * g1 + bq.x * f);
        float qy = pq.y + qq.y + (aq.y * g1 + bq.y * f);
        float kx = pk.x + qk.x + (ak.x * g1 + bk.x * f);
        float ky = pk.y + qk.y + (ak.y * g1 + bk.y * f);
        float vx = pv.x + qv.x + (av.x * g1 + bv.x * f);
        float vy = pv.y + qv.y + (av.y * g1 + bv.y * f);

        *(u64*)&qs[t][2 * cp] = pack2(qx, qy);
        *(u64*)&ks[t][2 * cp] = pack2(kx, ky);
        v2[tt] = pack2(vx, vy);
    }
    __syncthreads();

    {
        int aa = tid >> 4, bb = tid & 15;
        const ulonglong2* qrow = (const ulonglong2*)&qs[aa][0];
        const ulonglong2* krow = (const ulonglong2*)&ks[bb][0];
        u64 acc = pack2(0.f, 0.f);
#pragma unroll 8
        for (int c4 = 0; c4 < 64; c4++) {
            ulonglong2 qv = qrow[c4];
            ulonglong2 kv = krow[c4];
            acc = ffma2(qv.x, kv.x, acc);
            acc = ffma2(qv.y, kv.y, acc);
        }
        float dotv = lo32(acc) + hi32(acc);
        float sc = dotv * 0.0625f;
        float mx = sc;
#pragma unroll
        for (int off = 8; off > 0; off >>= 1)
            mx = fmaxf(mx, __shfl_xor_sync(0xffffffffu, mx, off, 16));
        float e = expf(sc - mx);
        float sm = e;
#pragma unroll
        for (int off = 8; off > 0; off >>= 1)
            sm += __shfl_xor_sync(0xffffffffu, sm, off, 16);
        float attn = e / sm;
        red[aa][bb] = maskf[aa] * attn;
    }
    __syncthreads();

    if (tid < 16) {
        float s = 0.0f, dn = 0.0f;
#pragma unroll
        for (int a2 = 0; a2 < 16; a2++) {
            s += red[a2][tid];
            dn += maskf[a2];
        }
        wsh[tid] = s / dn;
    }
    __syncthreads();

    {
        u64 part = pack2(0.f, 0.f);
#pragma unroll
        for (int tt = 0; tt < 8; tt++) {
            float w = wsh[8 * th + tt];
            part = ffma2(pack2(w, w), v2[tt], part);
        }
        vp[th][cp] = part;
        __syncthreads();
        if (th == 0) {
            u64 tot = fadd2(vp[0][cp], vp[1][cp]);
            if (a_idx >= 0 && a_idx < N) {
                float2 o;
                o.x = lo32(tot);
                o.y = hi32(tot);
                *(float2*)(out + (size_t)a_idx * 512 + 256 + 2 * cp) = o;
            }
        }
    }
}

// ----------------------------------------------------------------------------
extern "C" void kernel_launch(void* const* d_in, const int* in_sizes, int n_in,
                              void* d_out, int out_size) {
    if (n_in < 7) return;
    const float* x = (const float*)d_in[0];
    const float* pos = (const float*)d_in[1];
    const int* anchor = (const int*)d_in[2];
    const int* corner = (const int*)d_in[3];
    const int* masks = (const int*)d_in[4];
    const float* W = (const float*)d_in[5];
    const float* bias = (const float*)d_in[6];
    float* out = (float*)d_out;

    int N = in_sizes[0] / 256;
    if (N > MAXN) N = MAXN;
    int write_masks = (out_size >= N * 512 + N * 16) ? 1 : 0;

    const int prep_work = 64 * 768 + 1536 * 256 + 1536;
    prep_misc_kernel<<<(prep_work + 255) / 256, 256>>>(W, bias, N);
    conv_x_kernel<<<(N * 256 + 255) / 256, 256>>>(x, N * 256);
    table_build_kernel<<<TAB_N + 1, 256>>>();
    out_init_kernel<<<(N * 512 + 255) / 256, 256>>>(x, out, N);

    dim3 gg(12, (N + 127) / 128);
    gemm_mma_kernel<<<gg, 256>>>(bias, N);

    triplet_main_kernel<<<N, 256>>>(pos, anchor, corner, masks, out, N, write_masks);
}

// round 9
// speedup vs baseline: 2.3656x; 1.1461x over previous
#include <cuda_runtime.h>
#include <cuda_fp16.h>
#include <math.h>
#include <stdint.h>
#include <stddef.h>

// ============================================================================
// TripletGNN:
//   qkv(n,t) = P[ci0] + Q[ci1] + g(cos_values(n,t))   (g tabulated fp16, lerp)
//   [P|Q] = x @ B via mma.sync split-fp16 (xh*Bh + xh*Bl + xl*Bh, fp32 accum).
//   Per-anchor 16x16 scores ALSO via mma.sync split-fp16 (1 warp, 96 MMAs).
// ============================================================================

#define MAXN 40000
#define TAB_N 1024
#define APAD 40    // gemm smem halves/row
#define QP 264     // score-stage smem halves/row (256 + 8 pad)

typedef unsigned long long u64;

__device__ float  g_PQ[(size_t)(MAXN + 1) * 1536];
__device__ float  g_WaT64[64 * 768];
__device__ __half g_TabH[(size_t)(TAB_N + 1) * 768];
__device__ __half g_Ah[(size_t)MAXN * 256];
__device__ __half g_Al[(size_t)MAXN * 256];
__device__ __half g_Bh[1536 * 256];
__device__ __half g_Bl[1536 * 256];

// ------------------------------------------------------------ f32x2 helpers -
__device__ __forceinline__ u64 ffma2(u64 a, u64 b, u64 c) {
    u64 d;
    asm("fma.rn.f32x2 %0, %1, %2, %3;" : "=l"(d) : "l"(a), "l"(b), "l"(c));
    return d;
}
__device__ __forceinline__ u64 fadd2(u64 a, u64 b) {
    u64 d;
    asm("add.rn.f32x2 %0, %1, %2;" : "=l"(d) : "l"(a), "l"(b));
    return d;
}
__device__ __forceinline__ u64 pack2(float lo, float hi) {
    u64 d;
    asm("mov.b64 %0, {%1, %2};" : "=l"(d) : "f"(lo), "f"(hi));
    return d;
}
__device__ __forceinline__ float lo32(u64 v) {
    return __uint_as_float((unsigned)(v & 0xffffffffull));
}
__device__ __forceinline__ float hi32(u64 v) {
    return __uint_as_float((unsigned)(v >> 32));
}

// ------------------------------------------------------------ mma helpers ---
__device__ __forceinline__ void ldsm4(uint32_t& r0, uint32_t& r1,
                                      uint32_t& r2, uint32_t& r3,
                                      uint32_t addr) {
    asm volatile("ldmatrix.sync.aligned.m8n8.x4.shared.b16 {%0,%1,%2,%3}, [%4];"
                 : "=r"(r0), "=r"(r1), "=r"(r2), "=r"(r3) : "r"(addr));
}
__device__ __forceinline__ void mma16816(float* d, const uint32_t* a,
                                         uint32_t b0, uint32_t b1) {
    asm volatile(
        "mma.sync.aligned.m16n8k16.row.col.f32.f16.f16.f32 "
        "{%0,%1,%2,%3}, {%4,%5,%6,%7}, {%8,%9}, {%0,%1,%2,%3};"
        : "+f"(d[0]), "+f"(d[1]), "+f"(d[2]), "+f"(d[3])
        : "r"(a[0]), "r"(a[1]), "r"(a[2]), "r"(a[3]), "r"(b0), "r"(b1));
}

// ------------------------------------------------------------------- prep ---
__global__ void prep_misc_kernel(const float* __restrict__ W,
                                 const float* __restrict__ bias, int N) {
    int idx = blockIdx.x * blockDim.x + threadIdx.x;
    const int WA_SZ = 64 * 768;
    const int B_SZ = 1536 * 256;
    if (idx < WA_SZ) {
        int m = idx / 768, j = idx % 768;
        g_WaT64[idx] = W[j * 576 + 512 + m];
    } else if (idx < WA_SZ + B_SZ) {
        int r = idx - WA_SZ;
        int j = r >> 8, k = r & 255;
        float v = (j < 768) ? W[j * 576 + k] : W[(j - 768) * 576 + 256 + k];
        __half hi = __float2half(v);
        g_Bh[r] = hi;
        g_Bl[r] = __float2half(v - __half2float(hi));
    } else if (idx < WA_SZ + B_SZ + 1536) {
        int j = idx - (WA_SZ + B_SZ);
        g_PQ[(size_t)N * 1536 + j] = (j < 768) ? bias[j] : 0.0f;
    }
}

// Fused: x -> (Ah, Al) fp16 split; out[:,0:256]=x; out[:,256:512]=0.
__global__ void fused_init_kernel(const float* __restrict__ x,
                                  float* __restrict__ out, int total) {
    int idx = blockIdx.x * blockDim.x + threadIdx.x;
    if (idx < total) {
        float v = x[idx];
        __half hi = __float2half(v);
        g_Ah[idx] = hi;
        g_Al[idx] = __float2half(v - __half2float(hi));
        int r = idx >> 8, c = idx & 255;
        out[(size_t)r * 512 + c] = v;
        out[(size_t)r * 512 + 256 + c] = 0.0f;
    }
}

// --------------------------------------------------------- angle table ------
__global__ __launch_bounds__(256)
void table_build_kernel() {
    __shared__ float S[64];
    int e = blockIdx.x;
    if (threadIdx.x < 32) {
        int m = threadIdx.x;
        float u = (float)e * (2.0f / TAB_N) - 1.0f;
        float om = u * expf(-0.28782313662425572f * (float)m);
        float s, c;
        sincosf(om, &s, &c);
        S[2 * m] = s;
        S[2 * m + 1] = c;
    }
    __syncthreads();
    int j = threadIdx.x;
    float a0 = 0.f, a1 = 0.f, a2 = 0.f;
#pragma unroll 8
    for (int m = 0; m < 64; m++) {
        float sv = S[m];
        a0 = fmaf(sv, g_WaT64[m * 768 + j], a0);
        a1 = fmaf(sv, g_WaT64[m * 768 + 256 + j], a1);
        a2 = fmaf(sv, g_WaT64[m * 768 + 512 + j], a2);
    }
    __half* row = g_TabH + (size_t)e * 768;
    row[j] = __float2half(a0);
    row[256 + j] = __float2half(a1);
    row[512 + j] = __float2half(a2);
}

// --------------------------------------------- HMMA split-fp16 GEMM for PQ --
__global__ __launch_bounds__(256, 2)
void gemm_mma_kernel(const float* __restrict__ bias, int M) {
    __shared__ __half sAh[128 * APAD];
    __shared__ __half sAl[128 * APAD];
    __shared__ __half sBh[128 * APAD];
    __shared__ __half sBl[128 * APAD];

    const int tid = threadIdx.x;
    const int wid = tid >> 5;
    const int lid = tid & 31;
    const int wm = wid >> 2;
    const int wn = wid & 3;
    const int row0 = blockIdx.y * 128;
    const int col0 = blockIdx.x * 128;

    uint32_t sAh_u = (uint32_t)__cvta_generic_to_shared(sAh);
    uint32_t sAl_u = (uint32_t)__cvta_generic_to_shared(sAl);
    uint32_t sBh_u = (uint32_t)__cvta_generic_to_shared(sBh);
    uint32_t sBl_u = (uint32_t)__cvta_generic_to_shared(sBl);

    float acc[4][4][4];
#pragma unroll
    for (int i = 0; i < 4; i++)
#pragma unroll
        for (int j = 0; j < 4; j++)
#pragma unroll
            for (int r = 0; r < 4; r++) acc[i][j][r] = 0.0f;

    const int lrow = lid & 15;
    const int lkoff = (lid >> 4) * 16;

    for (int kk = 0; kk < 256; kk += 32) {
        if (kk) __syncthreads();
#pragma unroll
        for (int l = 0; l < 2; l++) {
            int fid = tid + l * 256;
            int r = fid >> 2, q = fid & 3;
            int sdst = r * APAD + q * 8;
            int grow = row0 + r;
            uint4 vh = make_uint4(0, 0, 0, 0), vl = make_uint4(0, 0, 0, 0);
            if (grow < M) {
                size_t src = (size_t)grow * 256 + kk + q * 8;
                vh = *(const uint4*)(g_Ah + src);
                vl = *(const uint4*)(g_Al + src);
            }
            *(uint4*)(sAh + sdst) = vh;
            *(uint4*)(sAl + sdst) = vl;
            size_t bsrc = (size_t)(col0 + r) * 256 + kk + q * 8;
            *(uint4*)(sBh + sdst) = *(const uint4*)(g_Bh + bsrc);
            *(uint4*)(sBl + sdst) = *(const uint4*)(g_Bl + bsrc);
        }
        __syncthreads();

#pragma unroll
        for (int k16 = 0; k16 < 32; k16 += 16) {
            uint32_t bh[2][4], bl[2][4];
#pragma unroll
            for (int nt = 0; nt < 2; nt++) {
                uint32_t boff =
                    (uint32_t)((wn * 32 + nt * 16 + lrow) * APAD + k16) * 2 +
                    lkoff;
                ldsm4(bh[nt][0], bh[nt][1], bh[nt][2], bh[nt][3], sBh_u + boff);
                ldsm4(bl[nt][0], bl[nt][1], bl[nt][2], bl[nt][3], sBl_u + boff);
            }
#pragma unroll
            for (int mt = 0; mt < 4; mt++) {
                uint32_t aoff =
                    (uint32_t)((wm * 64 + mt * 16 + lrow) * APAD + k16) * 2 +
                    lkoff;
                uint32_t ah[4], al[4];
                ldsm4(ah[0], ah[1], ah[2], ah[3], sAh_u + aoff);
                ldsm4(al[0], al[1], al[2], al[3], sAl_u + aoff);
#pragma unroll
                for (int n = 0; n < 4; n++) {
                    int nt = n >> 1, jj = n & 1;
                    mma16816(acc[mt][n], ah, bh[nt][jj], bh[nt][jj + 2]);
                    mma16816(acc[mt][n], ah, bl[nt][jj], bl[nt][jj + 2]);
                    mma16816(acc[mt][n], al, bh[nt][jj], bh[nt][jj + 2]);
                }
            }
        }
    }

#pragma unroll
    for (int mt = 0; mt < 4; mt++) {
#pragma unroll
        for (int n = 0; n < 4; n++) {
            int gcol = col0 + wn * 32 + (n >> 1) * 16 + (n & 1) * 8 +
                       (lid & 3) * 2;
            float bx = 0.f, by = 0.f;
            if (gcol < 768) { bx = bias[gcol]; by = bias[gcol + 1]; }
            int r0g = row0 + wm * 64 + mt * 16 + (lid >> 2);
            if (r0g < M) {
                float2 o = make_float2(acc[mt][n][0] + bx, acc[mt][n][1] + by);
                *(float2*)(g_PQ + (size_t)r0g * 1536 + gcol) = o;
            }
            if (r0g + 8 < M) {
                float2 o = make_float2(acc[mt][n][2] + bx, acc[mt][n][3] + by);
                *(float2*)(g_PQ + (size_t)(r0g + 8) * 1536 + gcol) = o;
            }
        }
    }
}

// --------------------------------------------------------------- main ------
// cp = tid & 127 -> channels (2cp,2cp+1); th = tid>>7 -> t-half.
// Scores S = q k^T computed by warp 0 via split-fp16 mma.sync.
__global__ __launch_bounds__(256, 3)
void triplet_main_kernel(const float* __restrict__ pos,
                         const int* __restrict__ anchor_idx,
                         const int* __restrict__ corner_idx,
                         const int* __restrict__ masks,
                         float* __restrict__ out,
                         int N, int write_masks) {
    __shared__ __align__(16) __half qh[16][QP];
    __shared__ __align__(16) __half ql[16][QP];
    __shared__ __align__(16) __half kh[16][QP];
    __shared__ __align__(16) __half kl[16][QP];
    __shared__ __align__(16) float sS[16][17];
    __shared__ __align__(16) float red[16][16];
    __shared__ __align__(16) u64 vp[2][128];
    __shared__ int ci0s[16], ci1s[16];
    __shared__ int tIdx[16];
    __shared__ float tFrac[16];
    __shared__ float maskf[16], wsh[16];

    const int n = blockIdx.x;
    const int tid = threadIdx.x;
    const int cp = tid & 127;
    const int th = tid >> 7;
    const int lid = tid & 31;
    const int a_idx = anchor_idx[n];

    // ---- Phase 0: triplet geometry + table coords ----
    if (tid < 16) {
        int t = tid;
        float ax = 0.f, ay = 0.f;
        if (a_idx >= 0 && a_idx < N) {
            ax = pos[(size_t)a_idx * 3 + 0];
            ay = pos[(size_t)a_idx * 3 + 1];
        }
        int i0 = corner_idx[(size_t)n * 32 + 2 * t];
        int i1 = corner_idx[(size_t)n * 32 + 2 * t + 1];
        float p0x = 0.f, p0y = 0.f, p1x = 0.f, p1y = 0.f;
        if (i0 >= 0 && i0 < N) { p0x = pos[(size_t)i0 * 3]; p0y = pos[(size_t)i0 * 3 + 1]; }
        if (i1 >= 0 && i1 < N) { p1x = pos[(size_t)i1 * 3]; p1y = pos[(size_t)i1 * 3 + 1]; }
        float v0x = p0x - ax, v0y = p0y - ay;
        float v1x = p1x - ax, v1y = p1y - ay;
        float dot = v0x * v1x + v0y * v1y;
        float n0 = sqrtf(v0x * v0x + v0y * v0y);
        float n1 = sqrtf(v1x * v1x + v1y * v1y);
        float cosv = dot / (n0 * n1 + 1e-6f);
        float sinz = v0x * v1y - v0y * v1x;
        bool reorder = sinz < 0.0f;
        ci0s[t] = reorder ? i1 : i0;
        ci1s[t] = reorder ? i0 : i1;
        float s = (cosv + 1.0f) * (TAB_N * 0.5f);
        int ti = (int)floorf(s);
        if (ti < 0) ti = 0;
        if (ti > TAB_N - 1) ti = TAB_N - 1;
        tIdx[t] = ti;
        tFrac[t] = s - (float)ti;
        int mb = masks[(size_t)n * 16 + t];
        maskf[t] = (mb != 0) ? 1.0f : 0.0f;
        if (write_masks) {
            float newsin = reorder ? -sinz : sinz;
            out[(size_t)N * 512 + (size_t)n * 16 + t] =
                ((newsin < -1e-6f) && (mb != 0)) ? 1.0f : 0.0f;
        }
    }
    __syncthreads();

    // ---- Phase 1: gathers + table lerp; stage q,k as fp16 hi/lo ----
    u64 v2[8];
#pragma unroll
    for (int tt = 0; tt < 8; tt++) {
        int t = 8 * th + tt;
        int i0 = ci0s[t]; if (i0 < 0 || i0 > N) i0 = N;
        int i1 = ci1s[t]; if (i1 < 0 || i1 > N) i1 = N;
        const float2* r0 = (const float2*)(g_PQ + (size_t)i0 * 1536);
        const float2* r1 = (const float2*)(g_PQ + (size_t)i1 * 1536 + 768);
        float2 pq = r0[cp],       qq = r1[cp];
        float2 pk = r0[128 + cp], qk = r1[128 + cp];
        float2 pv = r0[256 + cp], qv = r1[256 + cp];

        const __half2* T0 = (const __half2*)(g_TabH + (size_t)tIdx[t] * 768);
        const __half2* T1 = T0 + 384;
        float f = tFrac[t], g1 = 1.0f - f;
        float2 aq = __half22float2(T0[cp]);
        float2 bq = __half22float2(T1[cp]);
        float2 ak = __half22float2(T0[128 + cp]);
        float2 bk = __half22float2(T1[128 + cp]);
        float2 av = __half22float2(T0[256 + cp]);
        float2 bv = __half22float2(T1[256 + cp]);

        float qx = pq.x + qq.x + (aq.x * g1 + bq.x * f);
        float qy = pq.y + qq.y + (aq.y * g1 + bq.y * f);
        float kx = pk.x + qk.x + (ak.x * g1 + bk.x * f);
        float ky = pk.y + qk.y + (ak.y * g1 + bk.y * f);
        float vx = pv.x + qv.x + (av.x * g1 + bv.x * f);
        float vy = pv.y + qv.y + (av.y * g1 + bv.y * f);

        // fp16 hi/lo split of q, k
        __half qhx = __float2half(qx), qhy = __float2half(qy);
        __half khx = __float2half(kx), khy = __float2half(ky);
        *(__half2*)&qh[t][2 * cp] = __halves2half2(qhx, qhy);
        *(__half2*)&ql[t][2 * cp] = __halves2half2(
            __float2half(qx - __half2float(qhx)),
            __float2half(qy - __half2float(qhy)));
        *(__half2*)&kh[t][2 * cp] = __halves2half2(khx, khy);
        *(__half2*)&kl[t][2 * cp] = __halves2half2(
            __float2half(kx - __half2float(khx)),
            __float2half(ky - __half2float(khy)));
        v2[tt] = pack2(vx, vy);
    }
    __syncthreads();

    // ---- Phase 2: S = q k^T via split-fp16 mma (warp 0 only) ----
    if (tid < 32) {
        const int lrow = lid & 15;
        const int lkoff = (lid >> 4) * 16;   // bytes
        uint32_t qh_u = (uint32_t)__cvta_generic_to_shared(qh);
        uint32_t ql_u = (uint32_t)__cvta_generic_to_shared(ql);
        uint32_t kh_u = (uint32_t)__cvta_generic_to_shared(kh);
        uint32_t kl_u = (uint32_t)__cvta_generic_to_shared(kl);
        float acc[2][4];
#pragma unroll
        for (int jj = 0; jj < 2; jj++)
#pragma unroll
            for (int r = 0; r < 4; r++) acc[jj][r] = 0.0f;

#pragma unroll
        for (int k16 = 0; k16 < 256; k16 += 16) {
            uint32_t off = (uint32_t)(lrow * QP + k16) * 2 + lkoff;
            uint32_t ah[4], al[4], bh[4], bl[4];
            ldsm4(ah[0], ah[1], ah[2], ah[3], qh_u + off);
            ldsm4(al[0], al[1], al[2], al[3], ql_u + off);
            ldsm4(bh[0], bh[1], bh[2], bh[3], kh_u + off);
            ldsm4(bl[0], bl[1], bl[2], bl[3], kl_u + off);
#pragma unroll
            for (int jj = 0; jj < 2; jj++) {
                mma16816(acc[jj], ah, bh[jj], bh[jj + 2]);
                mma16816(acc[jj], ah, bl[jj], bl[jj + 2]);
                mma16816(acc[jj], al, bh[jj], bh[jj + 2]);
            }
        }
        int r0 = lid >> 2;
        int c0 = (lid & 3) * 2;
#pragma unroll
        for (int jj = 0; jj < 2; jj++) {
            sS[r0][jj * 8 + c0] = acc[jj][0];
            sS[r0][jj * 8 + c0 + 1] = acc[jj][1];
            sS[r0 + 8][jj * 8 + c0] = acc[jj][2];
            sS[r0 + 8][jj * 8 + c0 + 1] = acc[jj][3];
        }
    }
    __syncthreads();

    // ---- Phase 3: softmax (thread = (a,b)) ----
    {
        int aa = tid >> 4, bb = tid & 15;
        float sc = sS[aa][bb] * 0.0625f;
        float mx = sc;
#pragma unroll
        for (int off = 8; off > 0; off >>= 1)
            mx = fmaxf(mx, __shfl_xor_sync(0xffffffffu, mx, off, 16));
        float e = expf(sc - mx);
        float sm = e;
#pragma unroll
        for (int off = 8; off > 0; off >>= 1)
            sm += __shfl_xor_sync(0xffffffffu, sm, off, 16);
        float attn = e / sm;
        red[aa][bb] = maskf[aa] * attn;
    }
    __syncthreads();

    // ---- Phase 4: fold mask-mean into per-k weights ----
    if (tid < 16) {
        float s = 0.0f, dn = 0.0f;
#pragma unroll
        for (int a2 = 0; a2 < 16; a2++) {
            s += red[a2][tid];
            dn += maskf[a2];
        }
        wsh[tid] = s / dn;
    }
    __syncthreads();

    // ---- Phase 5: mean over t, scatter float2 ----
    {
        u64 part = pack2(0.f, 0.f);
#pragma unroll
        for (int tt = 0; tt < 8; tt++) {
            float w = wsh[8 * th + tt];
            part = ffma2(pack2(w, w), v2[tt], part);
        }
        vp[th][cp] = part;
        __syncthreads();
        if (th == 0) {
            u64 tot = fadd2(vp[0][cp], vp[1][cp]);
            if (a_idx >= 0 && a_idx < N) {
                float2 o;
                o.x = lo32(tot);
                o.y = hi32(tot);
                *(float2*)(out + (size_t)a_idx * 512 + 256 + 2 * cp) = o;
            }
        }
    }
}

// ----------------------------------------------------------------------------
extern "C" void kernel_launch(void* const* d_in, const int* in_sizes, int n_in,
                              void* d_out, int out_size) {
    if (n_in < 7) return;
    const float* x = (const float*)d_in[0];
    const float* pos = (const float*)d_in[1];
    const int* anchor = (const int*)d_in[2];
    const int* corner = (const int*)d_in[3];
    const int* masks = (const int*)d_in[4];
    const float* W = (const float*)d_in[5];
    const float* bias = (const float*)d_in[6];
    float* out = (float*)d_out;

    int N = in_sizes[0] / 256;
    if (N > MAXN) N = MAXN;
    int write_masks = (out_size >= N * 512 + N * 16) ? 1 : 0;

    const int prep_work = 64 * 768 + 1536 * 256 + 1536;
    prep_misc_kernel<<<(prep_work + 255) / 256, 256>>>(W, bias, N);
    fused_init_kernel<<<(N * 256 + 255) / 256, 256>>>(x, out, N * 256);
    table_build_kernel<<<TAB_N + 1, 256>>>();

    dim3 gg(12, (N + 127) / 128);
    gemm_mma_kernel<<<gg, 256>>>(bias, N);

    triplet_main_kernel<<<N, 256>>>(pos, anchor, corner, masks, out, N, write_masks);
}

// round 10
// speedup vs baseline: 2.5463x; 1.0764x over previous
#include <cuda_runtime.h>
#include <cuda_fp16.h>
#include <math.h>
#include <stdint.h>
#include <stddef.h>

// ============================================================================
// TripletGNN:
//   qkv(n,t) = P[ci0] + Q[ci1] + g(cos_values(n,t))
//   g tabulated at 4097 points, nearest-neighbor (err ~1e-5, < fp16 storage).
//   [P|Q] = x @ B via cp.async double-buffered split-fp16 mma.sync.
//   16x16 scores via split-fp16 mma.sync (warp 0).
// ============================================================================

#define MAXN 40000
#define TAB_N 4096
#define APAD 40    // gemm smem halves/row
#define QP 264     // score-stage smem halves/row

typedef unsigned long long u64;

__device__ float  g_PQ[(size_t)(MAXN + 1) * 1536];
__device__ float  g_WaT64[64 * 768];
__device__ __half g_TabH[(size_t)(TAB_N + 1) * 768];
__device__ __half g_Ah[(size_t)MAXN * 256];
__device__ __half g_Al[(size_t)MAXN * 256];
__device__ __half g_Bh[1536 * 256];
__device__ __half g_Bl[1536 * 256];

// ------------------------------------------------------------ f32x2 helpers -
__device__ __forceinline__ u64 ffma2(u64 a, u64 b, u64 c) {
    u64 d;
    asm("fma.rn.f32x2 %0, %1, %2, %3;" : "=l"(d) : "l"(a), "l"(b), "l"(c));
    return d;
}
__device__ __forceinline__ u64 fadd2(u64 a, u64 b) {
    u64 d;
    asm("add.rn.f32x2 %0, %1, %2;" : "=l"(d) : "l"(a), "l"(b));
    return d;
}
__device__ __forceinline__ u64 pack2(float lo, float hi) {
    u64 d;
    asm("mov.b64 %0, {%1, %2};" : "=l"(d) : "f"(lo), "f"(hi));
    return d;
}
__device__ __forceinline__ float lo32(u64 v) {
    return __uint_as_float((unsigned)(v & 0xffffffffull));
}
__device__ __forceinline__ float hi32(u64 v) {
    return __uint_as_float((unsigned)(v >> 32));
}

// ------------------------------------------------------------ mma helpers ---
__device__ __forceinline__ void ldsm4(uint32_t& r0, uint32_t& r1,
                                      uint32_t& r2, uint32_t& r3,
                                      uint32_t addr) {
    asm volatile("ldmatrix.sync.aligned.m8n8.x4.shared.b16 {%0,%1,%2,%3}, [%4];"
                 : "=r"(r0), "=r"(r1), "=r"(r2), "=r"(r3) : "r"(addr));
}
__device__ __forceinline__ void mma16816(float* d, const uint32_t* a,
                                         uint32_t b0, uint32_t b1) {
    asm volatile(
        "mma.sync.aligned.m16n8k16.row.col.f32.f16.f16.f32 "
        "{%0,%1,%2,%3}, {%4,%5,%6,%7}, {%8,%9}, {%0,%1,%2,%3};"
        : "+f"(d[0]), "+f"(d[1]), "+f"(d[2]), "+f"(d[3])
        : "r"(a[0]), "r"(a[1]), "r"(a[2]), "r"(a[3]), "r"(b0), "r"(b1));
}
__device__ __forceinline__ void cp_async16(uint32_t dst, const void* src,
                                           int src_bytes) {
    asm volatile("cp.async.cg.shared.global [%0], [%1], 16, %2;"
                 :: "r"(dst), "l"(src), "r"(src_bytes));
}
#define CP_COMMIT() asm volatile("cp.async.commit_group;" ::: "memory")
#define CP_WAIT1()  asm volatile("cp.async.wait_group 1;" ::: "memory")
#define CP_WAIT0()  asm volatile("cp.async.wait_group 0;" ::: "memory")

// ------------------------------------------------------------------- prep ---
__global__ void prep_misc_kernel(const float* __restrict__ W,
                                 const float* __restrict__ bias, int N) {
    int idx = blockIdx.x * blockDim.x + threadIdx.x;
    const int WA_SZ = 64 * 768;
    const int B_SZ = 1536 * 256;
    if (idx < WA_SZ) {
        int m = idx / 768, j = idx % 768;
        g_WaT64[idx] = W[j * 576 + 512 + m];
    } else if (idx < WA_SZ + B_SZ) {
        int r = idx - WA_SZ;
        int j = r >> 8, k = r & 255;
        float v = (j < 768) ? W[j * 576 + k] : W[(j - 768) * 576 + 256 + k];
        __half hi = __float2half(v);
        g_Bh[r] = hi;
        g_Bl[r] = __float2half(v - __half2float(hi));
    } else if (idx < WA_SZ + B_SZ + 1536) {
        int j = idx - (WA_SZ + B_SZ);
        g_PQ[(size_t)N * 1536 + j] = (j < 768) ? bias[j] : 0.0f;
    }
}

// Fused: x -> (Ah, Al) fp16 split; out[:,0:256]=x; out[:,256:512]=0.
__global__ void fused_init_kernel(const float* __restrict__ x,
                                  float* __restrict__ out, int total) {
    int idx = blockIdx.x * blockDim.x + threadIdx.x;
    if (idx < total) {
        float v = x[idx];
        __half hi = __float2half(v);
        g_Ah[idx] = hi;
        g_Al[idx] = __float2half(v - __half2float(hi));
        int r = idx >> 8, c = idx & 255;
        out[(size_t)r * 512 + c] = v;
        out[(size_t)r * 512 + 256 + c] = 0.0f;
    }
}

// --------------------------------------------------------- angle table ------
// T[e][j] = sum_m S[e][m] * WaT64[m][j].  Block: 64 e-rows x 256 j-cols.
__global__ __launch_bounds__(256)
void table_build_kernel() {
    __shared__ float S[64][65];
    const int tid = threadIdx.x;
    const int e0 = blockIdx.x * 64;
    const int j = blockIdx.y * 256 + tid;

    for (int idx = tid; idx < 64 * 64; idx += 256) {
        int el = idx >> 6, m = idx & 63;
        int e = e0 + el;
        float val = 0.0f;
        if (e <= TAB_N) {
            int mp = m >> 1;
            float u = (float)e * (2.0f / TAB_N) - 1.0f;
            float om = u * expf(-0.28782313662425572f * (float)mp);
            float s, c;
            sincosf(om, &s, &c);
            val = (m & 1) ? c : s;
        }
        S[idx >> 6][m] = val;
    }
    __syncthreads();

    float acc[64];
#pragma unroll
    for (int el = 0; el < 64; el++) acc[el] = 0.0f;
#pragma unroll 8
    for (int m = 0; m < 64; m++) {
        float w = g_WaT64[m * 768 + j];
#pragma unroll
        for (int el = 0; el < 64; el++) acc[el] = fmaf(S[el][m], w, acc[el]);
    }
#pragma unroll
    for (int el = 0; el < 64; el++) {
        int e = e0 + el;
        if (e <= TAB_N) g_TabH[(size_t)e * 768 + j] = __float2half(acc[el]);
    }
}

// --------------------------- cp.async double-buffered split-fp16 GEMM -------
// stage = 4 arrays (Ah, Al, Bh, Bl) x 128 rows x APAD halves. 2 stages.
#define STAGE_B 40960            // bytes per stage (4 * 5120 halves * 2B)
#define ARR_B 10240              // bytes per array
#define GEMM_SMEM_B (2 * STAGE_B)

__global__ __launch_bounds__(256, 2)
void gemm_mma_kernel(const float* __restrict__ bias, int M) {
    extern __shared__ __half smem_h[];
    const int tid = threadIdx.x;
    const int wid = tid >> 5;
    const int lid = tid & 31;
    const int wm = wid >> 2;
    const int wn = wid & 3;
    const int row0 = blockIdx.y * 128;
    const int col0 = blockIdx.x * 128;
    uint32_t sbase = (uint32_t)__cvta_generic_to_shared(smem_h);

    float acc[4][4][4];
#pragma unroll
    for (int i = 0; i < 4; i++)
#pragma unroll
        for (int jq = 0; jq < 4; jq++)
#pragma unroll
            for (int r = 0; r < 4; r++) acc[i][jq][r] = 0.0f;

    const int lrow = lid & 15;
    const int lkoff = (lid >> 4) * 16;

#define ISSUE(ST, KK)                                                         \
    {                                                                         \
        uint32_t stb = sbase + (ST) * STAGE_B;                                \
        _Pragma("unroll") for (int l = 0; l < 2; l++) {                       \
            int fid = tid + l * 256;                                          \
            int r = fid >> 2, q = fid & 3;                                    \
            uint32_t d0 = stb + (uint32_t)(r * APAD + q * 8) * 2;             \
            int grow = row0 + r;                                              \
            int asz = (grow < M) ? 16 : 0;                                    \
            size_t asrc = (size_t)(grow < M ? grow : 0) * 256 + (KK) + q * 8; \
            cp_async16(d0, g_Ah + asrc, asz);                                 \
            cp_async16(d0 + ARR_B, g_Al + asrc, asz);                         \
            size_t bsrc = (size_t)(col0 + r) * 256 + (KK) + q * 8;            \
            cp_async16(d0 + 2 * ARR_B, g_Bh + bsrc, 16);                      \
            cp_async16(d0 + 3 * ARR_B, g_Bl + bsrc, 16);                      \
        }                                                                     \
        CP_COMMIT();                                                          \
    }

    ISSUE(0, 0)
    for (int kt = 0; kt < 8; kt++) {
        if (kt < 7) {
            ISSUE((kt + 1) & 1, (kt + 1) * 32)
            CP_WAIT1();
        } else {
            CP_WAIT0();
        }
        __syncthreads();

        uint32_t stb = sbase + (kt & 1) * STAGE_B;
#pragma unroll
        for (int k16 = 0; k16 < 32; k16 += 16) {
            uint32_t bh[2][4], bl[2][4];
#pragma unroll
            for (int nt = 0; nt < 2; nt++) {
                uint32_t boff = stb + 2 * ARR_B +
                    (uint32_t)((wn * 32 + nt * 16 + lrow) * APAD + k16) * 2 +
                    lkoff;
                ldsm4(bh[nt][0], bh[nt][1], bh[nt][2], bh[nt][3], boff);
                ldsm4(bl[nt][0], bl[nt][1], bl[nt][2], bl[nt][3], boff + ARR_B);
            }
#pragma unroll
            for (int mt = 0; mt < 4; mt++) {
                uint32_t aoff = stb +
                    (uint32_t)((wm * 64 + mt * 16 + lrow) * APAD + k16) * 2 +
                    lkoff;
                uint32_t ah[4], al[4];
                ldsm4(ah[0], ah[1], ah[2], ah[3], aoff);
                ldsm4(al[0], al[1], al[2], al[3], aoff + ARR_B);
#pragma unroll
                for (int n = 0; n < 4; n++) {
                    int nt = n >> 1, jj = n & 1;
                    mma16816(acc[mt][n], ah, bh[nt][jj], bh[nt][jj + 2]);
                    mma16816(acc[mt][n], ah, bl[nt][jj], bl[nt][jj + 2]);
                    mma16816(acc[mt][n], al, bh[nt][jj], bh[nt][jj + 2]);
                }
            }
        }
        __syncthreads();
    }
#undef ISSUE

#pragma unroll
    for (int mt = 0; mt < 4; mt++) {
#pragma unroll
        for (int n = 0; n < 4; n++) {
            int gcol = col0 + wn * 32 + (n >> 1) * 16 + (n & 1) * 8 +
                       (lid & 3) * 2;
            float bx = 0.f, by = 0.f;
            if (gcol < 768) { bx = bias[gcol]; by = bias[gcol + 1]; }
            int r0g = row0 + wm * 64 + mt * 16 + (lid >> 2);
            if (r0g < M) {
                float2 o = make_float2(acc[mt][n][0] + bx, acc[mt][n][1] + by);
                *(float2*)(g_PQ + (size_t)r0g * 1536 + gcol) = o;
            }
            if (r0g + 8 < M) {
                float2 o = make_float2(acc[mt][n][2] + bx, acc[mt][n][3] + by);
                *(float2*)(g_PQ + (size_t)(r0g + 8) * 1536 + gcol) = o;
            }
        }
    }
}

// --------------------------------------------------------------- main ------
__global__ __launch_bounds__(256, 3)
void triplet_main_kernel(const float* __restrict__ pos,
                         const int* __restrict__ anchor_idx,
                         const int* __restrict__ corner_idx,
                         const int* __restrict__ masks,
                         float* __restrict__ out,
                         int N, int write_masks) {
    __shared__ __align__(16) __half qh[16][QP];
    __shared__ __align__(16) __half ql[16][QP];
    __shared__ __align__(16) __half kh[16][QP];
    __shared__ __align__(16) __half kl[16][QP];
    __shared__ __align__(16) float sS[16][17];
    __shared__ __align__(16) float red[16][16];
    __shared__ __align__(16) u64 vp[2][128];
    __shared__ int ci0s[16], ci1s[16];
    __shared__ int tIdx[16];
    __shared__ float maskf[16], wsh[16];

    const int n = blockIdx.x;
    const int tid = threadIdx.x;
    const int cp = tid & 127;
    const int th = tid >> 7;
    const int lid = tid & 31;
    const int a_idx = anchor_idx[n];

    // ---- Phase 0: triplet geometry + table index (nearest) ----
    if (tid < 16) {
        int t = tid;
        float ax = 0.f, ay = 0.f;
        if (a_idx >= 0 && a_idx < N) {
            ax = pos[(size_t)a_idx * 3 + 0];
            ay = pos[(size_t)a_idx * 3 + 1];
        }
        int i0 = corner_idx[(size_t)n * 32 + 2 * t];
        int i1 = corner_idx[(size_t)n * 32 + 2 * t + 1];
        float p0x = 0.f, p0y = 0.f, p1x = 0.f, p1y = 0.f;
        if (i0 >= 0 && i0 < N) { p0x = pos[(size_t)i0 * 3]; p0y = pos[(size_t)i0 * 3 + 1]; }
        if (i1 >= 0 && i1 < N) { p1x = pos[(size_t)i1 * 3]; p1y = pos[(size_t)i1 * 3 + 1]; }
        float v0x = p0x - ax, v0y = p0y - ay;
        float v1x = p1x - ax, v1y = p1y - ay;
        float dot = v0x * v1x + v0y * v1y;
        float n0 = sqrtf(v0x * v0x + v0y * v0y);
        float n1 = sqrtf(v1x * v1x + v1y * v1y);
        float cosv = dot / (n0 * n1 + 1e-6f);
        float sinz = v0x * v1y - v0y * v1x;
        bool reorder = sinz < 0.0f;
        ci0s[t] = reorder ? i1 : i0;
        ci1s[t] = reorder ? i0 : i1;
        float s = (cosv + 1.0f) * (TAB_N * 0.5f);
        int ti = (int)floorf(s + 0.5f);
        if (ti < 0) ti = 0;
        if (ti > TAB_N) ti = TAB_N;
        tIdx[t] = ti;
        int mb = masks[(size_t)n * 16 + t];
        maskf[t] = (mb != 0) ? 1.0f : 0.0f;
        if (write_masks) {
            float newsin = reorder ? -sinz : sinz;
            out[(size_t)N * 512 + (size_t)n * 16 + t] =
                ((newsin < -1e-6f) && (mb != 0)) ? 1.0f : 0.0f;
        }
    }
    __syncthreads();

    // ---- Phase 1: gathers + NN table; stage q,k as fp16 hi/lo ----
    u64 v2[8];
#pragma unroll
    for (int tt = 0; tt < 8; tt++) {
        int t = 8 * th + tt;
        int i0 = ci0s[t]; if (i0 < 0 || i0 > N) i0 = N;
        int i1 = ci1s[t]; if (i1 < 0 || i1 > N) i1 = N;
        const float2* r0 = (const float2*)(g_PQ + (size_t)i0 * 1536);
        const float2* r1 = (const float2*)(g_PQ + (size_t)i1 * 1536 + 768);
        float2 pq = r0[cp],       qq = r1[cp];
        float2 pk = r0[128 + cp], qk = r1[128 + cp];
        float2 pv = r0[256 + cp], qv = r1[256 + cp];

        const __half2* T0 = (const __half2*)(g_TabH + (size_t)tIdx[t] * 768);
        float2 aq = __half22float2(T0[cp]);
        float2 ak = __half22float2(T0[128 + cp]);
        float2 av = __half22float2(T0[256 + cp]);

        float qx = pq.x + qq.x + aq.x;
        float qy = pq.y + qq.y + aq.y;
        float kx = pk.x + qk.x + ak.x;
        float ky = pk.y + qk.y + ak.y;
        float vx = pv.x + qv.x + av.x;
        float vy = pv.y + qv.y + av.y;

        __half qhx = __float2half(qx), qhy = __float2half(qy);
        __half khx = __float2half(kx), khy = __float2half(ky);
        *(__half2*)&qh[t][2 * cp] = __halves2half2(qhx, qhy);
        *(__half2*)&ql[t][2 * cp] = __halves2half2(
            __float2half(qx - __half2float(qhx)),
            __float2half(qy - __half2float(qhy)));
        *(__half2*)&kh[t][2 * cp] = __halves2half2(khx, khy);
        *(__half2*)&kl[t][2 * cp] = __halves2half2(
            __float2half(kx - __half2float(khx)),
            __float2half(ky - __half2float(khy)));
        v2[tt] = pack2(vx, vy);
    }
    __syncthreads();

    // ---- Phase 2: S = q k^T via split-fp16 mma (warp 0) ----
    if (tid < 32) {
        const int lrow = lid & 15;
        const int lkoff = (lid >> 4) * 16;
        uint32_t qh_u = (uint32_t)__cvta_generic_to_shared(qh);
        uint32_t ql_u = (uint32_t)__cvta_generic_to_shared(ql);
        uint32_t kh_u = (uint32_t)__cvta_generic_to_shared(kh);
        uint32_t kl_u = (uint32_t)__cvta_generic_to_shared(kl);
        float acc[2][4];
#pragma unroll
        for (int jj = 0; jj < 2; jj++)
#pragma unroll
            for (int r = 0; r < 4; r++) acc[jj][r] = 0.0f;

#pragma unroll
        for (int k16 = 0; k16 < 256; k16 += 16) {
            uint32_t off = (uint32_t)(lrow * QP + k16) * 2 + lkoff;
            uint32_t ah[4], al[4], bh[4], bl[4];
            ldsm4(ah[0], ah[1], ah[2], ah[3], qh_u + off);
            ldsm4(al[0], al[1], al[2], al[3], ql_u + off);
            ldsm4(bh[0], bh[1], bh[2], bh[3], kh_u + off);
            ldsm4(bl[0], bl[1], bl[2], bl[3], kl_u + off);
#pragma unroll
            for (int jj = 0; jj < 2; jj++) {
                mma16816(acc[jj], ah, bh[jj], bh[jj + 2]);
                mma16816(acc[jj], ah, bl[jj], bl[jj + 2]);
                mma16816(acc[jj], al, bh[jj], bh[jj + 2]);
            }
        }
        int r0 = lid >> 2;
        int c0 = (lid & 3) * 2;
#pragma unroll
        for (int jj = 0; jj < 2; jj++) {
            sS[r0][jj * 8 + c0] = acc[jj][0];
            sS[r0][jj * 8 + c0 + 1] = acc[jj][1];
            sS[r0 + 8][jj * 8 + c0] = acc[jj][2];
            sS[r0 + 8][jj * 8 + c0 + 1] = acc[jj][3];
        }
    }
    __syncthreads();

    // ---- Phase 3: softmax ----
    {
        int aa = tid >> 4, bb = tid & 15;
        float sc = sS[aa][bb] * 0.0625f;
        float mx = sc;
#pragma unroll
        for (int off = 8; off > 0; off >>= 1)
            mx = fmaxf(mx, __shfl_xor_sync(0xffffffffu, mx, off, 16));
        float e = expf(sc - mx);
        float sm = e;
#pragma unroll
        for (int off = 8; off > 0; off >>= 1)
            sm += __shfl_xor_sync(0xffffffffu, sm, off, 16);
        float attn = e / sm;
        red[aa][bb] = maskf[aa] * attn;
    }
    __syncthreads();

    // ---- Phase 4: fold mask-mean into per-k weights ----
    if (tid < 16) {
        float s = 0.0f, dn = 0.0f;
#pragma unroll
        for (int a2 = 0; a2 < 16; a2++) {
            s += red[a2][tid];
            dn += maskf[a2];
        }
        wsh[tid] = s / dn;
    }
    __syncthreads();

    // ---- Phase 5: mean over t, scatter ----
    {
        u64 part = pack2(0.f, 0.f);
#pragma unroll
        for (int tt = 0; tt < 8; tt++) {
            float w = wsh[8 * th + tt];
            part = ffma2(pack2(w, w), v2[tt], part);
        }
        vp[th][cp] = part;
        __syncthreads();
        if (th == 0) {
            u64 tot = fadd2(vp[0][cp], vp[1][cp]);
            if (a_idx >= 0 && a_idx < N) {
                float2 o;
                o.x = lo32(tot);
                o.y = hi32(tot);
                *(float2*)(out + (size_t)a_idx * 512 + 256 + 2 * cp) = o;
            }
        }
    }
}

// ----------------------------------------------------------------------------
extern "C" void kernel_launch(void* const* d_in, const int* in_sizes, int n_in,
                              void* d_out, int out_size) {
    if (n_in < 7) return;
    const float* x = (const float*)d_in[0];
    const float* pos = (const float*)d_in[1];
    const int* anchor = (const int*)d_in[2];
    const int* corner = (const int*)d_in[3];
    const int* masks = (const int*)d_in[4];
    const float* W = (const float*)d_in[5];
    const float* bias = (const float*)d_in[6];
    float* out = (float*)d_out;

    int N = in_sizes[0] / 256;
    if (N > MAXN) N = MAXN;
    int write_masks = (out_size >= N * 512 + N * 16) ? 1 : 0;

    cudaFuncSetAttribute(gemm_mma_kernel,
                         cudaFuncAttributeMaxDynamicSharedMemorySize,
                         GEMM_SMEM_B);

    const int prep_work = 64 * 768 + 1536 * 256 + 1536;
    prep_misc_kernel<<<(prep_work + 255) / 256, 256>>>(W, bias, N);
    fused_init_kernel<<<(N * 256 + 255) / 256, 256>>>(x, out, N * 256);

    dim3 tg((TAB_N + 64) / 64, 3);
    table_build_kernel<<<tg, 256>>>();

    dim3 gg(12, (N + 127) / 128);
    gemm_mma_kernel<<<gg, 256, GEMM_SMEM_B>>>(bias, N);

    triplet_main_kernel<<<N, 256>>>(pos, anchor, corner, masks, out, N, write_masks);
}

// round 11
// speedup vs baseline: 2.7087x; 1.0638x over previous
#include <cuda_runtime.h>
#include <cuda_fp16.h>
#include <math.h>
#include <stdint.h>
#include <stddef.h>

// ============================================================================
// TripletGNN:
//   qkv(n,t) = P[ci0] + Q[ci1] + g(cos_values(n,t))
//   g tabulated at 4097 points, nearest-neighbor.
//   [P|Q] = x @ B via cp.async double-buffered split-fp16 mma.sync.
//   16x16 scores via split-fp16 mma.sync (warp 0).
// ============================================================================

#define MAXN 40000
#define TAB_N 4096
#define APAD 40
#define QP 264

typedef unsigned long long u64;

__device__ float  g_PQ[(size_t)(MAXN + 1) * 1536];
__device__ float  g_WaT64[64 * 768];
__device__ __half g_TabH[(size_t)(TAB_N + 1) * 768];
__device__ __half g_Ah[(size_t)MAXN * 256];
__device__ __half g_Al[(size_t)MAXN * 256];
__device__ __half g_Bh[1536 * 256];
__device__ __half g_Bl[1536 * 256];

// ------------------------------------------------------------ f32x2 helpers -
__device__ __forceinline__ u64 ffma2(u64 a, u64 b, u64 c) {
    u64 d;
    asm("fma.rn.f32x2 %0, %1, %2, %3;" : "=l"(d) : "l"(a), "l"(b), "l"(c));
    return d;
}
__device__ __forceinline__ u64 fadd2(u64 a, u64 b) {
    u64 d;
    asm("add.rn.f32x2 %0, %1, %2;" : "=l"(d) : "l"(a), "l"(b));
    return d;
}
__device__ __forceinline__ u64 pack2(float lo, float hi) {
    u64 d;
    asm("mov.b64 %0, {%1, %2};" : "=l"(d) : "f"(lo), "f"(hi));
    return d;
}
__device__ __forceinline__ float lo32(u64 v) {
    return __uint_as_float((unsigned)(v & 0xffffffffull));
}
__device__ __forceinline__ float hi32(u64 v) {
    return __uint_as_float((unsigned)(v >> 32));
}

// ------------------------------------------------------------ mma helpers ---
__device__ __forceinline__ void ldsm4(uint32_t& r0, uint32_t& r1,
                                      uint32_t& r2, uint32_t& r3,
                                      uint32_t addr) {
    asm volatile("ldmatrix.sync.aligned.m8n8.x4.shared.b16 {%0,%1,%2,%3}, [%4];"
                 : "=r"(r0), "=r"(r1), "=r"(r2), "=r"(r3) : "r"(addr));
}
__device__ __forceinline__ void mma16816(float* d, const uint32_t* a,
                                         uint32_t b0, uint32_t b1) {
    asm volatile(
        "mma.sync.aligned.m16n8k16.row.col.f32.f16.f16.f32 "
        "{%0,%1,%2,%3}, {%4,%5,%6,%7}, {%8,%9}, {%0,%1,%2,%3};"
        : "+f"(d[0]), "+f"(d[1]), "+f"(d[2]), "+f"(d[3])
        : "r"(a[0]), "r"(a[1]), "r"(a[2]), "r"(a[3]), "r"(b0), "r"(b1));
}
__device__ __forceinline__ void cp_async16(uint32_t dst, const void* src,
                                           int src_bytes) {
    asm volatile("cp.async.cg.shared.global [%0], [%1], 16, %2;"
                 :: "r"(dst), "l"(src), "r"(src_bytes));
}
#define CP_COMMIT() asm volatile("cp.async.commit_group;" ::: "memory")
#define CP_WAIT1()  asm volatile("cp.async.wait_group 1;" ::: "memory")
#define CP_WAIT0()  asm volatile("cp.async.wait_group 0;" ::: "memory")

// ------------------------------------------------------------------- prep ---
__global__ void prep_misc_kernel(const float* __restrict__ W,
                                 const float* __restrict__ bias, int N) {
    int idx = blockIdx.x * blockDim.x + threadIdx.x;
    const int WA_SZ = 64 * 768;
    const int B_SZ = 1536 * 256;
    if (idx < WA_SZ) {
        int m = idx / 768, j = idx % 768;
        g_WaT64[idx] = W[j * 576 + 512 + m];
    } else if (idx < WA_SZ + B_SZ) {
        int r = idx - WA_SZ;
        int j = r >> 8, k = r & 255;
        float v = (j < 768) ? W[j * 576 + k] : W[(j - 768) * 576 + 256 + k];
        __half hi = __float2half(v);
        g_Bh[r] = hi;
        g_Bl[r] = __float2half(v - __half2float(hi));
    } else if (idx < WA_SZ + B_SZ + 1536) {
        int j = idx - (WA_SZ + B_SZ);
        g_PQ[(size_t)N * 1536 + j] = (j < 768) ? bias[j] : 0.0f;
    }
}

// Fused, float4-vectorized: x -> (Ah, Al) split; out[:,0:256]=x; [256:512]=0.
__global__ void fused_init_kernel(const float* __restrict__ x,
                                  float* __restrict__ out, int total4) {
    int idx = blockIdx.x * blockDim.x + threadIdx.x;   // over float4s
    if (idx < total4) {
        float4 v = *(const float4*)(x + idx * 4);
        __half h0 = __float2half(v.x), h1 = __float2half(v.y);
        __half h2 = __float2half(v.z), h3 = __float2half(v.w);
        __half2 hi01 = __halves2half2(h0, h1);
        __half2 hi23 = __halves2half2(h2, h3);
        __half2 lo01 = __halves2half2(__float2half(v.x - __half2float(h0)),
                                      __float2half(v.y - __half2float(h1)));
        __half2 lo23 = __halves2half2(__float2half(v.z - __half2float(h2)),
                                      __float2half(v.w - __half2float(h3)));
        *(uint2*)(g_Ah + idx * 4) =
            make_uint2(*(unsigned*)&hi01, *(unsigned*)&hi23);
        *(uint2*)(g_Al + idx * 4) =
            make_uint2(*(unsigned*)&lo01, *(unsigned*)&lo23);
        int r = idx >> 6, c4 = idx & 63;               // 64 float4 per row
        *(float4*)(out + (size_t)r * 512 + c4 * 4) = v;
        *(float4*)(out + (size_t)r * 512 + 256 + c4 * 4) =
            make_float4(0.f, 0.f, 0.f, 0.f);
    }
}

// --------------------------------------------------------- angle table ------
__global__ __launch_bounds__(256)
void table_build_kernel() {
    __shared__ float S[64][65];
    const int tid = threadIdx.x;
    const int e0 = blockIdx.x * 64;
    const int j = blockIdx.y * 256 + tid;

    for (int idx = tid; idx < 64 * 64; idx += 256) {
        int el = idx >> 6, m = idx & 63;
        int e = e0 + el;
        float val = 0.0f;
        if (e <= TAB_N) {
            int mp = m >> 1;
            float u = (float)e * (2.0f / TAB_N) - 1.0f;
            float om = u * expf(-0.28782313662425572f * (float)mp);
            float s, c;
            sincosf(om, &s, &c);
            val = (m & 1) ? c : s;
        }
        S[idx >> 6][m] = val;
    }
    __syncthreads();

    float acc[64];
#pragma unroll
    for (int el = 0; el < 64; el++) acc[el] = 0.0f;
#pragma unroll 8
    for (int m = 0; m < 64; m++) {
        float w = g_WaT64[m * 768 + j];
#pragma unroll
        for (int el = 0; el < 64; el++) acc[el] = fmaf(S[el][m], w, acc[el]);
    }
#pragma unroll
    for (int el = 0; el < 64; el++) {
        int e = e0 + el;
        if (e <= TAB_N) g_TabH[(size_t)e * 768 + j] = __float2half(acc[el]);
    }
}

// --------------------------- cp.async double-buffered split-fp16 GEMM -------
#define STAGE_B 40960
#define ARR_B 10240
#define GEMM_SMEM_B (2 * STAGE_B)

__global__ __launch_bounds__(256, 2)
void gemm_mma_kernel(const float* __restrict__ bias, int M) {
    extern __shared__ __half smem_h[];
    const int tid = threadIdx.x;
    const int wid = tid >> 5;
    const int lid = tid & 31;
    const int wm = wid >> 2;
    const int wn = wid & 3;
    const int row0 = blockIdx.y * 128;
    const int col0 = blockIdx.x * 128;
    uint32_t sbase = (uint32_t)__cvta_generic_to_shared(smem_h);

    float acc[4][4][4];
#pragma unroll
    for (int i = 0; i < 4; i++)
#pragma unroll
        for (int jq = 0; jq < 4; jq++)
#pragma unroll
            for (int r = 0; r < 4; r++) acc[i][jq][r] = 0.0f;

    const int lrow = lid & 15;
    const int lkoff = (lid >> 4) * 16;

#define ISSUE(ST, KK)                                                         \
    {                                                                         \
        uint32_t stb = sbase + (ST) * STAGE_B;                                \
        _Pragma("unroll") for (int l = 0; l < 2; l++) {                       \
            int fid = tid + l * 256;                                          \
            int r = fid >> 2, q = fid & 3;                                    \
            uint32_t d0 = stb + (uint32_t)(r * APAD + q * 8) * 2;             \
            int grow = row0 + r;                                              \
            int asz = (grow < M) ? 16 : 0;                                    \
            size_t asrc = (size_t)(grow < M ? grow : 0) * 256 + (KK) + q * 8; \
            cp_async16(d0, g_Ah + asrc, asz);                                 \
            cp_async16(d0 + ARR_B, g_Al + asrc, asz);                         \
            size_t bsrc = (size_t)(col0 + r) * 256 + (KK) + q * 8;            \
            cp_async16(d0 + 2 * ARR_B, g_Bh + bsrc, 16);                      \
            cp_async16(d0 + 3 * ARR_B, g_Bl + bsrc, 16);                      \
        }                                                                     \
        CP_COMMIT();                                                          \
    }

    ISSUE(0, 0)
    for (int kt = 0; kt < 8; kt++) {
        if (kt < 7) {
            ISSUE((kt + 1) & 1, (kt + 1) * 32)
            CP_WAIT1();
        } else {
            CP_WAIT0();
        }
        __syncthreads();

        uint32_t stb = sbase + (kt & 1) * STAGE_B;
#pragma unroll
        for (int k16 = 0; k16 < 32; k16 += 16) {
            uint32_t bh[2][4], bl[2][4];
#pragma unroll
            for (int nt = 0; nt < 2; nt++) {
                uint32_t boff = stb + 2 * ARR_B +
                    (uint32_t)((wn * 32 + nt * 16 + lrow) * APAD + k16) * 2 +
                    lkoff;
                ldsm4(bh[nt][0], bh[nt][1], bh[nt][2], bh[nt][3], boff);
                ldsm4(bl[nt][0], bl[nt][1], bl[nt][2], bl[nt][3], boff + ARR_B);
            }
#pragma unroll
            for (int mt = 0; mt < 4; mt++) {
                uint32_t aoff = stb +
                    (uint32_t)((wm * 64 + mt * 16 + lrow) * APAD + k16) * 2 +
                    lkoff;
                uint32_t ah[4], al[4];
                ldsm4(ah[0], ah[1], ah[2], ah[3], aoff);
                ldsm4(al[0], al[1], al[2], al[3], aoff + ARR_B);
                // Term-major: consecutive MMAs hit different accumulators
                // (dependency distance 4) instead of chaining on one acc.
#pragma unroll
                for (int n = 0; n < 4; n++) {
                    int nt = n >> 1, jj = n & 1;
                    mma16816(acc[mt][n], ah, bh[nt][jj], bh[nt][jj + 2]);
                }
#pragma unroll
                for (int n = 0; n < 4; n++) {
                    int nt = n >> 1, jj = n & 1;
                    mma16816(acc[mt][n], ah, bl[nt][jj], bl[nt][jj + 2]);
                }
#pragma unroll
                for (int n = 0; n < 4; n++) {
                    int nt = n >> 1, jj = n & 1;
                    mma16816(acc[mt][n], al, bh[nt][jj], bh[nt][jj + 2]);
                }
            }
        }
        __syncthreads();
    }
#undef ISSUE

#pragma unroll
    for (int mt = 0; mt < 4; mt++) {
#pragma unroll
        for (int n = 0; n < 4; n++) {
            int gcol = col0 + wn * 32 + (n >> 1) * 16 + (n & 1) * 8 +
                       (lid & 3) * 2;
            float bx = 0.f, by = 0.f;
            if (gcol < 768) { bx = bias[gcol]; by = bias[gcol + 1]; }
            int r0g = row0 + wm * 64 + mt * 16 + (lid >> 2);
            if (r0g < M) {
                float2 o = make_float2(acc[mt][n][0] + bx, acc[mt][n][1] + by);
                *(float2*)(g_PQ + (size_t)r0g * 1536 + gcol) = o;
            }
            if (r0g + 8 < M) {
                float2 o = make_float2(acc[mt][n][2] + bx, acc[mt][n][3] + by);
                *(float2*)(g_PQ + (size_t)(r0g + 8) * 1536 + gcol) = o;
            }
        }
    }
}

// --------------------------------------------------------------- main ------
__global__ __launch_bounds__(256, 4)
void triplet_main_kernel(const float* __restrict__ pos,
                         const int* __restrict__ anchor_idx,
                         const int* __restrict__ corner_idx,
                         const int* __restrict__ masks,
                         float* __restrict__ out,
                         int N, int write_masks) {
    __shared__ __align__(16) __half qh[16][QP];
    __shared__ __align__(16) __half ql[16][QP];
    __shared__ __align__(16) __half kh[16][QP];
    __shared__ __align__(16) __half kl[16][QP];
    __shared__ __align__(16) float sS[16][17];
    __shared__ __align__(16) float red[16][16];
    __shared__ __align__(16) u64 vp[2][128];
    __shared__ int ci0s[16], ci1s[16];
    __shared__ int tIdx[16];
    __shared__ float maskf[16], wsh[16];

    const int n = blockIdx.x;
    const int tid = threadIdx.x;
    const int cp = tid & 127;
    const int th = tid >> 7;
    const int lid = tid & 31;
    const int a_idx = anchor_idx[n];

    // ---- Phase 0: triplet geometry + table index (nearest) ----
    if (tid < 16) {
        int t = tid;
        float ax = 0.f, ay = 0.f;
        if (a_idx >= 0 && a_idx < N) {
            ax = pos[(size_t)a_idx * 3 + 0];
            ay = pos[(size_t)a_idx * 3 + 1];
        }
        int i0 = corner_idx[(size_t)n * 32 + 2 * t];
        int i1 = corner_idx[(size_t)n * 32 + 2 * t + 1];
        float p0x = 0.f, p0y = 0.f, p1x = 0.f, p1y = 0.f;
        if (i0 >= 0 && i0 < N) { p0x = pos[(size_t)i0 * 3]; p0y = pos[(size_t)i0 * 3 + 1]; }
        if (i1 >= 0 && i1 < N) { p1x = pos[(size_t)i1 * 3]; p1y = pos[(size_t)i1 * 3 + 1]; }
        float v0x = p0x - ax, v0y = p0y - ay;
        float v1x = p1x - ax, v1y = p1y - ay;
        float dot = v0x * v1x + v0y * v1y;
        float n0 = sqrtf(v0x * v0x + v0y * v0y);
        float n1 = sqrtf(v1x * v1x + v1y * v1y);
        float cosv = dot / (n0 * n1 + 1e-6f);
        float sinz = v0x * v1y - v0y * v1x;
        bool reorder = sinz < 0.0f;
        ci0s[t] = reorder ? i1 : i0;
        ci1s[t] = reorder ? i0 : i1;
        float s = (cosv + 1.0f) * (TAB_N * 0.5f);
        int ti = (int)floorf(s + 0.5f);
        if (ti < 0) ti = 0;
        if (ti > TAB_N) ti = TAB_N;
        tIdx[t] = ti;
        int mb = masks[(size_t)n * 16 + t];
        maskf[t] = (mb != 0) ? 1.0f : 0.0f;
        if (write_masks) {
            float newsin = reorder ? -sinz : sinz;
            out[(size_t)N * 512 + (size_t)n * 16 + t] =
                ((newsin < -1e-6f) && (mb != 0)) ? 1.0f : 0.0f;
        }
    }
    __syncthreads();

    // ---- Phase 1: gathers + NN table; stage q,k as fp16 hi/lo ----
    u64 v2[8];
#pragma unroll
    for (int tt = 0; tt < 8; tt++) {
        int t = 8 * th + tt;
        int i0 = ci0s[t]; if (i0 < 0 || i0 > N) i0 = N;
        int i1 = ci1s[t]; if (i1 < 0 || i1 > N) i1 = N;
        const float2* r0 = (const float2*)(g_PQ + (size_t)i0 * 1536);
        const float2* r1 = (const float2*)(g_PQ + (size_t)i1 * 1536 + 768);
        float2 pq = r0[cp],       qq = r1[cp];
        float2 pk = r0[128 + cp], qk = r1[128 + cp];
        float2 pv = r0[256 + cp], qv = r1[256 + cp];

        const __half2* T0 = (const __half2*)(g_TabH + (size_t)tIdx[t] * 768);
        float2 aq = __half22float2(T0[cp]);
        float2 ak = __half22float2(T0[128 + cp]);
        float2 av = __half22float2(T0[256 + cp]);

        float qx = pq.x + qq.x + aq.x;
        float qy = pq.y + qq.y + aq.y;
        float kx = pk.x + qk.x + ak.x;
        float ky = pk.y + qk.y + ak.y;
        float vx = pv.x + qv.x + av.x;
        float vy = pv.y + qv.y + av.y;

        __half qhx = __float2half(qx), qhy = __float2half(qy);
        __half khx = __float2half(kx), khy = __float2half(ky);
        *(__half2*)&qh[t][2 * cp] = __halves2half2(qhx, qhy);
        *(__half2*)&ql[t][2 * cp] = __halves2half2(
            __float2half(qx - __half2float(qhx)),
            __float2half(qy - __half2float(qhy)));
        *(__half2*)&kh[t][2 * cp] = __halves2half2(khx, khy);
        *(__half2*)&kl[t][2 * cp] = __halves2half2(
            __float2half(kx - __half2float(khx)),
            __float2half(ky - __half2float(khy)));
        v2[tt] = pack2(vx, vy);
    }
    __syncthreads();

    // ---- Phase 2: S = q k^T via split-fp16 mma (warp 0) ----
    if (tid < 32) {
        const int lrow = lid & 15;
        const int lkoff = (lid >> 4) * 16;
        uint32_t qh_u = (uint32_t)__cvta_generic_to_shared(qh);
        uint32_t ql_u = (uint32_t)__cvta_generic_to_shared(ql);
        uint32_t kh_u = (uint32_t)__cvta_generic_to_shared(kh);
        uint32_t kl_u = (uint32_t)__cvta_generic_to_shared(kl);
        float acc[2][4];
#pragma unroll
        for (int jj = 0; jj < 2; jj++)
#pragma unroll
            for (int r = 0; r < 4; r++) acc[jj][r] = 0.0f;

#pragma unroll
        for (int k16 = 0; k16 < 256; k16 += 16) {
            uint32_t off = (uint32_t)(lrow * QP + k16) * 2 + lkoff;
            uint32_t ah[4], al[4], bh[4], bl[4];
            ldsm4(ah[0], ah[1], ah[2], ah[3], qh_u + off);
            ldsm4(al[0], al[1], al[2], al[3], ql_u + off);
            ldsm4(bh[0], bh[1], bh[2], bh[3], kh_u + off);
            ldsm4(bl[0], bl[1], bl[2], bl[3], kl_u + off);
#pragma unroll
            for (int jj = 0; jj < 2; jj++)
                mma16816(acc[jj], ah, bh[jj], bh[jj + 2]);
#pragma unroll
            for (int jj = 0; jj < 2; jj++)
                mma16816(acc[jj], ah, bl[jj], bl[jj + 2]);
#pragma unroll
            for (int jj = 0; jj < 2; jj++)
                mma16816(acc[jj], al, bh[jj], bh[jj + 2]);
        }
        int r0 = lid >> 2;
        int c0 = (lid & 3) * 2;
#pragma unroll
        for (int jj = 0; jj < 2; jj++) {
            sS[r0][jj * 8 + c0] = acc[jj][0];
            sS[r0][jj * 8 + c0 + 1] = acc[jj][1];
            sS[r0 + 8][jj * 8 + c0] = acc[jj][2];
            sS[r0 + 8][jj * 8 + c0 + 1] = acc[jj][3];
        }
    }
    __syncthreads();

    // ---- Phase 3: softmax ----
    {
        int aa = tid >> 4, bb = tid & 15;
        float sc = sS[aa][bb] * 0.0625f;
        float mx = sc;
#pragma unroll
        for (int off = 8; off > 0; off >>= 1)
            mx = fmaxf(mx, __shfl_xor_sync(0xffffffffu, mx, off, 16));
        float e = expf(sc - mx);
        float sm = e;
#pragma unroll
        for (int off = 8; off > 0; off >>= 1)
            sm += __shfl_xor_sync(0xffffffffu, sm, off, 16);
        float attn = e / sm;
        red[aa][bb] = maskf[aa] * attn;
    }
    __syncthreads();

    // ---- Phase 4: fold mask-mean into per-k weights ----
    if (tid < 16) {
        float s = 0.0f, dn = 0.0f;
#pragma unroll
        for (int a2 = 0; a2 < 16; a2++) {
            s += red[a2][tid];
            dn += maskf[a2];
        }
        wsh[tid] = s / dn;
    }
    __syncthreads();

    // ---- Phase 5: mean over t, scatter ----
    {
        u64 part = pack2(0.f, 0.f);
#pragma unroll
        for (int tt = 0; tt < 8; tt++) {
            float w = wsh[8 * th + tt];
            part = ffma2(pack2(w, w), v2[tt], part);
        }
        vp[th][cp] = part;
        __syncthreads();
        if (th == 0) {
            u64 tot = fadd2(vp[0][cp], vp[1][cp]);
            if (a_idx >= 0 && a_idx < N) {
                float2 o;
                o.x = lo32(tot);
                o.y = hi32(tot);
                *(float2*)(out + (size_t)a_idx * 512 + 256 + 2 * cp) = o;
            }
        }
    }
}

// ----------------------------------------------------------------------------
extern "C" void kernel_launch(void* const* d_in, const int* in_sizes, int n_in,
                              void* d_out, int out_size) {
    if (n_in < 7) return;
    const float* x = (const float*)d_in[0];
    const float* pos = (const float*)d_in[1];
    const int* anchor = (const int*)d_in[2];
    const int* corner = (const int*)d_in[3];
    const int* masks = (const int*)d_in[4];
    const float* W = (const float*)d_in[5];
    const float* bias = (const float*)d_in[6];
    float* out = (float*)d_out;

    int N = in_sizes[0] / 256;
    if (N > MAXN) N = MAXN;
    int write_masks = (out_size >= N * 512 + N * 16) ? 1 : 0;

    cudaFuncSetAttribute(gemm_mma_kernel,
                         cudaFuncAttributeMaxDynamicSharedMemorySize,
                         GEMM_SMEM_B);

    const int prep_work = 64 * 768 + 1536 * 256 + 1536;
    prep_misc_kernel<<<(prep_work + 255) / 256, 256>>>(W, bias, N);

    int total4 = N * 64;   // float4s
    fused_init_kernel<<<(total4 + 255) / 256, 256>>>(x, out, total4);

    dim3 tg((TAB_N + 64) / 64, 3);
    table_build_kernel<<<tg, 256>>>();

    dim3 gg(12, (N + 127) / 128);
    gemm_mma_kernel<<<gg, 256, GEMM_SMEM_B>>>(bias, N);

    triplet_main_kernel<<<N, 256>>>(pos, anchor, corner, masks, out, N, write_masks);
}

// round 12
// speedup vs baseline: 2.7319x; 1.0086x over previous
#include <cuda_runtime.h>
#include <cuda_fp16.h>
#include <math.h>
#include <stdint.h>
#include <stddef.h>

// ============================================================================
// TripletGNN:
//   qkv(n,t) = P[ci0] + Q[ci1] + g(cos_values(n,t))
//   g tabulated at 4097 points, nearest-neighbor.
//   [P|Q] = x @ B via cp.async double-buffered split-fp16 mma.sync
//           (128x64 tile, 3 CTAs/SM).
//   16x16 scores via split-fp16 mma.sync, K split across 4 warps.
// ============================================================================

#define MAXN 40000
#define TAB_N 4096
#define APAD 40
#define QP 264

typedef unsigned long long u64;

__device__ float  g_PQ[(size_t)(MAXN + 1) * 1536];
__device__ float  g_WaT64[64 * 768];
__device__ __half g_TabH[(size_t)(TAB_N + 1) * 768];
__device__ __half g_Ah[(size_t)MAXN * 256];
__device__ __half g_Al[(size_t)MAXN * 256];
__device__ __half g_Bh[1536 * 256];
__device__ __half g_Bl[1536 * 256];

// ------------------------------------------------------------ f32x2 helpers -
__device__ __forceinline__ u64 ffma2(u64 a, u64 b, u64 c) {
    u64 d;
    asm("fma.rn.f32x2 %0, %1, %2, %3;" : "=l"(d) : "l"(a), "l"(b), "l"(c));
    return d;
}
__device__ __forceinline__ u64 fadd2(u64 a, u64 b) {
    u64 d;
    asm("add.rn.f32x2 %0, %1, %2;" : "=l"(d) : "l"(a), "l"(b));
    return d;
}
__device__ __forceinline__ u64 pack2(float lo, float hi) {
    u64 d;
    asm("mov.b64 %0, {%1, %2};" : "=l"(d) : "f"(lo), "f"(hi));
    return d;
}
__device__ __forceinline__ float lo32(u64 v) {
    return __uint_as_float((unsigned)(v & 0xffffffffull));
}
__device__ __forceinline__ float hi32(u64 v) {
    return __uint_as_float((unsigned)(v >> 32));
}

// ------------------------------------------------------------ mma helpers ---
__device__ __forceinline__ void ldsm4(uint32_t& r0, uint32_t& r1,
                                      uint32_t& r2, uint32_t& r3,
                                      uint32_t addr) {
    asm volatile("ldmatrix.sync.aligned.m8n8.x4.shared.b16 {%0,%1,%2,%3}, [%4];"
                 : "=r"(r0), "=r"(r1), "=r"(r2), "=r"(r3) : "r"(addr));
}
__device__ __forceinline__ void mma16816(float* d, const uint32_t* a,
                                         uint32_t b0, uint32_t b1) {
    asm volatile(
        "mma.sync.aligned.m16n8k16.row.col.f32.f16.f16.f32 "
        "{%0,%1,%2,%3}, {%4,%5,%6,%7}, {%8,%9}, {%0,%1,%2,%3};"
        : "+f"(d[0]), "+f"(d[1]), "+f"(d[2]), "+f"(d[3])
        : "r"(a[0]), "r"(a[1]), "r"(a[2]), "r"(a[3]), "r"(b0), "r"(b1));
}
__device__ __forceinline__ void cp_async16(uint32_t dst, const void* src,
                                           int src_bytes) {
    asm volatile("cp.async.cg.shared.global [%0], [%1], 16, %2;"
                 :: "r"(dst), "l"(src), "r"(src_bytes));
}
#define CP_COMMIT() asm volatile("cp.async.commit_group;" ::: "memory")
#define CP_WAIT1()  asm volatile("cp.async.wait_group 1;" ::: "memory")
#define CP_WAIT0()  asm volatile("cp.async.wait_group 0;" ::: "memory")

// ------------------------------------------------------------------- prep ---
__global__ void prep_misc_kernel(const float* __restrict__ W,
                                 const float* __restrict__ bias, int N) {
    int idx = blockIdx.x * blockDim.x + threadIdx.x;
    const int WA_SZ = 64 * 768;
    const int B_SZ = 1536 * 256;
    if (idx < WA_SZ) {
        int m = idx / 768, j = idx % 768;
        g_WaT64[idx] = W[j * 576 + 512 + m];
    } else if (idx < WA_SZ + B_SZ) {
        int r = idx - WA_SZ;
        int j = r >> 8, k = r & 255;
        float v = (j < 768) ? W[j * 576 + k] : W[(j - 768) * 576 + 256 + k];
        __half hi = __float2half(v);
        g_Bh[r] = hi;
        g_Bl[r] = __float2half(v - __half2float(hi));
    } else if (idx < WA_SZ + B_SZ + 1536) {
        int j = idx - (WA_SZ + B_SZ);
        g_PQ[(size_t)N * 1536 + j] = (j < 768) ? bias[j] : 0.0f;
    }
}

// Fused, float4-vectorized: x -> (Ah, Al) split; out[:,0:256]=x; [256:512]=0.
__global__ void fused_init_kernel(const float* __restrict__ x,
                                  float* __restrict__ out, int total4) {
    int idx = blockIdx.x * blockDim.x + threadIdx.x;
    if (idx < total4) {
        float4 v = *(const float4*)(x + idx * 4);
        __half h0 = __float2half(v.x), h1 = __float2half(v.y);
        __half h2 = __float2half(v.z), h3 = __float2half(v.w);
        __half2 hi01 = __halves2half2(h0, h1);
        __half2 hi23 = __halves2half2(h2, h3);
        __half2 lo01 = __halves2half2(__float2half(v.x - __half2float(h0)),
                                      __float2half(v.y - __half2float(h1)));
        __half2 lo23 = __halves2half2(__float2half(v.z - __half2float(h2)),
                                      __float2half(v.w - __half2float(h3)));
        *(uint2*)(g_Ah + idx * 4) =
            make_uint2(*(unsigned*)&hi01, *(unsigned*)&hi23);
        *(uint2*)(g_Al + idx * 4) =
            make_uint2(*(unsigned*)&lo01, *(unsigned*)&lo23);
        int r = idx >> 6, c4 = idx & 63;
        *(float4*)(out + (size_t)r * 512 + c4 * 4) = v;
        *(float4*)(out + (size_t)r * 512 + 256 + c4 * 4) =
            make_float4(0.f, 0.f, 0.f, 0.f);
    }
}

// --------------------------------------------------------- angle table ------
__global__ __launch_bounds__(256)
void table_build_kernel() {
    __shared__ float S[64][65];
    const int tid = threadIdx.x;
    const int e0 = blockIdx.x * 64;
    const int j = blockIdx.y * 256 + tid;

    for (int idx = tid; idx < 64 * 64; idx += 256) {
        int el = idx >> 6, m = idx & 63;
        int e = e0 + el;
        float val = 0.0f;
        if (e <= TAB_N) {
            int mp = m >> 1;
            float u = (float)e * (2.0f / TAB_N) - 1.0f;
            float om = u * expf(-0.28782313662425572f * (float)mp);
            float s, c;
            sincosf(om, &s, &c);
            val = (m & 1) ? c : s;
        }
        S[idx >> 6][m] = val;
    }
    __syncthreads();

    float acc[64];
#pragma unroll
    for (int el = 0; el < 64; el++) acc[el] = 0.0f;
#pragma unroll 8
    for (int m = 0; m < 64; m++) {
        float w = g_WaT64[m * 768 + j];
#pragma unroll
        for (int el = 0; el < 64; el++) acc[el] = fmaf(S[el][m], w, acc[el]);
    }
#pragma unroll
    for (int el = 0; el < 64; el++) {
        int e = e0 + el;
        if (e <= TAB_N) g_TabH[(size_t)e * 768 + j] = __float2half(acc[el]);
    }
}

// --------------------------- cp.async double-buffered split-fp16 GEMM -------
// Tile: 128(M) x 64(N), K chunks of 32. Warps: 2(M) x 4(N), warp tile 64x16.
// Stage: [Ah 10240][Al 10240][Bh 5120][Bl 5120] = 30720 B, 2 stages.
#define OFF_AH 0
#define OFF_AL 10240
#define OFF_BH 20480
#define OFF_BL 25600
#define STAGE_B 30720
#define GEMM_SMEM_B (2 * STAGE_B)

__global__ __launch_bounds__(256, 3)
void gemm_mma_kernel(const float* __restrict__ bias, int M) {
    extern __shared__ __half smem_h[];
    const int tid = threadIdx.x;
    const int wid = tid >> 5;
    const int lid = tid & 31;
    const int wm = wid >> 2;
    const int wn = wid & 3;
    const int row0 = blockIdx.y * 128;
    const int col0 = blockIdx.x * 64;
    uint32_t sbase = (uint32_t)__cvta_generic_to_shared(smem_h);

    float acc[4][2][4];
#pragma unroll
    for (int i = 0; i < 4; i++)
#pragma unroll
        for (int jq = 0; jq < 2; jq++)
#pragma unroll
            for (int r = 0; r < 4; r++) acc[i][jq][r] = 0.0f;

    const int lrow = lid & 15;
    const int lkoff = (lid >> 4) * 16;

#define ISSUE(ST, KK)                                                         \
    {                                                                         \
        uint32_t stb = sbase + (ST) * STAGE_B;                                \
        _Pragma("unroll") for (int l = 0; l < 2; l++) {                       \
            int fid = tid + l * 256;                                          \
            int r = fid >> 2, q = fid & 3;                                    \
            uint32_t d0 = stb + (uint32_t)(r * APAD + q * 8) * 2;             \
            int grow = row0 + r;                                              \
            int asz = (grow < M) ? 16 : 0;                                    \
            size_t asrc = (size_t)(grow < M ? grow : 0) * 256 + (KK) + q * 8; \
            cp_async16(d0 + OFF_AH, g_Ah + asrc, asz);                        \
            cp_async16(d0 + OFF_AL, g_Al + asrc, asz);                        \
        }                                                                     \
        {                                                                     \
            int r = tid >> 2, q = tid & 3;                                    \
            uint32_t d0 = stb + (uint32_t)(r * APAD + q * 8) * 2;             \
            size_t bsrc = (size_t)(col0 + r) * 256 + (KK) + q * 8;            \
            cp_async16(d0 + OFF_BH, g_Bh + bsrc, 16);                         \
            cp_async16(d0 + OFF_BL, g_Bl + bsrc, 16);                         \
        }                                                                     \
        CP_COMMIT();                                                          \
    }

    ISSUE(0, 0)
    for (int kt = 0; kt < 8; kt++) {
        if (kt < 7) {
            ISSUE((kt + 1) & 1, (kt + 1) * 32)
            CP_WAIT1();
        } else {
            CP_WAIT0();
        }
        __syncthreads();

        uint32_t stb = sbase + (kt & 1) * STAGE_B;
#pragma unroll
        for (int k16 = 0; k16 < 32; k16 += 16) {
            uint32_t bh[4], bl[4];
            uint32_t boff = stb + OFF_BH +
                (uint32_t)((wn * 16 + lrow) * APAD + k16) * 2 + lkoff;
            ldsm4(bh[0], bh[1], bh[2], bh[3], boff);
            ldsm4(bl[0], bl[1], bl[2], bl[3], boff + (OFF_BL - OFF_BH));
#pragma unroll
            for (int mt = 0; mt < 4; mt++) {
                uint32_t aoff = stb + OFF_AH +
                    (uint32_t)((wm * 64 + mt * 16 + lrow) * APAD + k16) * 2 +
                    lkoff;
                uint32_t ah[4], al[4];
                ldsm4(ah[0], ah[1], ah[2], ah[3], aoff);
                ldsm4(al[0], al[1], al[2], al[3], aoff + (OFF_AL - OFF_AH));
#pragma unroll
                for (int jj = 0; jj < 2; jj++)
                    mma16816(acc[mt][jj], ah, bh[jj], bh[jj + 2]);
#pragma unroll
                for (int jj = 0; jj < 2; jj++)
                    mma16816(acc[mt][jj], ah, bl[jj], bl[jj + 2]);
#pragma unroll
                for (int jj = 0; jj < 2; jj++)
                    mma16816(acc[mt][jj], al, bh[jj], bh[jj + 2]);
            }
        }
        __syncthreads();
    }
#undef ISSUE

#pragma unroll
    for (int mt = 0; mt < 4; mt++) {
#pragma unroll
        for (int jj = 0; jj < 2; jj++) {
            int gcol = col0 + wn * 16 + jj * 8 + (lid & 3) * 2;
            float bx = 0.f, by = 0.f;
            if (gcol < 768) { bx = bias[gcol]; by = bias[gcol + 1]; }
            int r0g = row0 + wm * 64 + mt * 16 + (lid >> 2);
            if (r0g < M) {
                float2 o = make_float2(acc[mt][jj][0] + bx, acc[mt][jj][1] + by);
                *(float2*)(g_PQ + (size_t)r0g * 1536 + gcol) = o;
            }
            if (r0g + 8 < M) {
                float2 o = make_float2(acc[mt][jj][2] + bx, acc[mt][jj][3] + by);
                *(float2*)(g_PQ + (size_t)(r0g + 8) * 1536 + gcol) = o;
            }
        }
    }
}

// --------------------------------------------------------------- main ------
__global__ __launch_bounds__(256, 4)
void triplet_main_kernel(const float* __restrict__ pos,
                         const int* __restrict__ anchor_idx,
                         const int* __restrict__ corner_idx,
                         const int* __restrict__ masks,
                         float* __restrict__ out,
                         int N, int write_masks) {
    __shared__ __align__(16) __half qh[16][QP];
    __shared__ __align__(16) __half ql[16][QP];
    __shared__ __align__(16) __half kh[16][QP];
    __shared__ __align__(16) __half kl[16][QP];
    __shared__ __align__(16) float sSp[4][16][17];
    __shared__ __align__(16) float red[16][16];
    __shared__ __align__(16) u64 vp[2][128];
    __shared__ int ci0s[16], ci1s[16];
    __shared__ int tIdx[16];
    __shared__ float maskf[16], wsh[16];

    const int n = blockIdx.x;
    const int tid = threadIdx.x;
    const int cp = tid & 127;
    const int th = tid >> 7;
    const int wid = tid >> 5;
    const int lid = tid & 31;
    const int a_idx = anchor_idx[n];

    // ---- Phase 0: triplet geometry + table index (nearest) ----
    if (tid < 16) {
        int t = tid;
        float ax = 0.f, ay = 0.f;
        if (a_idx >= 0 && a_idx < N) {
            ax = pos[(size_t)a_idx * 3 + 0];
            ay = pos[(size_t)a_idx * 3 + 1];
        }
        int i0 = corner_idx[(size_t)n * 32 + 2 * t];
        int i1 = corner_idx[(size_t)n * 32 + 2 * t + 1];
        float p0x = 0.f, p0y = 0.f, p1x = 0.f, p1y = 0.f;
        if (i0 >= 0 && i0 < N) { p0x = pos[(size_t)i0 * 3]; p0y = pos[(size_t)i0 * 3 + 1]; }
        if (i1 >= 0 && i1 < N) { p1x = pos[(size_t)i1 * 3]; p1y = pos[(size_t)i1 * 3 + 1]; }
        float v0x = p0x - ax, v0y = p0y - ay;
        float v1x = p1x - ax, v1y = p1y - ay;
        float dot = v0x * v1x + v0y * v1y;
        float n0 = sqrtf(v0x * v0x + v0y * v0y);
        float n1 = sqrtf(v1x * v1x + v1y * v1y);
        float cosv = dot / (n0 * n1 + 1e-6f);
        float sinz = v0x * v1y - v0y * v1x;
        bool reorder = sinz < 0.0f;
        ci0s[t] = reorder ? i1 : i0;
        ci1s[t] = reorder ? i0 : i1;
        float s = (cosv + 1.0f) * (TAB_N * 0.5f);
        int ti = (int)floorf(s + 0.5f);
        if (ti < 0) ti = 0;
        if (ti > TAB_N) ti = TAB_N;
        tIdx[t] = ti;
        int mb = masks[(size_t)n * 16 + t];
        maskf[t] = (mb != 0) ? 1.0f : 0.0f;
        if (write_masks) {
            float newsin = reorder ? -sinz : sinz;
            out[(size_t)N * 512 + (size_t)n * 16 + t] =
                ((newsin < -1e-6f) && (mb != 0)) ? 1.0f : 0.0f;
        }
    }
    __syncthreads();

    // ---- Phase 1: gathers + NN table; stage q,k as fp16 hi/lo ----
    u64 v2[8];
#pragma unroll
    for (int tt = 0; tt < 8; tt++) {
        int t = 8 * th + tt;
        int i0 = ci0s[t]; if (i0 < 0 || i0 > N) i0 = N;
        int i1 = ci1s[t]; if (i1 < 0 || i1 > N) i1 = N;
        const float2* r0 = (const float2*)(g_PQ + (size_t)i0 * 1536);
        const float2* r1 = (const float2*)(g_PQ + (size_t)i1 * 1536 + 768);
        float2 pq = r0[cp],       qq = r1[cp];
        float2 pk = r0[128 + cp], qk = r1[128 + cp];
        float2 pv = r0[256 + cp], qv = r1[256 + cp];

        const __half2* T0 = (const __half2*)(g_TabH + (size_t)tIdx[t] * 768);
        float2 aq = __half22float2(T0[cp]);
        float2 ak = __half22float2(T0[128 + cp]);
        float2 av = __half22float2(T0[256 + cp]);

        float qx = pq.x + qq.x + aq.x;
        float qy = pq.y + qq.y + aq.y;
        float kx = pk.x + qk.x + ak.x;
        float ky = pk.y + qk.y + ak.y;
        float vx = pv.x + qv.x + av.x;
        float vy = pv.y + qv.y + av.y;

        __half qhx = __float2half(qx), qhy = __float2half(qy);
        __half khx = __float2half(kx), khy = __float2half(ky);
        *(__half2*)&qh[t][2 * cp] = __halves2half2(qhx, qhy);
        *(__half2*)&ql[t][2 * cp] = __halves2half2(
            __float2half(qx - __half2float(qhx)),
            __float2half(qy - __half2float(qhy)));
        *(__half2*)&kh[t][2 * cp] = __halves2half2(khx, khy);
        *(__half2*)&kl[t][2 * cp] = __halves2half2(
            __float2half(kx - __half2float(khx)),
            __float2half(ky - __half2float(khy)));
        v2[tt] = pack2(vx, vy);
    }
    __syncthreads();

    // ---- Phase 2: S = q k^T via split-fp16 mma, K split over warps 0-3 ----
    if (wid < 4) {
        const int lrow = lid & 15;
        const int lkoff = (lid >> 4) * 16;
        uint32_t qh_u = (uint32_t)__cvta_generic_to_shared(qh);
        uint32_t ql_u = (uint32_t)__cvta_generic_to_shared(ql);
        uint32_t kh_u = (uint32_t)__cvta_generic_to_shared(kh);
        uint32_t kl_u = (uint32_t)__cvta_generic_to_shared(kl);
        float acc[2][4];
#pragma unroll
        for (int jj = 0; jj < 2; jj++)
#pragma unroll
            for (int r = 0; r < 4; r++) acc[jj][r] = 0.0f;

        const int kbase = wid * 64;
#pragma unroll
        for (int kq = 0; kq < 64; kq += 16) {
            int k16 = kbase + kq;
            uint32_t off = (uint32_t)(lrow * QP + k16) * 2 + lkoff;
            uint32_t ah[4], al[4], bh[4], bl[4];
            ldsm4(ah[0], ah[1], ah[2], ah[3], qh_u + off);
            ldsm4(al[0], al[1], al[2], al[3], ql_u + off);
            ldsm4(bh[0], bh[1], bh[2], bh[3], kh_u + off);
            ldsm4(bl[0], bl[1], bl[2], bl[3], kl_u + off);
#pragma unroll
            for (int jj = 0; jj < 2; jj++)
                mma16816(acc[jj], ah, bh[jj], bh[jj + 2]);
#pragma unroll
            for (int jj = 0; jj < 2; jj++)
                mma16816(acc[jj], ah, bl[jj], bl[jj + 2]);
#pragma unroll
            for (int jj = 0; jj < 2; jj++)
                mma16816(acc[jj], al, bh[jj], bh[jj + 2]);
        }
        int r0 = lid >> 2;
        int c0 = (lid & 3) * 2;
#pragma unroll
        for (int jj = 0; jj < 2; jj++) {
            sSp[wid][r0][jj * 8 + c0] = acc[jj][0];
            sSp[wid][r0][jj * 8 + c0 + 1] = acc[jj][1];
            sSp[wid][r0 + 8][jj * 8 + c0] = acc[jj][2];
            sSp[wid][r0 + 8][jj * 8 + c0 + 1] = acc[jj][3];
        }
    }
    __syncthreads();

    // ---- Phase 3: softmax (sum the 4 K-partials first) ----
    {
        int aa = tid >> 4, bb = tid & 15;
        float sc = (sSp[0][aa][bb] + sSp[1][aa][bb] +
                    sSp[2][aa][bb] + sSp[3][aa][bb]) * 0.0625f;
        float mx = sc;
#pragma unroll
        for (int off = 8; off > 0; off >>= 1)
            mx = fmaxf(mx, __shfl_xor_sync(0xffffffffu, mx, off, 16));
        float e = expf(sc - mx);
        float sm = e;
#pragma unroll
        for (int off = 8; off > 0; off >>= 1)
            sm += __shfl_xor_sync(0xffffffffu, sm, off, 16);
        float attn = e / sm;
        red[aa][bb] = maskf[aa] * attn;
    }
    __syncthreads();

    // ---- Phase 4: fold mask-mean into per-k weights ----
    if (tid < 16) {
        float s = 0.0f, dn = 0.0f;
#pragma unroll
        for (int a2 = 0; a2 < 16; a2++) {
            s += red[a2][tid];
            dn += maskf[a2];
        }
        wsh[tid] = s / dn;
    }
    __syncthreads();

    // ---- Phase 5: mean over t, scatter ----
    {
        u64 part = pack2(0.f, 0.f);
#pragma unroll
        for (int tt = 0; tt < 8; tt++) {
            float w = wsh[8 * th + tt];
            part = ffma2(pack2(w, w), v2[tt], part);
        }
        vp[th][cp] = part;
        __syncthreads();
        if (th == 0) {
            u64 tot = fadd2(vp[0][cp], vp[1][cp]);
            if (a_idx >= 0 && a_idx < N) {
                float2 o;
                o.x = lo32(tot);
                o.y = hi32(tot);
                *(float2*)(out + (size_t)a_idx * 512 + 256 + 2 * cp) = o;
            }
        }
    }
}

// ----------------------------------------------------------------------------
extern "C" void kernel_launch(void* const* d_in, const int* in_sizes, int n_in,
                              void* d_out, int out_size) {
    if (n_in < 7) return;
    const float* x = (const float*)d_in[0];
    const float* pos = (const float*)d_in[1];
    const int* anchor = (const int*)d_in[2];
    const int* corner = (const int*)d_in[3];
    const int* masks = (const int*)d_in[4];
    const float* W = (const float*)d_in[5];
    const float* bias = (const float*)d_in[6];
    float* out = (float*)d_out;

    int N = in_sizes[0] / 256;
    if (N > MAXN) N = MAXN;
    int write_masks = (out_size >= N * 512 + N * 16) ? 1 : 0;

    cudaFuncSetAttribute(gemm_mma_kernel,
                         cudaFuncAttributeMaxDynamicSharedMemorySize,
                         GEMM_SMEM_B);

    const int prep_work = 64 * 768 + 1536 * 256 + 1536;
    prep_misc_kernel<<<(prep_work + 255) / 256, 256>>>(W, bias, N);

    int total4 = N * 64;
    fused_init_kernel<<<(total4 + 255) / 256, 256>>>(x, out, total4);

    dim3 tg((TAB_N + 64) / 64, 3);
    table_build_kernel<<<tg, 256>>>();

    dim3 gg(24, (N + 127) / 128);
    gemm_mma_kernel<<<gg, 256, GEMM_SMEM_B>>>(bias, N);

    triplet_main_kernel<<<N, 256>>>(pos, anchor, corner, masks, out, N, write_masks);
}

// round 13
// speedup vs baseline: 2.9931x; 1.0956x over previous
#include <cuda_runtime.h>
#include <cuda_fp16.h>
#include <math.h>
#include <stdint.h>
#include <stddef.h>

// ============================================================================
// TripletGNN:
//   qkv(n,t) = P[ci0] + Q[ci1] + g(cos_values(n,t))
//   g tabulated at 4097 points, nearest-neighbor.
//   [P|Q] = x @ Bh via 2-term split-fp16 mma.sync: (xh + xl) * Bh.
//   x recovered to 2^-22; only B carries fp16 quantization (~7e-5 rel).
//   16x16 scores via 3-term split-fp16 mma.sync, K split across 4 warps.
// ============================================================================

#define MAXN 40000
#define TAB_N 4096
#define APAD 40
#define QP 264

typedef unsigned long long u64;

__device__ float  g_PQ[(size_t)(MAXN + 1) * 1536];
__device__ float  g_WaT64[64 * 768];
__device__ __half g_TabH[(size_t)(TAB_N + 1) * 768];
__device__ __half g_Ah[(size_t)MAXN * 256];
__device__ __half g_Al[(size_t)MAXN * 256];
__device__ __half g_Bh[1536 * 256];

// ------------------------------------------------------------ f32x2 helpers -
__device__ __forceinline__ u64 ffma2(u64 a, u64 b, u64 c) {
    u64 d;
    asm("fma.rn.f32x2 %0, %1, %2, %3;" : "=l"(d) : "l"(a), "l"(b), "l"(c));
    return d;
}
__device__ __forceinline__ u64 fadd2(u64 a, u64 b) {
    u64 d;
    asm("add.rn.f32x2 %0, %1, %2;" : "=l"(d) : "l"(a), "l"(b));
    return d;
}
__device__ __forceinline__ u64 pack2(float lo, float hi) {
    u64 d;
    asm("mov.b64 %0, {%1, %2};" : "=l"(d) : "f"(lo), "f"(hi));
    return d;
}
__device__ __forceinline__ float lo32(u64 v) {
    return __uint_as_float((unsigned)(v & 0xffffffffull));
}
__device__ __forceinline__ float hi32(u64 v) {
    return __uint_as_float((unsigned)(v >> 32));
}

// ------------------------------------------------------------ mma helpers ---
__device__ __forceinline__ void ldsm4(uint32_t& r0, uint32_t& r1,
                                      uint32_t& r2, uint32_t& r3,
                                      uint32_t addr) {
    asm volatile("ldmatrix.sync.aligned.m8n8.x4.shared.b16 {%0,%1,%2,%3}, [%4];"
                 : "=r"(r0), "=r"(r1), "=r"(r2), "=r"(r3) : "r"(addr));
}
__device__ __forceinline__ void mma16816(float* d, const uint32_t* a,
                                         uint32_t b0, uint32_t b1) {
    asm volatile(
        "mma.sync.aligned.m16n8k16.row.col.f32.f16.f16.f32 "
        "{%0,%1,%2,%3}, {%4,%5,%6,%7}, {%8,%9}, {%0,%1,%2,%3};"
        : "+f"(d[0]), "+f"(d[1]), "+f"(d[2]), "+f"(d[3])
        : "r"(a[0]), "r"(a[1]), "r"(a[2]), "r"(a[3]), "r"(b0), "r"(b1));
}
__device__ __forceinline__ void cp_async16(uint32_t dst, const void* src,
                                           int src_bytes) {
    asm volatile("cp.async.cg.shared.global [%0], [%1], 16, %2;"
                 :: "r"(dst), "l"(src), "r"(src_bytes));
}
#define CP_COMMIT() asm volatile("cp.async.commit_group;" ::: "memory")
#define CP_WAIT1()  asm volatile("cp.async.wait_group 1;" ::: "memory")
#define CP_WAIT0()  asm volatile("cp.async.wait_group 0;" ::: "memory")

// ------------------------------------------------------------------- prep ---
__global__ void prep_misc_kernel(const float* __restrict__ W,
                                 const float* __restrict__ bias, int N) {
    int idx = blockIdx.x * blockDim.x + threadIdx.x;
    const int WA_SZ = 64 * 768;
    const int B_SZ = 1536 * 256;
    if (idx < WA_SZ) {
        int m = idx / 768, j = idx % 768;
        g_WaT64[idx] = W[j * 576 + 512 + m];
    } else if (idx < WA_SZ + B_SZ) {
        int r = idx - WA_SZ;
        int j = r >> 8, k = r & 255;
        float v = (j < 768) ? W[j * 576 + k] : W[(j - 768) * 576 + 256 + k];
        g_Bh[r] = __float2half(v);
    } else if (idx < WA_SZ + B_SZ + 1536) {
        int j = idx - (WA_SZ + B_SZ);
        g_PQ[(size_t)N * 1536 + j] = (j < 768) ? bias[j] : 0.0f;
    }
}

// Fused, float4-vectorized: x -> (Ah, Al) split; out[:,0:256]=x; [256:512]=0.
__global__ void fused_init_kernel(const float* __restrict__ x,
                                  float* __restrict__ out, int total4) {
    int idx = blockIdx.x * blockDim.x + threadIdx.x;
    if (idx < total4) {
        float4 v = *(const float4*)(x + idx * 4);
        __half h0 = __float2half(v.x), h1 = __float2half(v.y);
        __half h2 = __float2half(v.z), h3 = __float2half(v.w);
        __half2 hi01 = __halves2half2(h0, h1);
        __half2 hi23 = __halves2half2(h2, h3);
        __half2 lo01 = __halves2half2(__float2half(v.x - __half2float(h0)),
                                      __float2half(v.y - __half2float(h1)));
        __half2 lo23 = __halves2half2(__float2half(v.z - __half2float(h2)),
                                      __float2half(v.w - __half2float(h3)));
        *(uint2*)(g_Ah + idx * 4) =
            make_uint2(*(unsigned*)&hi01, *(unsigned*)&hi23);
        *(uint2*)(g_Al + idx * 4) =
            make_uint2(*(unsigned*)&lo01, *(unsigned*)&lo23);
        int r = idx >> 6, c4 = idx & 63;
        *(float4*)(out + (size_t)r * 512 + c4 * 4) = v;
        *(float4*)(out + (size_t)r * 512 + 256 + c4 * 4) =
            make_float4(0.f, 0.f, 0.f, 0.f);
    }
}

// --------------------------------------------------------- angle table ------
__global__ __launch_bounds__(256)
void table_build_kernel() {
    __shared__ float S[64][65];
    const int tid = threadIdx.x;
    const int e0 = blockIdx.x * 64;
    const int j = blockIdx.y * 256 + tid;

    for (int idx = tid; idx < 64 * 64; idx += 256) {
        int el = idx >> 6, m = idx & 63;
        int e = e0 + el;
        float val = 0.0f;
        if (e <= TAB_N) {
            int mp = m >> 1;
            float u = (float)e * (2.0f / TAB_N) - 1.0f;
            float om = u * expf(-0.28782313662425572f * (float)mp);
            float s, c;
            sincosf(om, &s, &c);
            val = (m & 1) ? c : s;
        }
        S[idx >> 6][m] = val;
    }
    __syncthreads();

    float acc[64];
#pragma unroll
    for (int el = 0; el < 64; el++) acc[el] = 0.0f;
#pragma unroll 8
    for (int m = 0; m < 64; m++) {
        float w = g_WaT64[m * 768 + j];
#pragma unroll
        for (int el = 0; el < 64; el++) acc[el] = fmaf(S[el][m], w, acc[el]);
    }
#pragma unroll
    for (int el = 0; el < 64; el++) {
        int e = e0 + el;
        if (e <= TAB_N) g_TabH[(size_t)e * 768 + j] = __float2half(acc[el]);
    }
}

// ------------------- cp.async double-buffered 2-term split-fp16 GEMM --------
// Tile: 128(M) x 128(N), K chunks of 32. Warps: 2(M) x 4(N), warp tile 64x32.
// Stage: [Ah 10240][Al 10240][Bh 10240] = 30720 B, 2 stages.
#define OFF_AH 0
#define OFF_AL 10240
#define OFF_BH 20480
#define STAGE_B 30720
#define GEMM_SMEM_B (2 * STAGE_B)

__global__ __launch_bounds__(256, 2)
void gemm_mma_kernel(const float* __restrict__ bias, int M) {
    extern __shared__ __half smem_h[];
    const int tid = threadIdx.x;
    const int wid = tid >> 5;
    const int lid = tid & 31;
    const int wm = wid >> 2;
    const int wn = wid & 3;
    const int row0 = blockIdx.y * 128;
    const int col0 = blockIdx.x * 128;
    uint32_t sbase = (uint32_t)__cvta_generic_to_shared(smem_h);

    float acc[4][4][4];
#pragma unroll
    for (int i = 0; i < 4; i++)
#pragma unroll
        for (int jq = 0; jq < 4; jq++)
#pragma unroll
            for (int r = 0; r < 4; r++) acc[i][jq][r] = 0.0f;

    const int lrow = lid & 15;
    const int lkoff = (lid >> 4) * 16;

#define ISSUE(ST, KK)                                                         \
    {                                                                         \
        uint32_t stb = sbase + (ST) * STAGE_B;                                \
        _Pragma("unroll") for (int l = 0; l < 2; l++) {                       \
            int fid = tid + l * 256;                                          \
            int r = fid >> 2, q = fid & 3;                                    \
            uint32_t d0 = stb + (uint32_t)(r * APAD + q * 8) * 2;             \
            int grow = row0 + r;                                              \
            int asz = (grow < M) ? 16 : 0;                                    \
            size_t asrc = (size_t)(grow < M ? grow : 0) * 256 + (KK) + q * 8; \
            cp_async16(d0 + OFF_AH, g_Ah + asrc, asz);                        \
            cp_async16(d0 + OFF_AL, g_Al + asrc, asz);                        \
            size_t bsrc = (size_t)(col0 + r) * 256 + (KK) + q * 8;            \
            cp_async16(d0 + OFF_BH, g_Bh + bsrc, 16);                         \
        }                                                                     \
        CP_COMMIT();                                                          \
    }

    ISSUE(0, 0)
    for (int kt = 0; kt < 8; kt++) {
        if (kt < 7) {
            ISSUE((kt + 1) & 1, (kt + 1) * 32)
            CP_WAIT1();
        } else {
            CP_WAIT0();
        }
        __syncthreads();

        uint32_t stb = sbase + (kt & 1) * STAGE_B;
#pragma unroll
        for (int k16 = 0; k16 < 32; k16 += 16) {
            uint32_t bh[2][4];
#pragma unroll
            for (int nt = 0; nt < 2; nt++) {
                uint32_t boff = stb + OFF_BH +
                    (uint32_t)((wn * 32 + nt * 16 + lrow) * APAD + k16) * 2 +
                    lkoff;
                ldsm4(bh[nt][0], bh[nt][1], bh[nt][2], bh[nt][3], boff);
            }
#pragma unroll
            for (int mt = 0; mt < 4; mt++) {
                uint32_t aoff = stb + OFF_AH +
                    (uint32_t)((wm * 64 + mt * 16 + lrow) * APAD + k16) * 2 +
                    lkoff;
                uint32_t ah[4], al[4];
                ldsm4(ah[0], ah[1], ah[2], ah[3], aoff);
                ldsm4(al[0], al[1], al[2], al[3], aoff + (OFF_AL - OFF_AH));
#pragma unroll
                for (int n = 0; n < 4; n++) {
                    int nt = n >> 1, jj = n & 1;
                    mma16816(acc[mt][n], ah, bh[nt][jj], bh[nt][jj + 2]);
                }
#pragma unroll
                for (int n = 0; n < 4; n++) {
                    int nt = n >> 1, jj = n & 1;
                    mma16816(acc[mt][n], al, bh[nt][jj], bh[nt][jj + 2]);
                }
            }
        }
        __syncthreads();
    }
#undef ISSUE

#pragma unroll
    for (int mt = 0; mt < 4; mt++) {
#pragma unroll
        for (int n = 0; n < 4; n++) {
            int gcol = col0 + wn * 32 + (n >> 1) * 16 + (n & 1) * 8 +
                       (lid & 3) * 2;
            float bx = 0.f, by = 0.f;
            if (gcol < 768) { bx = bias[gcol]; by = bias[gcol + 1]; }
            int r0g = row0 + wm * 64 + mt * 16 + (lid >> 2);
            if (r0g < M) {
                float2 o = make_float2(acc[mt][n][0] + bx, acc[mt][n][1] + by);
                *(float2*)(g_PQ + (size_t)r0g * 1536 + gcol) = o;
            }
            if (r0g + 8 < M) {
                float2 o = make_float2(acc[mt][n][2] + bx, acc[mt][n][3] + by);
                *(float2*)(g_PQ + (size_t)(r0g + 8) * 1536 + gcol) = o;
            }
        }
    }
}

// --------------------------------------------------------------- main ------
__global__ __launch_bounds__(256, 4)
void triplet_main_kernel(const float* __restrict__ pos,
                         const int* __restrict__ anchor_idx,
                         const int* __restrict__ corner_idx,
                         const int* __restrict__ masks,
                         float* __restrict__ out,
                         int N, int write_masks) {
    __shared__ __align__(16) __half qh[16][QP];
    __shared__ __align__(16) __half ql[16][QP];
    __shared__ __align__(16) __half kh[16][QP];
    __shared__ __align__(16) __half kl[16][QP];
    __shared__ __align__(16) float sSp[4][16][17];
    __shared__ __align__(16) float red[16][16];
    __shared__ __align__(16) u64 vp[2][128];
    __shared__ int ci0s[16], ci1s[16];
    __shared__ int tIdx[16];
    __shared__ float maskf[16], wsh[16];

    const int n = blockIdx.x;
    const int tid = threadIdx.x;
    const int cp = tid & 127;
    const int th = tid >> 7;
    const int wid = tid >> 5;
    const int lid = tid & 31;
    const int a_idx = anchor_idx[n];

    // ---- Phase 0: triplet geometry + table index (nearest) ----
    if (tid < 16) {
        int t = tid;
        float ax = 0.f, ay = 0.f;
        if (a_idx >= 0 && a_idx < N) {
            ax = pos[(size_t)a_idx * 3 + 0];
            ay = pos[(size_t)a_idx * 3 + 1];
        }
        int i0 = corner_idx[(size_t)n * 32 + 2 * t];
        int i1 = corner_idx[(size_t)n * 32 + 2 * t + 1];
        float p0x = 0.f, p0y = 0.f, p1x = 0.f, p1y = 0.f;
        if (i0 >= 0 && i0 < N) { p0x = pos[(size_t)i0 * 3]; p0y = pos[(size_t)i0 * 3 + 1]; }
        if (i1 >= 0 && i1 < N) { p1x = pos[(size_t)i1 * 3]; p1y = pos[(size_t)i1 * 3 + 1]; }
        float v0x = p0x - ax, v0y = p0y - ay;
        float v1x = p1x - ax, v1y = p1y - ay;
        float dot = v0x * v1x + v0y * v1y;
        float n0 = sqrtf(v0x * v0x + v0y * v0y);
        float n1 = sqrtf(v1x * v1x + v1y * v1y);
        float cosv = dot / (n0 * n1 + 1e-6f);
        float sinz = v0x * v1y - v0y * v1x;
        bool reorder = sinz < 0.0f;
        ci0s[t] = reorder ? i1 : i0;
        ci1s[t] = reorder ? i0 : i1;
        float s = (cosv + 1.0f) * (TAB_N * 0.5f);
        int ti = (int)floorf(s + 0.5f);
        if (ti < 0) ti = 0;
        if (ti > TAB_N) ti = TAB_N;
        tIdx[t] = ti;
        int mb = masks[(size_t)n * 16 + t];
        maskf[t] = (mb != 0) ? 1.0f : 0.0f;
        if (write_masks) {
            float newsin = reorder ? -sinz : sinz;
            out[(size_t)N * 512 + (size_t)n * 16 + t] =
                ((newsin < -1e-6f) && (mb != 0)) ? 1.0f : 0.0f;
        }
    }
    __syncthreads();

    // ---- Phase 1: gathers + NN table; stage q,k as fp16 hi/lo ----
    u64 v2[8];
#pragma unroll
    for (int tt = 0; tt < 8; tt++) {
        int t = 8 * th + tt;
        int i0 = ci0s[t]; if (i0 < 0 || i0 > N) i0 = N;
        int i1 = ci1s[t]; if (i1 < 0 || i1 > N) i1 = N;
        const float2* r0 = (const float2*)(g_PQ + (size_t)i0 * 1536);
        const float2* r1 = (const float2*)(g_PQ + (size_t)i1 * 1536 + 768);
        float2 pq = r0[cp],       qq = r1[cp];
        float2 pk = r0[128 + cp], qk = r1[128 + cp];
        float2 pv = r0[256 + cp], qv = r1[256 + cp];

        const __half2* T0 = (const __half2*)(g_TabH + (size_t)tIdx[t] * 768);
        float2 aq = __half22float2(T0[cp]);
        float2 ak = __half22float2(T0[128 + cp]);
        float2 av = __half22float2(T0[256 + cp]);

        float qx = pq.x + qq.x + aq.x;
        float qy = pq.y + qq.y + aq.y;
        float kx = pk.x + qk.x + ak.x;
        float ky = pk.y + qk.y + ak.y;
        float vx = pv.x + qv.x + av.x;
        float vy = pv.y + qv.y + av.y;

        __half qhx = __float2half(qx), qhy = __float2half(qy);
        __half khx = __float2half(kx), khy = __float2half(ky);
        *(__half2*)&qh[t][2 * cp] = __halves2half2(qhx, qhy);
        *(__half2*)&ql[t][2 * cp] = __halves2half2(
            __float2half(qx - __half2float(qhx)),
            __float2half(qy - __half2float(qhy)));
        *(__half2*)&kh[t][2 * cp] = __halves2half2(khx, khy);
        *(__half2*)&kl[t][2 * cp] = __halves2half2(
            __float2half(kx - __half2float(khx)),
            __float2half(ky - __half2float(khy)));
        v2[tt] = pack2(vx, vy);
    }
    __syncthreads();

    // ---- Phase 2: S = q k^T via split-fp16 mma, K split over warps 0-3 ----
    if (wid < 4) {
        const int lrow = lid & 15;
        const int lkoff = (lid >> 4) * 16;
        uint32_t qh_u = (uint32_t)__cvta_generic_to_shared(qh);
        uint32_t ql_u = (uint32_t)__cvta_generic_to_shared(ql);
        uint32_t kh_u = (uint32_t)__cvta_generic_to_shared(kh);
        uint32_t kl_u = (uint32_t)__cvta_generic_to_shared(kl);
        float acc[2][4];
#pragma unroll
        for (int jj = 0; jj < 2; jj++)
#pragma unroll
            for (int r = 0; r < 4; r++) acc[jj][r] = 0.0f;

        const int kbase = wid * 64;
#pragma unroll
        for (int kq = 0; kq < 64; kq += 16) {
            int k16 = kbase + kq;
            uint32_t off = (uint32_t)(lrow * QP + k16) * 2 + lkoff;
            uint32_t ah[4], al[4], bh[4], bl[4];
            ldsm4(ah[0], ah[1], ah[2], ah[3], qh_u + off);
            ldsm4(al[0], al[1], al[2], al[3], ql_u + off);
            ldsm4(bh[0], bh[1], bh[2], bh[3], kh_u + off);
            ldsm4(bl[0], bl[1], bl[2], bl[3], kl_u + off);
#pragma unroll
            for (int jj = 0; jj < 2; jj++)
                mma16816(acc[jj], ah, bh[jj], bh[jj + 2]);
#pragma unroll
            for (int jj = 0; jj < 2; jj++)
                mma16816(acc[jj], ah, bl[jj], bl[jj + 2]);
#pragma unroll
            for (int jj = 0; jj < 2; jj++)
                mma16816(acc[jj], al, bh[jj], bh[jj + 2]);
        }
        int r0 = lid >> 2;
        int c0 = (lid & 3) * 2;
#pragma unroll
        for (int jj = 0; jj < 2; jj++) {
            sSp[wid][r0][jj * 8 + c0] = acc[jj][0];
            sSp[wid][r0][jj * 8 + c0 + 1] = acc[jj][1];
            sSp[wid][r0 + 8][jj * 8 + c0] = acc[jj][2];
            sSp[wid][r0 + 8][jj * 8 + c0 + 1] = acc[jj][3];
        }
    }
    __syncthreads();

    // ---- Phase 3: softmax (sum the 4 K-partials first) ----
    {
        int aa = tid >> 4, bb = tid & 15;
        float sc = (sSp[0][aa][bb] + sSp[1][aa][bb] +
                    sSp[2][aa][bb] + sSp[3][aa][bb]) * 0.0625f;
        float mx = sc;
#pragma unroll
        for (int off = 8; off > 0; off >>= 1)
            mx = fmaxf(mx, __shfl_xor_sync(0xffffffffu, mx, off, 16));
        float e = expf(sc - mx);
        float sm = e;
#pragma unroll
        for (int off = 8; off > 0; off >>= 1)
            sm += __shfl_xor_sync(0xffffffffu, sm, off, 16);
        float attn = e / sm;
        red[aa][bb] = maskf[aa] * attn;
    }
    __syncthreads();

    // ---- Phase 4: fold mask-mean into per-k weights ----
    if (tid < 16) {
        float s = 0.0f, dn = 0.0f;
#pragma unroll
        for (int a2 = 0; a2 < 16; a2++) {
            s += red[a2][tid];
            dn += maskf[a2];
        }
        wsh[tid] = s / dn;
    }
    __syncthreads();

    // ---- Phase 5: mean over t, scatter ----
    {
        u64 part = pack2(0.f, 0.f);
#pragma unroll
        for (int tt = 0; tt < 8; tt++) {
            float w = wsh[8 * th + tt];
            part = ffma2(pack2(w, w), v2[tt], part);
        }
        vp[th][cp] = part;
        __syncthreads();
        if (th == 0) {
            u64 tot = fadd2(vp[0][cp], vp[1][cp]);
            if (a_idx >= 0 && a_idx < N) {
                float2 o;
                o.x = lo32(tot);
                o.y = hi32(tot);
                *(float2*)(out + (size_t)a_idx * 512 + 256 + 2 * cp) = o;
            }
        }
    }
}

// ----------------------------------------------------------------------------
extern "C" void kernel_launch(void* const* d_in, const int* in_sizes, int n_in,
                              void* d_out, int out_size) {
    if (n_in < 7) return;
    const float* x = (const float*)d_in[0];
    const float* pos = (const float*)d_in[1];
    const int* anchor = (const int*)d_in[2];
    const int* corner = (const int*)d_in[3];
    const int* masks = (const int*)d_in[4];
    const float* W = (const float*)d_in[5];
    const float* bias = (const float*)d_in[6];
    float* out = (float*)d_out;

    int N = in_sizes[0] / 256;
    if (N > MAXN) N = MAXN;
    int write_masks = (out_size >= N * 512 + N * 16) ? 1 : 0;

    cudaFuncSetAttribute(gemm_mma_kernel,
                         cudaFuncAttributeMaxDynamicSharedMemorySize,
                         GEMM_SMEM_B);

    const int prep_work = 64 * 768 + 1536 * 256 + 1536;
    prep_misc_kernel<<<(prep_work + 255) / 256, 256>>>(W, bias, N);

    int total4 = N * 64;
    fused_init_kernel<<<(total4 + 255) / 256, 256>>>(x, out, total4);

    dim3 tg((TAB_N + 64) / 64, 3);
    table_build_kernel<<<tg, 256>>>();

    dim3 gg(12, (N + 127) / 128);
    gemm_mma_kernel<<<gg, 256, GEMM_SMEM_B>>>(bias, N);

    triplet_main_kernel<<<N, 256>>>(pos, anchor, corner, masks, out, N, write_masks);
}

// round 14
// speedup vs baseline: 3.4634x; 1.1571x over previous
#include <cuda_runtime.h>
#include <cuda_fp16.h>
#include <math.h>
#include <stdint.h>
#include <stddef.h>

// ============================================================================
// TripletGNN:
//   qkv(n,t) = P[ci0] + Q[ci1] + g(cos_values(n,t))
//   g tabulated at 4097 points, nearest-neighbor, fp16.
//   [P|Q] = x @ Bh via 2-term split-fp16 mma.sync: (xh + xl) * Bh.
//   PQ stored fp16 (quantized once after fp32 accumulation) -> gather bytes /2.
//   16x16 scores via 3-term split-fp16 mma.sync, K split across 4 warps.
// ============================================================================

#define MAXN 40000
#define TAB_N 4096
#define APAD 40
#define QP 264

typedef unsigned long long u64;

__device__ __half g_PQh[(size_t)(MAXN + 1) * 1536];
__device__ float  g_WaT64[64 * 768];
__device__ __half g_TabH[(size_t)(TAB_N + 1) * 768];
__device__ __half g_Ah[(size_t)MAXN * 256];
__device__ __half g_Al[(size_t)MAXN * 256];
__device__ __half g_Bh[1536 * 256];

// ------------------------------------------------------------ f32x2 helpers -
__device__ __forceinline__ u64 ffma2(u64 a, u64 b, u64 c) {
    u64 d;
    asm("fma.rn.f32x2 %0, %1, %2, %3;" : "=l"(d) : "l"(a), "l"(b), "l"(c));
    return d;
}
__device__ __forceinline__ u64 fadd2(u64 a, u64 b) {
    u64 d;
    asm("add.rn.f32x2 %0, %1, %2;" : "=l"(d) : "l"(a), "l"(b));
    return d;
}
__device__ __forceinline__ u64 pack2(float lo, float hi) {
    u64 d;
    asm("mov.b64 %0, {%1, %2};" : "=l"(d) : "f"(lo), "f"(hi));
    return d;
}
__device__ __forceinline__ float lo32(u64 v) {
    return __uint_as_float((unsigned)(v & 0xffffffffull));
}
__device__ __forceinline__ float hi32(u64 v) {
    return __uint_as_float((unsigned)(v >> 32));
}

// ------------------------------------------------------------ mma helpers ---
__device__ __forceinline__ void ldsm4(uint32_t& r0, uint32_t& r1,
                                      uint32_t& r2, uint32_t& r3,
                                      uint32_t addr) {
    asm volatile("ldmatrix.sync.aligned.m8n8.x4.shared.b16 {%0,%1,%2,%3}, [%4];"
                 : "=r"(r0), "=r"(r1), "=r"(r2), "=r"(r3) : "r"(addr));
}
__device__ __forceinline__ void mma16816(float* d, const uint32_t* a,
                                         uint32_t b0, uint32_t b1) {
    asm volatile(
        "mma.sync.aligned.m16n8k16.row.col.f32.f16.f16.f32 "
        "{%0,%1,%2,%3}, {%4,%5,%6,%7}, {%8,%9}, {%0,%1,%2,%3};"
        : "+f"(d[0]), "+f"(d[1]), "+f"(d[2]), "+f"(d[3])
        : "r"(a[0]), "r"(a[1]), "r"(a[2]), "r"(a[3]), "r"(b0), "r"(b1));
}
__device__ __forceinline__ void cp_async16(uint32_t dst, const void* src,
                                           int src_bytes) {
    asm volatile("cp.async.cg.shared.global [%0], [%1], 16, %2;"
                 :: "r"(dst), "l"(src), "r"(src_bytes));
}
#define CP_COMMIT() asm volatile("cp.async.commit_group;" ::: "memory")
#define CP_WAIT2()  asm volatile("cp.async.wait_group 2;" ::: "memory")
#define CP_WAIT0()  asm volatile("cp.async.wait_group 0;" ::: "memory")

// ------------------------------------------------------------------- prep ---
__global__ void prep_misc_kernel(const float* __restrict__ W,
                                 const float* __restrict__ bias, int N) {
    int idx = blockIdx.x * blockDim.x + threadIdx.x;
    const int WA_SZ = 64 * 768;
    const int B_SZ = 1536 * 256;
    if (idx < WA_SZ) {
        int m = idx / 768, j = idx % 768;
        g_WaT64[idx] = W[j * 576 + 512 + m];
    } else if (idx < WA_SZ + B_SZ) {
        int r = idx - WA_SZ;
        int j = r >> 8, k = r & 255;
        float v = (j < 768) ? W[j * 576 + k] : W[(j - 768) * 576 + 256 + k];
        g_Bh[r] = __float2half(v);
    } else if (idx < WA_SZ + B_SZ + 1536) {
        int j = idx - (WA_SZ + B_SZ);
        g_PQh[(size_t)N * 1536 + j] =
            __float2half((j < 768) ? bias[j] : 0.0f);
    }
}

// Fused, float4-vectorized: x -> (Ah, Al) split; out[:,0:256]=x; [256:512]=0.
__global__ void fused_init_kernel(const float* __restrict__ x,
                                  float* __restrict__ out, int total4) {
    int idx = blockIdx.x * blockDim.x + threadIdx.x;
    if (idx < total4) {
        float4 v = *(const float4*)(x + idx * 4);
        __half h0 = __float2half(v.x), h1 = __float2half(v.y);
        __half h2 = __float2half(v.z), h3 = __float2half(v.w);
        __half2 hi01 = __halves2half2(h0, h1);
        __half2 hi23 = __halves2half2(h2, h3);
        __half2 lo01 = __halves2half2(__float2half(v.x - __half2float(h0)),
                                      __float2half(v.y - __half2float(h1)));
        __half2 lo23 = __halves2half2(__float2half(v.z - __half2float(h2)),
                                      __float2half(v.w - __half2float(h3)));
        *(uint2*)(g_Ah + idx * 4) =
            make_uint2(*(unsigned*)&hi01, *(unsigned*)&hi23);
        *(uint2*)(g_Al + idx * 4) =
            make_uint2(*(unsigned*)&lo01, *(unsigned*)&lo23);
        int r = idx >> 6, c4 = idx & 63;
        *(float4*)(out + (size_t)r * 512 + c4 * 4) = v;
        *(float4*)(out + (size_t)r * 512 + 256 + c4 * 4) =
            make_float4(0.f, 0.f, 0.f, 0.f);
    }
}

// --------------------------------------------------------- angle table ------
__global__ __launch_bounds__(256)
void table_build_kernel() {
    __shared__ float S[64][65];
    const int tid = threadIdx.x;
    const int e0 = blockIdx.x * 64;
    const int j = blockIdx.y * 256 + tid;

    for (int idx = tid; idx < 64 * 64; idx += 256) {
        int el = idx >> 6, m = idx & 63;
        int e = e0 + el;
        float val = 0.0f;
        if (e <= TAB_N) {
            int mp = m >> 1;
            float u = (float)e * (2.0f / TAB_N) - 1.0f;
            float om = u * expf(-0.28782313662425572f * (float)mp);
            float s, c;
            sincosf(om, &s, &c);
            val = (m & 1) ? c : s;
        }
        S[idx >> 6][m] = val;
    }
    __syncthreads();

    float acc[64];
#pragma unroll
    for (int el = 0; el < 64; el++) acc[el] = 0.0f;
#pragma unroll 8
    for (int m = 0; m < 64; m++) {
        float w = g_WaT64[m * 768 + j];
#pragma unroll
        for (int el = 0; el < 64; el++) acc[el] = fmaf(S[el][m], w, acc[el]);
    }
#pragma unroll
    for (int el = 0; el < 64; el++) {
        int e = e0 + el;
        if (e <= TAB_N) g_TabH[(size_t)e * 768 + j] = __float2half(acc[el]);
    }
}

// ------------------- cp.async 3-stage 2-term split-fp16 GEMM ----------------
// Tile: 128(M) x 128(N), K chunks of 32. Warps: 2(M) x 4(N), warp tile 64x32.
// Stage: [Ah 10240][Al 10240][Bh 10240] = 30720 B, 3 stages.
#define OFF_AH 0
#define OFF_AL 10240
#define OFF_BH 20480
#define STAGE_B 30720
#define GEMM_SMEM_B (3 * STAGE_B)

__global__ __launch_bounds__(256, 2)
void gemm_mma_kernel(const float* __restrict__ bias, int M) {
    extern __shared__ __half smem_h[];
    const int tid = threadIdx.x;
    const int wid = tid >> 5;
    const int lid = tid & 31;
    const int wm = wid >> 2;
    const int wn = wid & 3;
    const int row0 = blockIdx.y * 128;
    const int col0 = blockIdx.x * 128;
    uint32_t sbase = (uint32_t)__cvta_generic_to_shared(smem_h);

    float acc[4][4][4];
#pragma unroll
    for (int i = 0; i < 4; i++)
#pragma unroll
        for (int jq = 0; jq < 4; jq++)
#pragma unroll
            for (int r = 0; r < 4; r++) acc[i][jq][r] = 0.0f;

    const int lrow = lid & 15;
    const int lkoff = (lid >> 4) * 16;

#define ISSUE(ST, KK)                                                         \
    {                                                                         \
        uint32_t stb = sbase + (ST) * STAGE_B;                                \
        _Pragma("unroll") for (int l = 0; l < 2; l++) {                       \
            int fid = tid + l * 256;                                          \
            int r = fid >> 2, q = fid & 3;                                    \
            uint32_t d0 = stb + (uint32_t)(r * APAD + q * 8) * 2;             \
            int grow = row0 + r;                                              \
            int asz = (grow < M) ? 16 : 0;                                    \
            size_t asrc = (size_t)(grow < M ? grow : 0) * 256 + (KK) + q * 8; \
            cp_async16(d0 + OFF_AH, g_Ah + asrc, asz);                        \
            cp_async16(d0 + OFF_AL, g_Al + asrc, asz);                        \
            size_t bsrc = (size_t)(col0 + r) * 256 + (KK) + q * 8;            \
            cp_async16(d0 + OFF_BH, g_Bh + bsrc, 16);                         \
        }                                                                     \
        CP_COMMIT();                                                          \
    }

    ISSUE(0, 0)
    ISSUE(1, 32)
    for (int kt = 0; kt < 8; kt++) {
        if (kt < 6) {
            ISSUE((kt + 2) % 3, (kt + 2) * 32)
            CP_WAIT2();
        } else {
            CP_WAIT0();
        }
        __syncthreads();

        uint32_t stb = sbase + (kt % 3) * STAGE_B;
#pragma unroll
        for (int k16 = 0; k16 < 32; k16 += 16) {
            uint32_t bh[2][4];
#pragma unroll
            for (int nt = 0; nt < 2; nt++) {
                uint32_t boff = stb + OFF_BH +
                    (uint32_t)((wn * 32 + nt * 16 + lrow) * APAD + k16) * 2 +
                    lkoff;
                ldsm4(bh[nt][0], bh[nt][1], bh[nt][2], bh[nt][3], boff);
            }
#pragma unroll
            for (int mt = 0; mt < 4; mt++) {
                uint32_t aoff = stb + OFF_AH +
                    (uint32_t)((wm * 64 + mt * 16 + lrow) * APAD + k16) * 2 +
                    lkoff;
                uint32_t ah[4], al[4];
                ldsm4(ah[0], ah[1], ah[2], ah[3], aoff);
                ldsm4(al[0], al[1], al[2], al[3], aoff + (OFF_AL - OFF_AH));
#pragma unroll
                for (int n = 0; n < 4; n++) {
                    int nt = n >> 1, jj = n & 1;
                    mma16816(acc[mt][n], ah, bh[nt][jj], bh[nt][jj + 2]);
                }
#pragma unroll
                for (int n = 0; n < 4; n++) {
                    int nt = n >> 1, jj = n & 1;
                    mma16816(acc[mt][n], al, bh[nt][jj], bh[nt][jj + 2]);
                }
            }
        }
        __syncthreads();
    }
#undef ISSUE

    // Epilogue: +bias (fp32), quantize to fp16, store __half2.
#pragma unroll
    for (int mt = 0; mt < 4; mt++) {
#pragma unroll
        for (int n = 0; n < 4; n++) {
            int gcol = col0 + wn * 32 + (n >> 1) * 16 + (n & 1) * 8 +
                       (lid & 3) * 2;
            float bx = 0.f, by = 0.f;
            if (gcol < 768) { bx = bias[gcol]; by = bias[gcol + 1]; }
            int r0g = row0 + wm * 64 + mt * 16 + (lid >> 2);
            if (r0g < M) {
                __half2 o = __halves2half2(__float2half(acc[mt][n][0] + bx),
                                           __float2half(acc[mt][n][1] + by));
                *(__half2*)(g_PQh + (size_t)r0g * 1536 + gcol) = o;
            }
            if (r0g + 8 < M) {
                __half2 o = __halves2half2(__float2half(acc[mt][n][2] + bx),
                                           __float2half(acc[mt][n][3] + by));
                *(__half2*)(g_PQh + (size_t)(r0g + 8) * 1536 + gcol) = o;
            }
        }
    }
}

// --------------------------------------------------------------- main ------
__global__ __launch_bounds__(256, 4)
void triplet_main_kernel(const float* __restrict__ pos,
                         const int* __restrict__ anchor_idx,
                         const int* __restrict__ corner_idx,
                         const int* __restrict__ masks,
                         float* __restrict__ out,
                         int N, int write_masks) {
    __shared__ __align__(16) __half qh[16][QP];
    __shared__ __align__(16) __half ql[16][QP];
    __shared__ __align__(16) __half kh[16][QP];
    __shared__ __align__(16) __half kl[16][QP];
    __shared__ __align__(16) float sSp[4][16][17];
    __shared__ __align__(16) float red[16][16];
    __shared__ __align__(16) u64 vp[2][128];
    __shared__ int ci0s[16], ci1s[16];
    __shared__ int tIdx[16];
    __shared__ float maskf[16], wsh[16];

    const int n = blockIdx.x;
    const int tid = threadIdx.x;
    const int cp = tid & 127;
    const int th = tid >> 7;
    const int wid = tid >> 5;
    const int lid = tid & 31;
    const int a_idx = anchor_idx[n];

    // ---- Phase 0: triplet geometry + table index (nearest) ----
    if (tid < 16) {
        int t = tid;
        float ax = 0.f, ay = 0.f;
        if (a_idx >= 0 && a_idx < N) {
            ax = pos[(size_t)a_idx * 3 + 0];
            ay = pos[(size_t)a_idx * 3 + 1];
        }
        int i0 = corner_idx[(size_t)n * 32 + 2 * t];
        int i1 = corner_idx[(size_t)n * 32 + 2 * t + 1];
        float p0x = 0.f, p0y = 0.f, p1x = 0.f, p1y = 0.f;
        if (i0 >= 0 && i0 < N) { p0x = pos[(size_t)i0 * 3]; p0y = pos[(size_t)i0 * 3 + 1]; }
        if (i1 >= 0 && i1 < N) { p1x = pos[(size_t)i1 * 3]; p1y = pos[(size_t)i1 * 3 + 1]; }
        float v0x = p0x - ax, v0y = p0y - ay;
        float v1x = p1x - ax, v1y = p1y - ay;
        float dot = v0x * v1x + v0y * v1y;
        float n0 = sqrtf(v0x * v0x + v0y * v0y);
        float n1 = sqrtf(v1x * v1x + v1y * v1y);
        float cosv = dot / (n0 * n1 + 1e-6f);
        float sinz = v0x * v1y - v0y * v1x;
        bool reorder = sinz < 0.0f;
        ci0s[t] = reorder ? i1 : i0;
        ci1s[t] = reorder ? i0 : i1;
        float s = (cosv + 1.0f) * (TAB_N * 0.5f);
        int ti = (int)floorf(s + 0.5f);
        if (ti < 0) ti = 0;
        if (ti > TAB_N) ti = TAB_N;
        tIdx[t] = ti;
        int mb = masks[(size_t)n * 16 + t];
        maskf[t] = (mb != 0) ? 1.0f : 0.0f;
        if (write_masks) {
            float newsin = reorder ? -sinz : sinz;
            out[(size_t)N * 512 + (size_t)n * 16 + t] =
                ((newsin < -1e-6f) && (mb != 0)) ? 1.0f : 0.0f;
        }
    }
    __syncthreads();

    // ---- Phase 1: fp16 gathers + NN table; stage q,k as fp16 hi/lo ----
    u64 v2[8];
#pragma unroll
    for (int tt = 0; tt < 8; tt++) {
        int t = 8 * th + tt;
        int i0 = ci0s[t]; if (i0 < 0 || i0 > N) i0 = N;
        int i1 = ci1s[t]; if (i1 < 0 || i1 > N) i1 = N;
        const __half2* r0 = (const __half2*)(g_PQh + (size_t)i0 * 1536);
        const __half2* r1 = (const __half2*)(g_PQh + (size_t)i1 * 1536 + 768);
        float2 pq = __half22float2(r0[cp]);
        float2 qq = __half22float2(r1[cp]);
        float2 pk = __half22float2(r0[128 + cp]);
        float2 qk = __half22float2(r1[128 + cp]);
        float2 pv = __half22float2(r0[256 + cp]);
        float2 qv = __half22float2(r1[256 + cp]);

        const __half2* T0 = (const __half2*)(g_TabH + (size_t)tIdx[t] * 768);
        float2 aq = __half22float2(T0[cp]);
        float2 ak = __half22float2(T0[128 + cp]);
        float2 av = __half22float2(T0[256 + cp]);

        float qx = pq.x + qq.x + aq.x;
        float qy = pq.y + qq.y + aq.y;
        float kx = pk.x + qk.x + ak.x;
        float ky = pk.y + qk.y + ak.y;
        float vx = pv.x + qv.x + av.x;
        float vy = pv.y + qv.y + av.y;

        __half qhx = __float2half(qx), qhy = __float2half(qy);
        __half khx = __float2half(kx), khy = __float2half(ky);
        *(__half2*)&qh[t][2 * cp] = __halves2half2(qhx, qhy);
        *(__half2*)&ql[t][2 * cp] = __halves2half2(
            __float2half(qx - __half2float(qhx)),
            __float2half(qy - __half2float(qhy)));
        *(__half2*)&kh[t][2 * cp] = __halves2half2(khx, khy);
        *(__half2*)&kl[t][2 * cp] = __halves2half2(
            __float2half(kx - __half2float(khx)),
            __float2half(ky - __half2float(khy)));
        v2[tt] = pack2(vx, vy);
    }
    __syncthreads();

    // ---- Phase 2: S = q k^T via split-fp16 mma, K split over warps 0-3 ----
    if (wid < 4) {
        const int lrow = lid & 15;
        const int lkoff = (lid >> 4) * 16;
        uint32_t qh_u = (uint32_t)__cvta_generic_to_shared(qh);
        uint32_t ql_u = (uint32_t)__cvta_generic_to_shared(ql);
        uint32_t kh_u = (uint32_t)__cvta_generic_to_shared(kh);
        uint32_t kl_u = (uint32_t)__cvta_generic_to_shared(kl);
        float acc[2][4];
#pragma unroll
        for (int jj = 0; jj < 2; jj++)
#pragma unroll
            for (int r = 0; r < 4; r++) acc[jj][r] = 0.0f;

        const int kbase = wid * 64;
#pragma unroll
        for (int kq = 0; kq < 64; kq += 16) {
            int k16 = kbase + kq;
            uint32_t off = (uint32_t)(lrow * QP + k16) * 2 + lkoff;
            uint32_t ah[4], al[4], bh[4], bl[4];
            ldsm4(ah[0], ah[1], ah[2], ah[3], qh_u + off);
            ldsm4(al[0], al[1], al[2], al[3], ql_u + off);
            ldsm4(bh[0], bh[1], bh[2], bh[3], kh_u + off);
            ldsm4(bl[0], bl[1], bl[2], bl[3], kl_u + off);
#pragma unroll
            for (int jj = 0; jj < 2; jj++)
                mma16816(acc[jj], ah, bh[jj], bh[jj + 2]);
#pragma unroll
            for (int jj = 0; jj < 2; jj++)
                mma16816(acc[jj], ah, bl[jj], bl[jj + 2]);
#pragma unroll
            for (int jj = 0; jj < 2; jj++)
                mma16816(acc[jj], al, bh[jj], bh[jj + 2]);
        }
        int r0 = lid >> 2;
        int c0 = (lid & 3) * 2;
#pragma unroll
        for (int jj = 0; jj < 2; jj++) {
            sSp[wid][r0][jj * 8 + c0] = acc[jj][0];
            sSp[wid][r0][jj * 8 + c0 + 1] = acc[jj][1];
            sSp[wid][r0 + 8][jj * 8 + c0] = acc[jj][2];
            sSp[wid][r0 + 8][jj * 8 + c0 + 1] = acc[jj][3];
        }
    }
    __syncthreads();

    // ---- Phase 3: softmax (sum the 4 K-partials first) ----
    {
        int aa = tid >> 4, bb = tid & 15;
        float sc = (sSp[0][aa][bb] + sSp[1][aa][bb] +
                    sSp[2][aa][bb] + sSp[3][aa][bb]) * 0.0625f;
        float mx = sc;
#pragma unroll
        for (int off = 8; off > 0; off >>= 1)
            mx = fmaxf(mx, __shfl_xor_sync(0xffffffffu, mx, off, 16));
        float e = expf(sc - mx);
        float sm = e;
#pragma unroll
        for (int off = 8; off > 0; off >>= 1)
            sm += __shfl_xor_sync(0xffffffffu, sm, off, 16);
        float attn = e / sm;
        red[aa][bb] = maskf[aa] * attn;
    }
    __syncthreads();

    // ---- Phase 4: fold mask-mean into per-k weights ----
    if (tid < 16) {
        float s = 0.0f, dn = 0.0f;
#pragma unroll
        for (int a2 = 0; a2 < 16; a2++) {
            s += red[a2][tid];
            dn += maskf[a2];
        }
        wsh[tid] = s / dn;
    }
    __syncthreads();

    // ---- Phase 5: mean over t, scatter ----
    {
        u64 part = pack2(0.f, 0.f);
#pragma unroll
        for (int tt = 0; tt < 8; tt++) {
            float w = wsh[8 * th + tt];
            part = ffma2(pack2(w, w), v2[tt], part);
        }
        vp[th][cp] = part;
        __syncthreads();
        if (th == 0) {
            u64 tot = fadd2(vp[0][cp], vp[1][cp]);
            if (a_idx >= 0 && a_idx < N) {
                float2 o;
                o.x = lo32(tot);
                o.y = hi32(tot);
                *(float2*)(out + (size_t)a_idx * 512 + 256 + 2 * cp) = o;
            }
        }
    }
}

// ----------------------------------------------------------------------------
extern "C" void kernel_launch(void* const* d_in, const int* in_sizes, int n_in,
                              void* d_out, int out_size) {
    if (n_in < 7) return;
    const float* x = (const float*)d_in[0];
    const float* pos = (const float*)d_in[1];
    const int* anchor = (const int*)d_in[2];
    const int* corner = (const int*)d_in[3];
    const int* masks = (const int*)d_in[4];
    const float* W = (const float*)d_in[5];
    const float* bias = (const float*)d_in[6];
    float* out = (float*)d_out;

    int N = in_sizes[0] / 256;
    if (N > MAXN) N = MAXN;
    int write_masks = (out_size >= N * 512 + N * 16) ? 1 : 0;

    cudaFuncSetAttribute(gemm_mma_kernel,
                         cudaFuncAttributeMaxDynamicSharedMemorySize,
                         GEMM_SMEM_B);

    const int prep_work = 64 * 768 + 1536 * 256 + 1536;
    prep_misc_kernel<<<(prep_work + 255) / 256, 256>>>(W, bias, N);

    int total4 = N * 64;
    fused_init_kernel<<<(total4 + 255) / 256, 256>>>(x, out, total4);

    dim3 tg((TAB_N + 64) / 64, 3);
    table_build_kernel<<<tg, 256>>>();

    dim3 gg(12, (N + 127) / 128);
    gemm_mma_kernel<<<gg, 256, GEMM_SMEM_B>>>(bias, N);

    triplet_main_kernel<<<N, 256>>>(pos, anchor, corner, masks, out, N, write_masks);
}

// round 15
// speedup vs baseline: 3.7514x; 1.0832x over previous
#include <cuda_runtime.h>
#include <cuda_fp16.h>
#include <math.h>
#include <stdint.h>
#include <stddef.h>

// ============================================================================
// TripletGNN:
//   qkv(n,t) = P[ci0] + Q[ci1] + g(cos_values(n,t))
//   g tabulated at 4097 points, nearest-neighbor, fp16.
//   [P|Q] = x @ Bh via 2-term split-fp16 mma.sync: (xh + xl) * Bh.
//   PQ stored fp16. Scores = (qh+ql) * kh (k residual dropped, ~1.5e-4).
// ============================================================================

#define MAXN 40000
#define TAB_N 4096
#define APAD 40
#define QP 264

typedef unsigned long long u64;

__device__ __half g_PQh[(size_t)(MAXN + 1) * 1536];
__device__ float  g_WaT64[64 * 768];
__device__ __half g_TabH[(size_t)(TAB_N + 1) * 768];
__device__ __half g_Ah[(size_t)MAXN * 256];
__device__ __half g_Al[(size_t)MAXN * 256];
__device__ __half g_Bh[1536 * 256];

// ------------------------------------------------------------ f32x2 helpers -
__device__ __forceinline__ u64 ffma2(u64 a, u64 b, u64 c) {
    u64 d;
    asm("fma.rn.f32x2 %0, %1, %2, %3;" : "=l"(d) : "l"(a), "l"(b), "l"(c));
    return d;
}
__device__ __forceinline__ u64 fadd2(u64 a, u64 b) {
    u64 d;
    asm("add.rn.f32x2 %0, %1, %2;" : "=l"(d) : "l"(a), "l"(b));
    return d;
}
__device__ __forceinline__ u64 pack2(float lo, float hi) {
    u64 d;
    asm("mov.b64 %0, {%1, %2};" : "=l"(d) : "f"(lo), "f"(hi));
    return d;
}
__device__ __forceinline__ float lo32(u64 v) {
    return __uint_as_float((unsigned)(v & 0xffffffffull));
}
__device__ __forceinline__ float hi32(u64 v) {
    return __uint_as_float((unsigned)(v >> 32));
}

// ------------------------------------------------------------ mma helpers ---
__device__ __forceinline__ void ldsm4(uint32_t& r0, uint32_t& r1,
                                      uint32_t& r2, uint32_t& r3,
                                      uint32_t addr) {
    asm volatile("ldmatrix.sync.aligned.m8n8.x4.shared.b16 {%0,%1,%2,%3}, [%4];"
                 : "=r"(r0), "=r"(r1), "=r"(r2), "=r"(r3) : "r"(addr));
}
__device__ __forceinline__ void mma16816(float* d, const uint32_t* a,
                                         uint32_t b0, uint32_t b1) {
    asm volatile(
        "mma.sync.aligned.m16n8k16.row.col.f32.f16.f16.f32 "
        "{%0,%1,%2,%3}, {%4,%5,%6,%7}, {%8,%9}, {%0,%1,%2,%3};"
        : "+f"(d[0]), "+f"(d[1]), "+f"(d[2]), "+f"(d[3])
        : "r"(a[0]), "r"(a[1]), "r"(a[2]), "r"(a[3]), "r"(b0), "r"(b1));
}
__device__ __forceinline__ void cp_async16(uint32_t dst, const void* src,
                                           int src_bytes) {
    asm volatile("cp.async.cg.shared.global [%0], [%1], 16, %2;"
                 :: "r"(dst), "l"(src), "r"(src_bytes));
}
#define CP_COMMIT() asm volatile("cp.async.commit_group;" ::: "memory")
#define CP_WAIT2()  asm volatile("cp.async.wait_group 2;" ::: "memory")
#define CP_WAIT0()  asm volatile("cp.async.wait_group 0;" ::: "memory")

// ------------------------------------------------------------------- prep ---
__global__ void prep_misc_kernel(const float* __restrict__ W,
                                 const float* __restrict__ bias, int N) {
    int idx = blockIdx.x * blockDim.x + threadIdx.x;
    const int WA_SZ = 64 * 768;
    const int B_SZ = 1536 * 256;
    if (idx < WA_SZ) {
        int m = idx / 768, j = idx % 768;
        g_WaT64[idx] = W[j * 576 + 512 + m];
    } else if (idx < WA_SZ + B_SZ) {
        int r = idx - WA_SZ;
        int j = r >> 8, k = r & 255;
        float v = (j < 768) ? W[j * 576 + k] : W[(j - 768) * 576 + 256 + k];
        g_Bh[r] = __float2half(v);
    } else if (idx < WA_SZ + B_SZ + 1536) {
        int j = idx - (WA_SZ + B_SZ);
        g_PQh[(size_t)N * 1536 + j] =
            __float2half((j < 768) ? bias[j] : 0.0f);
    }
}

// Fused, float4-vectorized: x -> (Ah, Al) split; out[:,0:256]=x; [256:512]=0.
__global__ void fused_init_kernel(const float* __restrict__ x,
                                  float* __restrict__ out, int total4) {
    int idx = blockIdx.x * blockDim.x + threadIdx.x;
    if (idx < total4) {
        float4 v = *(const float4*)(x + idx * 4);
        __half h0 = __float2half(v.x), h1 = __float2half(v.y);
        __half h2 = __float2half(v.z), h3 = __float2half(v.w);
        __half2 hi01 = __halves2half2(h0, h1);
        __half2 hi23 = __halves2half2(h2, h3);
        __half2 lo01 = __halves2half2(__float2half(v.x - __half2float(h0)),
                                      __float2half(v.y - __half2float(h1)));
        __half2 lo23 = __halves2half2(__float2half(v.z - __half2float(h2)),
                                      __float2half(v.w - __half2float(h3)));
        *(uint2*)(g_Ah + idx * 4) =
            make_uint2(*(unsigned*)&hi01, *(unsigned*)&hi23);
        *(uint2*)(g_Al + idx * 4) =
            make_uint2(*(unsigned*)&lo01, *(unsigned*)&lo23);
        int r = idx >> 6, c4 = idx & 63;
        *(float4*)(out + (size_t)r * 512 + c4 * 4) = v;
        *(float4*)(out + (size_t)r * 512 + 256 + c4 * 4) =
            make_float4(0.f, 0.f, 0.f, 0.f);
    }
}

// --------------------------------------------------------- angle table ------
__global__ __launch_bounds__(256)
void table_build_kernel() {
    __shared__ float S[64][65];
    const int tid = threadIdx.x;
    const int e0 = blockIdx.x * 64;
    const int j = blockIdx.y * 256 + tid;

    for (int idx = tid; idx < 64 * 64; idx += 256) {
        int el = idx >> 6, m = idx & 63;
        int e = e0 + el;
        float val = 0.0f;
        if (e <= TAB_N) {
            int mp = m >> 1;
            float u = (float)e * (2.0f / TAB_N) - 1.0f;
            float om = u * expf(-0.28782313662425572f * (float)mp);
            float s, c;
            sincosf(om, &s, &c);
            val = (m & 1) ? c : s;
        }
        S[idx >> 6][m] = val;
    }
    __syncthreads();

    float acc[64];
#pragma unroll
    for (int el = 0; el < 64; el++) acc[el] = 0.0f;
#pragma unroll 8
    for (int m = 0; m < 64; m++) {
        float w = g_WaT64[m * 768 + j];
#pragma unroll
        for (int el = 0; el < 64; el++) acc[el] = fmaf(S[el][m], w, acc[el]);
    }
#pragma unroll
    for (int el = 0; el < 64; el++) {
        int e = e0 + el;
        if (e <= TAB_N) g_TabH[(size_t)e * 768 + j] = __float2half(acc[el]);
    }
}

// ------------------- cp.async 3-stage 2-term split-fp16 GEMM ----------------
#define OFF_AH 0
#define OFF_AL 10240
#define OFF_BH 20480
#define STAGE_B 30720
#define GEMM_SMEM_B (3 * STAGE_B)

__global__ __launch_bounds__(256, 2)
void gemm_mma_kernel(const float* __restrict__ bias, int M) {
    extern __shared__ __half smem_h[];
    const int tid = threadIdx.x;
    const int wid = tid >> 5;
    const int lid = tid & 31;
    const int wm = wid >> 2;
    const int wn = wid & 3;
    const int row0 = blockIdx.y * 128;
    const int col0 = blockIdx.x * 128;
    uint32_t sbase = (uint32_t)__cvta_generic_to_shared(smem_h);

    float acc[4][4][4];
#pragma unroll
    for (int i = 0; i < 4; i++)
#pragma unroll
        for (int jq = 0; jq < 4; jq++)
#pragma unroll
            for (int r = 0; r < 4; r++) acc[i][jq][r] = 0.0f;

    const int lrow = lid & 15;
    const int lkoff = (lid >> 4) * 16;

#define ISSUE(ST, KK)                                                         \
    {                                                                         \
        uint32_t stb = sbase + (ST) * STAGE_B;                                \
        _Pragma("unroll") for (int l = 0; l < 2; l++) {                       \
            int fid = tid + l * 256;                                          \
            int r = fid >> 2, q = fid & 3;                                    \
            uint32_t d0 = stb + (uint32_t)(r * APAD + q * 8) * 2;             \
            int grow = row0 + r;                                              \
            int asz = (grow < M) ? 16 : 0;                                    \
            size_t asrc = (size_t)(grow < M ? grow : 0) * 256 + (KK) + q * 8; \
            cp_async16(d0 + OFF_AH, g_Ah + asrc, asz);                        \
            cp_async16(d0 + OFF_AL, g_Al + asrc, asz);                        \
            size_t bsrc = (size_t)(col0 + r) * 256 + (KK) + q * 8;            \
            cp_async16(d0 + OFF_BH, g_Bh + bsrc, 16);                         \
        }                                                                     \
        CP_COMMIT();                                                          \
    }

    ISSUE(0, 0)
    ISSUE(1, 32)
    for (int kt = 0; kt < 8; kt++) {
        if (kt < 6) {
            ISSUE((kt + 2) % 3, (kt + 2) * 32)
            CP_WAIT2();
        } else {
            CP_WAIT0();
        }
        __syncthreads();

        uint32_t stb = sbase + (kt % 3) * STAGE_B;
#pragma unroll
        for (int k16 = 0; k16 < 32; k16 += 16) {
            uint32_t bh[2][4];
#pragma unroll
            for (int nt = 0; nt < 2; nt++) {
                uint32_t boff = stb + OFF_BH +
                    (uint32_t)((wn * 32 + nt * 16 + lrow) * APAD + k16) * 2 +
                    lkoff;
                ldsm4(bh[nt][0], bh[nt][1], bh[nt][2], bh[nt][3], boff);
            }
#pragma unroll
            for (int mt = 0; mt < 4; mt++) {
                uint32_t aoff = stb + OFF_AH +
                    (uint32_t)((wm * 64 + mt * 16 + lrow) * APAD + k16) * 2 +
                    lkoff;
                uint32_t ah[4], al[4];
                ldsm4(ah[0], ah[1], ah[2], ah[3], aoff);
                ldsm4(al[0], al[1], al[2], al[3], aoff + (OFF_AL - OFF_AH));
#pragma unroll
                for (int n = 0; n < 4; n++) {
                    int nt = n >> 1, jj = n & 1;
                    mma16816(acc[mt][n], ah, bh[nt][jj], bh[nt][jj + 2]);
                }
#pragma unroll
                for (int n = 0; n < 4; n++) {
                    int nt = n >> 1, jj = n & 1;
                    mma16816(acc[mt][n], al, bh[nt][jj], bh[nt][jj + 2]);
                }
            }
        }
        __syncthreads();
    }
#undef ISSUE

    // Epilogue: +bias (fp32), quantize to fp16, store __half2.
#pragma unroll
    for (int mt = 0; mt < 4; mt++) {
#pragma unroll
        for (int n = 0; n < 4; n++) {
            int gcol = col0 + wn * 32 + (n >> 1) * 16 + (n & 1) * 8 +
                       (lid & 3) * 2;
            float bx = 0.f, by = 0.f;
            if (gcol < 768) { bx = bias[gcol]; by = bias[gcol + 1]; }
            int r0g = row0 + wm * 64 + mt * 16 + (lid >> 2);
            if (r0g < M) {
                __half2 o = __halves2half2(__float2half(acc[mt][n][0] + bx),
                                           __float2half(acc[mt][n][1] + by));
                *(__half2*)(g_PQh + (size_t)r0g * 1536 + gcol) = o;
            }
            if (r0g + 8 < M) {
                __half2 o = __halves2half2(__float2half(acc[mt][n][2] + bx),
                                           __float2half(acc[mt][n][3] + by));
                *(__half2*)(g_PQh + (size_t)(r0g + 8) * 1536 + gcol) = o;
            }
        }
    }
}

// --------------------------------------------------------------- main ------
// Scores: (qh + ql) * kh  -- q exact to 2^-22, k fp16 (err ~1.5e-4 on attn).
__global__ __launch_bounds__(256, 5)
void triplet_main_kernel(const float* __restrict__ pos,
                         const int* __restrict__ anchor_idx,
                         const int* __restrict__ corner_idx,
                         const int* __restrict__ masks,
                         float* __restrict__ out,
                         int N, int write_masks) {
    __shared__ __align__(16) __half qh[16][QP];
    __shared__ __align__(16) __half ql[16][QP];
    __shared__ __align__(16) __half kh[16][QP];
    __shared__ __align__(16) float sSp[4][16][17];
    __shared__ __align__(16) float red[16][16];
    __shared__ __align__(16) u64 vp[2][128];
    __shared__ int ci0s[16], ci1s[16];
    __shared__ int tIdx[16];
    __shared__ float maskf[16], wsh[16];

    const int n = blockIdx.x;
    const int tid = threadIdx.x;
    const int cp = tid & 127;
    const int th = tid >> 7;
    const int wid = tid >> 5;
    const int lid = tid & 31;
    const int a_idx = anchor_idx[n];

    // ---- Phase 0: triplet geometry + table index (nearest) ----
    if (tid < 16) {
        int t = tid;
        float ax = 0.f, ay = 0.f;
        if (a_idx >= 0 && a_idx < N) {
            ax = pos[(size_t)a_idx * 3 + 0];
            ay = pos[(size_t)a_idx * 3 + 1];
        }
        int i0 = corner_idx[(size_t)n * 32 + 2 * t];
        int i1 = corner_idx[(size_t)n * 32 + 2 * t + 1];
        float p0x = 0.f, p0y = 0.f, p1x = 0.f, p1y = 0.f;
        if (i0 >= 0 && i0 < N) { p0x = pos[(size_t)i0 * 3]; p0y = pos[(size_t)i0 * 3 + 1]; }
        if (i1 >= 0 && i1 < N) { p1x = pos[(size_t)i1 * 3]; p1y = pos[(size_t)i1 * 3 + 1]; }
        float v0x = p0x - ax, v0y = p0y - ay;
        float v1x = p1x - ax, v1y = p1y - ay;
        float dot = v0x * v1x + v0y * v1y;
        float n0 = sqrtf(v0x * v0x + v0y * v0y);
        float n1 = sqrtf(v1x * v1x + v1y * v1y);
        float cosv = dot / (n0 * n1 + 1e-6f);
        float sinz = v0x * v1y - v0y * v1x;
        bool reorder = sinz < 0.0f;
        ci0s[t] = reorder ? i1 : i0;
        ci1s[t] = reorder ? i0 : i1;
        float s = (cosv + 1.0f) * (TAB_N * 0.5f);
        int ti = (int)floorf(s + 0.5f);
        if (ti < 0) ti = 0;
        if (ti > TAB_N) ti = TAB_N;
        tIdx[t] = ti;
        int mb = masks[(size_t)n * 16 + t];
        maskf[t] = (mb != 0) ? 1.0f : 0.0f;
        if (write_masks) {
            float newsin = reorder ? -sinz : sinz;
            out[(size_t)N * 512 + (size_t)n * 16 + t] =
                ((newsin < -1e-6f) && (mb != 0)) ? 1.0f : 0.0f;
        }
    }
    __syncthreads();

    // ---- Phase 1: fp16 gathers + NN table; stage qh/ql, kh ----
    u64 v2[8];
#pragma unroll
    for (int tt = 0; tt < 8; tt++) {
        int t = 8 * th + tt;
        int i0 = ci0s[t]; if (i0 < 0 || i0 > N) i0 = N;
        int i1 = ci1s[t]; if (i1 < 0 || i1 > N) i1 = N;
        const __half2* r0 = (const __half2*)(g_PQh + (size_t)i0 * 1536);
        const __half2* r1 = (const __half2*)(g_PQh + (size_t)i1 * 1536 + 768);
        float2 pq = __half22float2(r0[cp]);
        float2 qq = __half22float2(r1[cp]);
        float2 pk = __half22float2(r0[128 + cp]);
        float2 qk = __half22float2(r1[128 + cp]);
        float2 pv = __half22float2(r0[256 + cp]);
        float2 qv = __half22float2(r1[256 + cp]);

        const __half2* T0 = (const __half2*)(g_TabH + (size_t)tIdx[t] * 768);
        float2 aq = __half22float2(T0[cp]);
        float2 ak = __half22float2(T0[128 + cp]);
        float2 av = __half22float2(T0[256 + cp]);

        float qx = pq.x + qq.x + aq.x;
        float qy = pq.y + qq.y + aq.y;
        float kx = pk.x + qk.x + ak.x;
        float ky = pk.y + qk.y + ak.y;
        float vx = pv.x + qv.x + av.x;
        float vy = pv.y + qv.y + av.y;

        __half qhx = __float2half(qx), qhy = __float2half(qy);
        *(__half2*)&qh[t][2 * cp] = __halves2half2(qhx, qhy);
        *(__half2*)&ql[t][2 * cp] = __halves2half2(
            __float2half(qx - __half2float(qhx)),
            __float2half(qy - __half2float(qhy)));
        *(__half2*)&kh[t][2 * cp] =
            __halves2half2(__float2half(kx), __float2half(ky));
        v2[tt] = pack2(vx, vy);
    }
    __syncthreads();

    // ---- Phase 2: S = (qh+ql) kh^T via mma, K split over warps 0-3 ----
    if (wid < 4) {
        const int lrow = lid & 15;
        const int lkoff = (lid >> 4) * 16;
        uint32_t qh_u = (uint32_t)__cvta_generic_to_shared(qh);
        uint32_t ql_u = (uint32_t)__cvta_generic_to_shared(ql);
        uint32_t kh_u = (uint32_t)__cvta_generic_to_shared(kh);
        float acc[2][4];
#pragma unroll
        for (int jj = 0; jj < 2; jj++)
#pragma unroll
            for (int r = 0; r < 4; r++) acc[jj][r] = 0.0f;

        const int kbase = wid * 64;
#pragma unroll
        for (int kq = 0; kq < 64; kq += 16) {
            int k16 = kbase + kq;
            uint32_t off = (uint32_t)(lrow * QP + k16) * 2 + lkoff;
            uint32_t ah[4], al[4], bh[4];
            ldsm4(ah[0], ah[1], ah[2], ah[3], qh_u + off);
            ldsm4(al[0], al[1], al[2], al[3], ql_u + off);
            ldsm4(bh[0], bh[1], bh[2], bh[3], kh_u + off);
#pragma unroll
            for (int jj = 0; jj < 2; jj++)
                mma16816(acc[jj], ah, bh[jj], bh[jj + 2]);
#pragma unroll
            for (int jj = 0; jj < 2; jj++)
                mma16816(acc[jj], al, bh[jj], bh[jj + 2]);
        }
        int r0 = lid >> 2;
        int c0 = (lid & 3) * 2;
#pragma unroll
        for (int jj = 0; jj < 2; jj++) {
            sSp[wid][r0][jj * 8 + c0] = acc[jj][0];
            sSp[wid][r0][jj * 8 + c0 + 1] = acc[jj][1];
            sSp[wid][r0 + 8][jj * 8 + c0] = acc[jj][2];
            sSp[wid][r0 + 8][jj * 8 + c0 + 1] = acc[jj][3];
        }
    }
    __syncthreads();

    // ---- Phase 3: softmax (sum the 4 K-partials first) ----
    {
        int aa = tid >> 4, bb = tid & 15;
        float sc = (sSp[0][aa][bb] + sSp[1][aa][bb] +
                    sSp[2][aa][bb] + sSp[3][aa][bb]) * 0.0625f;
        float mx = sc;
#pragma unroll
        for (int off = 8; off > 0; off >>= 1)
            mx = fmaxf(mx, __shfl_xor_sync(0xffffffffu, mx, off, 16));
        float e = expf(sc - mx);
        float sm = e;
#pragma unroll
        for (int off = 8; off > 0; off >>= 1)
            sm += __shfl_xor_sync(0xffffffffu, sm, off, 16);
        float attn = e / sm;
        red[aa][bb] = maskf[aa] * attn;
    }
    __syncthreads();

    // ---- Phase 4: fold mask-mean into per-k weights ----
    if (tid < 16) {
        float s = 0.0f, dn = 0.0f;
#pragma unroll
        for (int a2 = 0; a2 < 16; a2++) {
            s += red[a2][tid];
            dn += maskf[a2];
        }
        wsh[tid] = s / dn;
    }
    __syncthreads();

    // ---- Phase 5: mean over t, scatter ----
    {
        u64 part = pack2(0.f, 0.f);
#pragma unroll
        for (int tt = 0; tt < 8; tt++) {
            float w = wsh[8 * th + tt];
            part = ffma2(pack2(w, w), v2[tt], part);
        }
        vp[th][cp] = part;
        __syncthreads();
        if (th == 0) {
            u64 tot = fadd2(vp[0][cp], vp[1][cp]);
            if (a_idx >= 0 && a_idx < N) {
                float2 o;
                o.x = lo32(tot);
                o.y = hi32(tot);
                *(float2*)(out + (size_t)a_idx * 512 + 256 + 2 * cp) = o;
            }
        }
    }
}

// ----------------------------------------------------------------------------
extern "C" void kernel_launch(void* const* d_in, const int* in_sizes, int n_in,
                              void* d_out, int out_size) {
    if (n_in < 7) return;
    const float* x = (const float*)d_in[0];
    const float* pos = (const float*)d_in[1];
    const int* anchor = (const int*)d_in[2];
    const int* corner = (const int*)d_in[3];
    const int* masks = (const int*)d_in[4];
    const float* W = (const float*)d_in[5];
    const float* bias = (const float*)d_in[6];
    float* out = (float*)d_out;

    int N = in_sizes[0] / 256;
    if (N > MAXN) N = MAXN;
    int write_masks = (out_size >= N * 512 + N * 16) ? 1 : 0;

    cudaFuncSetAttribute(gemm_mma_kernel,
                         cudaFuncAttributeMaxDynamicSharedMemorySize,
                         GEMM_SMEM_B);

    const int prep_work = 64 * 768 + 1536 * 256 + 1536;
    prep_misc_kernel<<<(prep_work + 255) / 256, 256>>>(W, bias, N);

    int total4 = N * 64;
    fused_init_kernel<<<(total4 + 255) / 256, 256>>>(x, out, total4);

    dim3 tg((TAB_N + 64) / 64, 3);
    table_build_kernel<<<tg, 256>>>();

    dim3 gg(12, (N + 127) / 128);
    gemm_mma_kernel<<<gg, 256, GEMM_SMEM_B>>>(bias, N);

    triplet_main_kernel<<<N, 256>>>(pos, anchor, corner, masks, out, N, write_masks);
}

// round 16
// speedup vs baseline: 4.5032x; 1.2004x over previous
#include <cuda_runtime.h>
#include <cuda_fp16.h>
#include <math.h>
#include <stdint.h>
#include <stddef.h>

// ============================================================================
// TripletGNN:
//   qkv(n,t) = P[ci0] + Q[ci1] + g(cos_values(n,t))
//   g tabulated at 4097 points, nearest-neighbor, fp16.
//   [P|Q] = xh @ Bh, pure fp16 mma.sync with fp32 accum (~1e-4 total).
//   PQ stored fp16. Scores = qh * kh (pure fp16 operands, fp32 accum).
// ============================================================================

#define MAXN 40000
#define TAB_N 4096
#define APAD 40
#define QP 264

typedef unsigned long long u64;

__device__ __half g_PQh[(size_t)(MAXN + 1) * 1536];
__device__ float  g_WaT64[64 * 768];
__device__ __half g_TabH[(size_t)(TAB_N + 1) * 768];
__device__ __half g_Ah[(size_t)MAXN * 256];
__device__ __half g_Bh[1536 * 256];

// ------------------------------------------------------------ f32x2 helpers -
__device__ __forceinline__ u64 ffma2(u64 a, u64 b, u64 c) {
    u64 d;
    asm("fma.rn.f32x2 %0, %1, %2, %3;" : "=l"(d) : "l"(a), "l"(b), "l"(c));
    return d;
}
__device__ __forceinline__ u64 fadd2(u64 a, u64 b) {
    u64 d;
    asm("add.rn.f32x2 %0, %1, %2;" : "=l"(d) : "l"(a), "l"(b));
    return d;
}
__device__ __forceinline__ u64 pack2(float lo, float hi) {
    u64 d;
    asm("mov.b64 %0, {%1, %2};" : "=l"(d) : "f"(lo), "f"(hi));
    return d;
}
__device__ __forceinline__ float lo32(u64 v) {
    return __uint_as_float((unsigned)(v & 0xffffffffull));
}
__device__ __forceinline__ float hi32(u64 v) {
    return __uint_as_float((unsigned)(v >> 32));
}

// ------------------------------------------------------------ mma helpers ---
__device__ __forceinline__ void ldsm4(uint32_t& r0, uint32_t& r1,
                                      uint32_t& r2, uint32_t& r3,
                                      uint32_t addr) {
    asm volatile("ldmatrix.sync.aligned.m8n8.x4.shared.b16 {%0,%1,%2,%3}, [%4];"
                 : "=r"(r0), "=r"(r1), "=r"(r2), "=r"(r3) : "r"(addr));
}
__device__ __forceinline__ void mma16816(float* d, const uint32_t* a,
                                         uint32_t b0, uint32_t b1) {
    asm volatile(
        "mma.sync.aligned.m16n8k16.row.col.f32.f16.f16.f32 "
        "{%0,%1,%2,%3}, {%4,%5,%6,%7}, {%8,%9}, {%0,%1,%2,%3};"
        : "+f"(d[0]), "+f"(d[1]), "+f"(d[2]), "+f"(d[3])
        : "r"(a[0]), "r"(a[1]), "r"(a[2]), "r"(a[3]), "r"(b0), "r"(b1));
}
__device__ __forceinline__ void cp_async16(uint32_t dst, const void* src,
                                           int src_bytes) {
    asm volatile("cp.async.cg.shared.global [%0], [%1], 16, %2;"
                 :: "r"(dst), "l"(src), "r"(src_bytes));
}
#define CP_COMMIT() asm volatile("cp.async.commit_group;" ::: "memory")
#define CP_WAIT2()  asm volatile("cp.async.wait_group 2;" ::: "memory")
#define CP_WAIT0()  asm volatile("cp.async.wait_group 0;" ::: "memory")

// ------------------------------------------------------------------- prep ---
__global__ void prep_misc_kernel(const float* __restrict__ W,
                                 const float* __restrict__ bias, int N) {
    int idx = blockIdx.x * blockDim.x + threadIdx.x;
    const int WA_SZ = 64 * 768;
    const int B_SZ = 1536 * 256;
    if (idx < WA_SZ) {
        int m = idx / 768, j = idx % 768;
        g_WaT64[idx] = W[j * 576 + 512 + m];
    } else if (idx < WA_SZ + B_SZ) {
        int r = idx - WA_SZ;
        int j = r >> 8, k = r & 255;
        float v = (j < 768) ? W[j * 576 + k] : W[(j - 768) * 576 + 256 + k];
        g_Bh[r] = __float2half(v);
    } else if (idx < WA_SZ + B_SZ + 1536) {
        int j = idx - (WA_SZ + B_SZ);
        g_PQh[(size_t)N * 1536 + j] =
            __float2half((j < 768) ? bias[j] : 0.0f);
    }
}

// Fused, float4-vectorized: x -> Ah fp16; out[:,0:256]=x; [256:512]=0.
__global__ void fused_init_kernel(const float* __restrict__ x,
                                  float* __restrict__ out, int total4) {
    int idx = blockIdx.x * blockDim.x + threadIdx.x;
    if (idx < total4) {
        float4 v = *(const float4*)(x + idx * 4);
        __half2 hi01 = __halves2half2(__float2half(v.x), __float2half(v.y));
        __half2 hi23 = __halves2half2(__float2half(v.z), __float2half(v.w));
        *(uint2*)(g_Ah + idx * 4) =
            make_uint2(*(unsigned*)&hi01, *(unsigned*)&hi23);
        int r = idx >> 6, c4 = idx & 63;
        *(float4*)(out + (size_t)r * 512 + c4 * 4) = v;
        *(float4*)(out + (size_t)r * 512 + 256 + c4 * 4) =
            make_float4(0.f, 0.f, 0.f, 0.f);
    }
}

// --------------------------------------------------------- angle table ------
__global__ __launch_bounds__(256)
void table_build_kernel() {
    __shared__ float S[64][65];
    const int tid = threadIdx.x;
    const int e0 = blockIdx.x * 64;
    const int j = blockIdx.y * 256 + tid;

    for (int idx = tid; idx < 64 * 64; idx += 256) {
        int el = idx >> 6, m = idx & 63;
        int e = e0 + el;
        float val = 0.0f;
        if (e <= TAB_N) {
            int mp = m >> 1;
            float u = (float)e * (2.0f / TAB_N) - 1.0f;
            float om = u * expf(-0.28782313662425572f * (float)mp);
            float s, c;
            sincosf(om, &s, &c);
            val = (m & 1) ? c : s;
        }
        S[idx >> 6][m] = val;
    }
    __syncthreads();

    float acc[64];
#pragma unroll
    for (int el = 0; el < 64; el++) acc[el] = 0.0f;
#pragma unroll 8
    for (int m = 0; m < 64; m++) {
        float w = g_WaT64[m * 768 + j];
#pragma unroll
        for (int el = 0; el < 64; el++) acc[el] = fmaf(S[el][m], w, acc[el]);
    }
#pragma unroll
    for (int el = 0; el < 64; el++) {
        int e = e0 + el;
        if (e <= TAB_N) g_TabH[(size_t)e * 768 + j] = __float2half(acc[el]);
    }
}

// ------------------- cp.async 3-stage pure-fp16 GEMM ------------------------
// Tile: 128(M) x 128(N), K chunks of 32. Warps: 2(M) x 4(N), warp tile 64x32.
// Stage: [Ah 10240][Bh 10240] = 20480 B, 3 stages.
#define OFF_AH 0
#define OFF_BH 10240
#define STAGE_B 20480
#define GEMM_SMEM_B (3 * STAGE_B)

__global__ __launch_bounds__(256, 2)
void gemm_mma_kernel(const float* __restrict__ bias, int M) {
    extern __shared__ __half smem_h[];
    const int tid = threadIdx.x;
    const int wid = tid >> 5;
    const int lid = tid & 31;
    const int wm = wid >> 2;
    const int wn = wid & 3;
    const int row0 = blockIdx.y * 128;
    const int col0 = blockIdx.x * 128;
    uint32_t sbase = (uint32_t)__cvta_generic_to_shared(smem_h);

    float acc[4][4][4];
#pragma unroll
    for (int i = 0; i < 4; i++)
#pragma unroll
        for (int jq = 0; jq < 4; jq++)
#pragma unroll
            for (int r = 0; r < 4; r++) acc[i][jq][r] = 0.0f;

    const int lrow = lid & 15;
    const int lkoff = (lid >> 4) * 16;

#define ISSUE(ST, KK)                                                         \
    {                                                                         \
        uint32_t stb = sbase + (ST) * STAGE_B;                                \
        _Pragma("unroll") for (int l = 0; l < 2; l++) {                       \
            int fid = tid + l * 256;                                          \
            int r = fid >> 2, q = fid & 3;                                    \
            uint32_t d0 = stb + (uint32_t)(r * APAD + q * 8) * 2;             \
            int grow = row0 + r;                                              \
            int asz = (grow < M) ? 16 : 0;                                    \
            size_t asrc = (size_t)(grow < M ? grow : 0) * 256 + (KK) + q * 8; \
            cp_async16(d0 + OFF_AH, g_Ah + asrc, asz);                        \
            size_t bsrc = (size_t)(col0 + r) * 256 + (KK) + q * 8;            \
            cp_async16(d0 + OFF_BH, g_Bh + bsrc, 16);                         \
        }                                                                     \
        CP_COMMIT();                                                          \
    }

    ISSUE(0, 0)
    ISSUE(1, 32)
    for (int kt = 0; kt < 8; kt++) {
        if (kt < 6) {
            ISSUE((kt + 2) % 3, (kt + 2) * 32)
            CP_WAIT2();
        } else {
            CP_WAIT0();
        }
        __syncthreads();

        uint32_t stb = sbase + (kt % 3) * STAGE_B;
#pragma unroll
        for (int k16 = 0; k16 < 32; k16 += 16) {
            uint32_t bh[2][4];
#pragma unroll
            for (int nt = 0; nt < 2; nt++) {
                uint32_t boff = stb + OFF_BH +
                    (uint32_t)((wn * 32 + nt * 16 + lrow) * APAD + k16) * 2 +
                    lkoff;
                ldsm4(bh[nt][0], bh[nt][1], bh[nt][2], bh[nt][3], boff);
            }
#pragma unroll
            for (int mt = 0; mt < 4; mt++) {
                uint32_t aoff = stb + OFF_AH +
                    (uint32_t)((wm * 64 + mt * 16 + lrow) * APAD + k16) * 2 +
                    lkoff;
                uint32_t ah[4];
                ldsm4(ah[0], ah[1], ah[2], ah[3], aoff);
#pragma unroll
                for (int n = 0; n < 4; n++) {
                    int nt = n >> 1, jj = n & 1;
                    mma16816(acc[mt][n], ah, bh[nt][jj], bh[nt][jj + 2]);
                }
            }
        }
        __syncthreads();
    }
#undef ISSUE

    // Epilogue: +bias (fp32), quantize to fp16, store __half2.
#pragma unroll
    for (int mt = 0; mt < 4; mt++) {
#pragma unroll
        for (int n = 0; n < 4; n++) {
            int gcol = col0 + wn * 32 + (n >> 1) * 16 + (n & 1) * 8 +
                       (lid & 3) * 2;
            float bx = 0.f, by = 0.f;
            if (gcol < 768) { bx = bias[gcol]; by = bias[gcol + 1]; }
            int r0g = row0 + wm * 64 + mt * 16 + (lid >> 2);
            if (r0g < M) {
                __half2 o = __halves2half2(__float2half(acc[mt][n][0] + bx),
                                           __float2half(acc[mt][n][1] + by));
                *(__half2*)(g_PQh + (size_t)r0g * 1536 + gcol) = o;
            }
            if (r0g + 8 < M) {
                __half2 o = __halves2half2(__float2half(acc[mt][n][2] + bx),
                                           __float2half(acc[mt][n][3] + by));
                *(__half2*)(g_PQh + (size_t)(r0g + 8) * 1536 + gcol) = o;
            }
        }
    }
}

// --------------------------------------------------------------- main ------
// Scores: qh * kh (pure fp16 operands, fp32 accumulate).
__global__ __launch_bounds__(256, 5)
void triplet_main_kernel(const float* __restrict__ pos,
                         const int* __restrict__ anchor_idx,
                         const int* __restrict__ corner_idx,
                         const int* __restrict__ masks,
                         float* __restrict__ out,
                         int N, int write_masks) {
    __shared__ __align__(16) __half qh[16][QP];
    __shared__ __align__(16) __half kh[16][QP];
    __shared__ __align__(16) float sSp[4][16][17];
    __shared__ __align__(16) float red[16][16];
    __shared__ __align__(16) u64 vp[2][128];
    __shared__ int ci0s[16], ci1s[16];
    __shared__ int tIdx[16];
    __shared__ float maskf[16], wsh[16];

    const int n = blockIdx.x;
    const int tid = threadIdx.x;
    const int cp = tid & 127;
    const int th = tid >> 7;
    const int wid = tid >> 5;
    const int lid = tid & 31;
    const int a_idx = anchor_idx[n];

    // ---- Phase 0: triplet geometry + table index (nearest) ----
    if (tid < 16) {
        int t = tid;
        float ax = 0.f, ay = 0.f;
        if (a_idx >= 0 && a_idx < N) {
            ax = pos[(size_t)a_idx * 3 + 0];
            ay = pos[(size_t)a_idx * 3 + 1];
        }
        int i0 = corner_idx[(size_t)n * 32 + 2 * t];
        int i1 = corner_idx[(size_t)n * 32 + 2 * t + 1];
        float p0x = 0.f, p0y = 0.f, p1x = 0.f, p1y = 0.f;
        if (i0 >= 0 && i0 < N) { p0x = pos[(size_t)i0 * 3]; p0y = pos[(size_t)i0 * 3 + 1]; }
        if (i1 >= 0 && i1 < N) { p1x = pos[(size_t)i1 * 3]; p1y = pos[(size_t)i1 * 3 + 1]; }
        float v0x = p0x - ax, v0y = p0y - ay;
        float v1x = p1x - ax, v1y = p1y - ay;
        float dot = v0x * v1x + v0y * v1y;
        float n0 = sqrtf(v0x * v0x + v0y * v0y);
        float n1 = sqrtf(v1x * v1x + v1y * v1y);
        float cosv = dot / (n0 * n1 + 1e-6f);
        float sinz = v0x * v1y - v0y * v1x;
        bool reorder = sinz < 0.0f;
        ci0s[t] = reorder ? i1 : i0;
        ci1s[t] = reorder ? i0 : i1;
        float s = (cosv + 1.0f) * (TAB_N * 0.5f);
        int ti = (int)floorf(s + 0.5f);
        if (ti < 0) ti = 0;
        if (ti > TAB_N) ti = TAB_N;
        tIdx[t] = ti;
        int mb = masks[(size_t)n * 16 + t];
        maskf[t] = (mb != 0) ? 1.0f : 0.0f;
        if (write_masks) {
            float newsin = reorder ? -sinz : sinz;
            out[(size_t)N * 512 + (size_t)n * 16 + t] =
                ((newsin < -1e-6f) && (mb != 0)) ? 1.0f : 0.0f;
        }
    }
    __syncthreads();

    // ---- Phase 1: fp16 gathers + NN table; stage qh, kh ----
    u64 v2[8];
#pragma unroll
    for (int tt = 0; tt < 8; tt++) {
        int t = 8 * th + tt;
        int i0 = ci0s[t]; if (i0 < 0 || i0 > N) i0 = N;
        int i1 = ci1s[t]; if (i1 < 0 || i1 > N) i1 = N;
        const __half2* r0 = (const __half2*)(g_PQh + (size_t)i0 * 1536);
        const __half2* r1 = (const __half2*)(g_PQh + (size_t)i1 * 1536 + 768);
        float2 pq = __half22float2(r0[cp]);
        float2 qq = __half22float2(r1[cp]);
        float2 pk = __half22float2(r0[128 + cp]);
        float2 qk = __half22float2(r1[128 + cp]);
        float2 pv = __half22float2(r0[256 + cp]);
        float2 qv = __half22float2(r1[256 + cp]);

        const __half2* T0 = (const __half2*)(g_TabH + (size_t)tIdx[t] * 768);
        float2 aq = __half22float2(T0[cp]);
        float2 ak = __half22float2(T0[128 + cp]);
        float2 av = __half22float2(T0[256 + cp]);

        float qx = pq.x + qq.x + aq.x;
        float qy = pq.y + qq.y + aq.y;
        float kx = pk.x + qk.x + ak.x;
        float ky = pk.y + qk.y + ak.y;
        float vx = pv.x + qv.x + av.x;
        float vy = pv.y + qv.y + av.y;

        *(__half2*)&qh[t][2 * cp] =
            __halves2half2(__float2half(qx), __float2half(qy));
        *(__half2*)&kh[t][2 * cp] =
            __halves2half2(__float2half(kx), __float2half(ky));
        v2[tt] = pack2(vx, vy);
    }
    __syncthreads();

    // ---- Phase 2: S = qh kh^T via mma, K split over warps 0-3 ----
    if (wid < 4) {
        const int lrow = lid & 15;
        const int lkoff = (lid >> 4) * 16;
        uint32_t qh_u = (uint32_t)__cvta_generic_to_shared(qh);
        uint32_t kh_u = (uint32_t)__cvta_generic_to_shared(kh);
        float acc[2][4];
#pragma unroll
        for (int jj = 0; jj < 2; jj++)
#pragma unroll
            for (int r = 0; r < 4; r++) acc[jj][r] = 0.0f;

        const int kbase = wid * 64;
#pragma unroll
        for (int kq = 0; kq < 64; kq += 16) {
            int k16 = kbase + kq;
            uint32_t off = (uint32_t)(lrow * QP + k16) * 2 + lkoff;
            uint32_t ah[4], bh[4];
            ldsm4(ah[0], ah[1], ah[2], ah[3], qh_u + off);
            ldsm4(bh[0], bh[1], bh[2], bh[3], kh_u + off);
#pragma unroll
            for (int jj = 0; jj < 2; jj++)
                mma16816(acc[jj], ah, bh[jj], bh[jj + 2]);
        }
        int r0 = lid >> 2;
        int c0 = (lid & 3) * 2;
#pragma unroll
        for (int jj = 0; jj < 2; jj++) {
            sSp[wid][r0][jj * 8 + c0] = acc[jj][0];
            sSp[wid][r0][jj * 8 + c0 + 1] = acc[jj][1];
            sSp[wid][r0 + 8][jj * 8 + c0] = acc[jj][2];
            sSp[wid][r0 + 8][jj * 8 + c0 + 1] = acc[jj][3];
        }
    }
    __syncthreads();

    // ---- Phase 3: softmax (sum the 4 K-partials first) ----
    {
        int aa = tid >> 4, bb = tid & 15;
        float sc = (sSp[0][aa][bb] + sSp[1][aa][bb] +
                    sSp[2][aa][bb] + sSp[3][aa][bb]) * 0.0625f;
        float mx = sc;
#pragma unroll
        for (int off = 8; off > 0; off >>= 1)
            mx = fmaxf(mx, __shfl_xor_sync(0xffffffffu, mx, off, 16));
        float e = expf(sc - mx);
        float sm = e;
#pragma unroll
        for (int off = 8; off > 0; off >>= 1)
            sm += __shfl_xor_sync(0xffffffffu, sm, off, 16);
        float attn = e / sm;
        red[aa][bb] = maskf[aa] * attn;
    }
    __syncthreads();

    // ---- Phase 4: fold mask-mean into per-k weights ----
    if (tid < 16) {
        float s = 0.0f, dn = 0.0f;
#pragma unroll
        for (int a2 = 0; a2 < 16; a2++) {
            s += red[a2][tid];
            dn += maskf[a2];
        }
        wsh[tid] = s / dn;
    }
    __syncthreads();

    // ---- Phase 5: mean over t, scatter ----
    {
        u64 part = pack2(0.f, 0.f);
#pragma unroll
        for (int tt = 0; tt < 8; tt++) {
            float w = wsh[8 * th + tt];
            part = ffma2(pack2(w, w), v2[tt], part);
        }
        vp[th][cp] = part;
        __syncthreads();
        if (th == 0) {
            u64 tot = fadd2(vp[0][cp], vp[1][cp]);
            if (a_idx >= 0 && a_idx < N) {
                float2 o;
                o.x = lo32(tot);
                o.y = hi32(tot);
                *(float2*)(out + (size_t)a_idx * 512 + 256 + 2 * cp) = o;
            }
        }
    }
}

// ----------------------------------------------------------------------------
extern "C" void kernel_launch(void* const* d_in, const int* in_sizes, int n_in,
                              void* d_out, int out_size) {
    if (n_in < 7) return;
    const float* x = (const float*)d_in[0];
    const float* pos = (const float*)d_in[1];
    const int* anchor = (const int*)d_in[2];
    const int* corner = (const int*)d_in[3];
    const int* masks = (const int*)d_in[4];
    const float* W = (const float*)d_in[5];
    const float* bias = (const float*)d_in[6];
    float* out = (float*)d_out;

    int N = in_sizes[0] / 256;
    if (N > MAXN) N = MAXN;
    int write_masks = (out_size >= N * 512 + N * 16) ? 1 : 0;

    cudaFuncSetAttribute(gemm_mma_kernel,
                         cudaFuncAttributeMaxDynamicSharedMemorySize,
                         GEMM_SMEM_B);

    const int prep_work = 64 * 768 + 1536 * 256 + 1536;
    prep_misc_kernel<<<(prep_work + 255) / 256, 256>>>(W, bias, N);

    int total4 = N * 64;
    fused_init_kernel<<<(total4 + 255) / 256, 256>>>(x, out, total4);

    dim3 tg((TAB_N + 64) / 64, 3);
    table_build_kernel<<<tg, 256>>>();

    dim3 gg(12, (N + 127) / 128);
    gemm_mma_kernel<<<gg, 256, GEMM_SMEM_B>>>(bias, N);

    triplet_main_kernel<<<N, 256>>>(pos, anchor, corner, masks, out, N, write_masks);
}